// round 10
// baseline (speedup 1.0000x reference)
#include <cuda_runtime.h>
#include <cuda_bf16.h>
#include <math.h>
#include <stdint.h>

#define DMODEL 1024
#define DFF 4096
#define SEQ 2048
#define NTOK 4096
#define LN_EPS 1e-5f
typedef __nv_bfloat16 bf16;

// ---------------- device-global scratch ----------------
__device__ bf16 g_wqt_h[1u<<20], g_wqt_l[1u<<20];   // [N,K] K-major (wq pre-scaled 0.125)
__device__ bf16 g_wkt_h[1u<<20], g_wkt_l[1u<<20];
__device__ bf16 g_wvt_h[1u<<20], g_wvt_l[1u<<20];
__device__ bf16 g_wot_h[1u<<20], g_wot_l[1u<<20];
__device__ bf16 g_w1t_h[1u<<22], g_w1t_l[1u<<22];   // [4096,1024]
__device__ bf16 g_w2t_h[1u<<22], g_w2t_l[1u<<22];   // [1024,4096]
__device__ bf16 g_xn_h [1u<<22], g_xn_l [1u<<22];
__device__ bf16 g_q_h  [1u<<22], g_q_l  [1u<<22];
__device__ bf16 g_k_h  [1u<<22], g_k_l  [1u<<22];
__device__ bf16 g_vt_h [1u<<22], g_vt_l [1u<<22];   // [1024 dk, 4096 tok]
__device__ bf16 g_ctx_h[1u<<22], g_ctx_l[1u<<22];
__device__ bf16 g_ffh_h[1u<<24], g_ffh_l[1u<<24];   // [4096,4096]
__device__ float g_x1[1u<<22];

// ---------------- helpers ----------------
__device__ __forceinline__ void mma16816(float* d, const uint32_t* a, const uint32_t* b) {
    asm volatile(
        "mma.sync.aligned.m16n8k16.row.col.f32.bf16.bf16.f32 "
        "{%0,%1,%2,%3}, {%4,%5,%6,%7}, {%8,%9}, {%0,%1,%2,%3};"
        : "+f"(d[0]), "+f"(d[1]), "+f"(d[2]), "+f"(d[3])
        : "r"(a[0]), "r"(a[1]), "r"(a[2]), "r"(a[3]), "r"(b[0]), "r"(b[1]));
}
__device__ __forceinline__ uint16_t bfbits(bf16 v) { return __bfloat16_as_ushort(v); }
__device__ __forceinline__ void split(float f, bf16* h, bf16* l) {
    bf16 hh = __float2bfloat16(f);
    *h = hh; *l = __float2bfloat16(f - __bfloat162float(hh));
}
__device__ __forceinline__ float warpSum(float v) {
    #pragma unroll
    for (int o = 16; o > 0; o >>= 1) v += __shfl_down_sync(0xffffffffu, v, o);
    return v;
}
__device__ __forceinline__ float blockSum(float v) {
    __shared__ float sh[8];
    int l = threadIdx.x & 31, w = threadIdx.x >> 5;
    v = warpSum(v);
    if (l == 0) sh[w] = v;
    __syncthreads();
    if (w == 0) { float t = (l < 8) ? sh[l] : 0.f; t = warpSum(t); if (l == 0) sh[0] = t; }
    __syncthreads();
    float r = sh[0]; __syncthreads();
    return r;
}

// ---------------- weight prep: ONE launch for all six weights ----------------
__global__ void __launch_bounds__(256) k_prep_all(
    const float* __restrict__ wq, const float* __restrict__ wk,
    const float* __restrict__ wv, const float* __restrict__ wo,
    const float* __restrict__ w1, const float* __restrict__ w2)
{
    int t = blockIdx.x;
    const float* w; bf16 *th, *tl;
    int K, N, local;
    float scale = 1.0f;
    if (t < 4096) {
        int seg = t >> 10; local = t & 1023;
        K = 1024; N = 1024;
        switch (seg) {
            case 0: w = wq; th = g_wqt_h; tl = g_wqt_l; scale = 0.125f; break;
            case 1: w = wk; th = g_wkt_h; tl = g_wkt_l; break;
            case 2: w = wv; th = g_wvt_h; tl = g_wvt_l; break;
            default: w = wo; th = g_wot_h; tl = g_wot_l; break;
        }
    } else if (t < 8192) {
        local = t - 4096; w = w1; th = g_w1t_h; tl = g_w1t_l; K = 1024; N = 4096;
    } else {
        local = t - 8192; w = w2; th = g_w2t_h; tl = g_w2t_l; K = 4096; N = 1024;
    }
    const int xt = N >> 5;
    const int n0 = (local % xt) * 32, k0 = (local / xt) * 32;

    __shared__ float ts[32][33];
    int tx = threadIdx.x & 31, ty = threadIdx.x >> 5;
    #pragma unroll
    for (int i = 0; i < 4; i++)
        ts[ty + 8*i][tx] = w[(size_t)(k0 + ty + 8*i) * N + n0 + tx];
    __syncthreads();
    #pragma unroll
    for (int i = 0; i < 4; i++) {
        int n = n0 + ty + 8*i, k = k0 + tx;
        split(ts[tx][ty + 8*i] * scale, &th[(size_t)n * K + k], &tl[(size_t)n * K + k]);
    }
}

// ---------------- LayerNorm -> bf16 hi/lo ----------------
__global__ void __launch_bounds__(256) k_ln(const float* __restrict__ xin, int use_x1,
                                            const float* __restrict__ ap,
                                            const float* __restrict__ bp)
{
    const float* src = use_x1 ? g_x1 : xin;
    int row = blockIdx.x, t = threadIdx.x;
    const float* xr = src + (size_t)row * DMODEL;
    float v[4], s = 0.f, sq = 0.f;
    #pragma unroll
    for (int i = 0; i < 4; i++) { v[i] = xr[t + 256*i]; s += v[i]; sq += v[i]*v[i]; }
    s = blockSum(s); sq = blockSum(sq);
    float mean = s * (1.0f / DMODEL);
    float var = fmaxf((sq - (float)DMODEL * mean * mean) * (1.0f / (DMODEL - 1)), 0.f);
    float sc = ap[0] / (sqrtf(var) + LN_EPS);
    float bi = bp[0];
    #pragma unroll
    for (int i = 0; i < 4; i++) {
        size_t o = (size_t)row * DMODEL + t + 256*i;
        split((v[i] - mean) * sc + bi, &g_xn_h[o], &g_xn_l[o]);
    }
}

// ---------------------------------------------------------------------------
// Fused flash attention with register-prefetch pipeline.
// Per CTA: one (b,h) head, 128 q rows, 32 key-tiles of 64.
// K/V tile loads for kt+1 issue right after the smem-store barrier, hiding
// global latency under tile kt's MMAs + softmax.
// ---------------------------------------------------------------------------
__global__ void __launch_bounds__(256) kt_attn(const int* __restrict__ mask)
{
    const int z = blockIdx.y, b = z >> 4, h = z & 15;
    const int q0 = blockIdx.x * 128;
    const int tid = threadIdx.x, wid = tid >> 5, lane = tid & 31;
    const int g = lane >> 2, t4 = lane & 3;

    __shared__ __align__(16) uint16_t sKh[64*72], sKl[64*72];
    __shared__ __align__(16) uint16_t sVh[64*72], sVl[64*72];
    __shared__ int s_mask[SEQ];

    for (int i = tid; i < SEQ/4; i += 256)
        *(int4*)&s_mask[i*4] = *(const int4*)&mask[b*SEQ + i*4];

    // Q fragments, register-resident
    uint32_t qh[4][4], ql[4][4];
    {
        const uint32_t* Q32h = (const uint32_t*)g_q_h;
        const uint32_t* Q32l = (const uint32_t*)g_q_l;
        size_t r0 = ((size_t)(b*SEQ + q0 + wid*16 + g)) * 512 + h*32;
        size_t r8 = r0 + 8*512;
        #pragma unroll
        for (int s = 0; s < 4; s++) {
            qh[s][0] = Q32h[r0 + s*8 + t4];
            qh[s][1] = Q32h[r8 + s*8 + t4];
            qh[s][2] = Q32h[r0 + s*8 + 4 + t4];
            qh[s][3] = Q32h[r8 + s*8 + 4 + t4];
            ql[s][0] = Q32l[r0 + s*8 + t4];
            ql[s][1] = Q32l[r8 + s*8 + t4];
            ql[s][2] = Q32l[r0 + s*8 + 4 + t4];
            ql[s][3] = Q32l[r8 + s*8 + 4 + t4];
        }
    }

    float O[8][4];
    #pragma unroll
    for (int i = 0; i < 8; i++)
        #pragma unroll
        for (int j = 0; j < 4; j++) O[i][j] = 0.f;
    float m0 = -INFINITY, m1 = -INFINITY, l0 = 0.f, l1 = 0.f;

    const int krow = tid >> 2, kcb = (tid & 3) * 16;
    const uint32_t* K32h = (const uint32_t*)sKh;
    const uint32_t* K32l = (const uint32_t*)sKl;
    const uint32_t* V32h = (const uint32_t*)sVh;
    const uint32_t* V32l = (const uint32_t*)sVl;

    // register prefetch buffers (8 x uint4)
    uint4 pKh0, pKh1, pKl0, pKl1, pVh0, pVh1, pVl0, pVl1;
    auto pre = [&](int kt) {
        size_t gk = ((size_t)(b*SEQ + kt*64 + krow)) * 1024 + h*64 + kcb;
        pKh0 = *(const uint4*)&g_k_h[gk];
        pKh1 = *(const uint4*)&g_k_h[gk + 8];
        pKl0 = *(const uint4*)&g_k_l[gk];
        pKl1 = *(const uint4*)&g_k_l[gk + 8];
        size_t gv = ((size_t)(h*64 + krow)) * 4096 + b*SEQ + kt*64 + kcb;
        pVh0 = *(const uint4*)&g_vt_h[gv];
        pVh1 = *(const uint4*)&g_vt_h[gv + 8];
        pVl0 = *(const uint4*)&g_vt_l[gv];
        pVl1 = *(const uint4*)&g_vt_l[gv + 8];
    };

    pre(0);
    for (int kt = 0; kt < SEQ/64; kt++) {
        __syncthreads();   // previous compute done reading smem
        *(uint4*)&sKh[krow*72 + kcb]     = pKh0;
        *(uint4*)&sKh[krow*72 + kcb + 8] = pKh1;
        *(uint4*)&sKl[krow*72 + kcb]     = pKl0;
        *(uint4*)&sKl[krow*72 + kcb + 8] = pKl1;
        *(uint4*)&sVh[krow*72 + kcb]     = pVh0;
        *(uint4*)&sVh[krow*72 + kcb + 8] = pVh1;
        *(uint4*)&sVl[krow*72 + kcb]     = pVl0;
        *(uint4*)&sVl[krow*72 + kcb + 8] = pVl1;
        __syncthreads();
        if (kt + 1 < SEQ/64) pre(kt + 1);   // latency hides under compute below

        // ---- S = Q K^T ----
        float s[8][4];
        #pragma unroll
        for (int nt = 0; nt < 8; nt++) {
            s[nt][0] = s[nt][1] = s[nt][2] = s[nt][3] = 0.f;
            const int nr = (nt*8 + g) * 36;
            #pragma unroll
            for (int ks = 0; ks < 4; ks++) {
                uint32_t bh[2] = { K32h[nr + ks*8 + t4], K32h[nr + ks*8 + 4 + t4] };
                uint32_t bl[2] = { K32l[nr + ks*8 + t4], K32l[nr + ks*8 + 4 + t4] };
                mma16816(s[nt], qh[ks], bh);
                mma16816(s[nt], qh[ks], bl);
                mma16816(s[nt], ql[ks], bh);
            }
        }
        // ---- mask ----
        #pragma unroll
        for (int nt = 0; nt < 8; nt++) {
            const int c = kt*64 + nt*8 + 2*t4;
            if (s_mask[c]   == 0) { s[nt][0] = -1e9f; s[nt][2] = -1e9f; }
            if (s_mask[c+1] == 0) { s[nt][1] = -1e9f; s[nt][3] = -1e9f; }
        }
        // ---- online softmax ----
        float mx0 = -INFINITY, mx1 = -INFINITY;
        #pragma unroll
        for (int nt = 0; nt < 8; nt++) {
            mx0 = fmaxf(mx0, fmaxf(s[nt][0], s[nt][1]));
            mx1 = fmaxf(mx1, fmaxf(s[nt][2], s[nt][3]));
        }
        mx0 = fmaxf(mx0, __shfl_xor_sync(0xffffffffu, mx0, 1));
        mx0 = fmaxf(mx0, __shfl_xor_sync(0xffffffffu, mx0, 2));
        mx1 = fmaxf(mx1, __shfl_xor_sync(0xffffffffu, mx1, 1));
        mx1 = fmaxf(mx1, __shfl_xor_sync(0xffffffffu, mx1, 2));
        float nm0 = fmaxf(m0, mx0), nm1 = fmaxf(m1, mx1);
        float a0 = __expf(m0 - nm0), a1 = __expf(m1 - nm1);
        m0 = nm0; m1 = nm1;
        float ps0 = 0.f, ps1 = 0.f;
        #pragma unroll
        for (int nt = 0; nt < 8; nt++) {
            s[nt][0] = __expf(s[nt][0] - nm0);
            s[nt][1] = __expf(s[nt][1] - nm0);
            s[nt][2] = __expf(s[nt][2] - nm1);
            s[nt][3] = __expf(s[nt][3] - nm1);
            ps0 += s[nt][0] + s[nt][1];
            ps1 += s[nt][2] + s[nt][3];
        }
        ps0 += __shfl_xor_sync(0xffffffffu, ps0, 1);
        ps0 += __shfl_xor_sync(0xffffffffu, ps0, 2);
        ps1 += __shfl_xor_sync(0xffffffffu, ps1, 1);
        ps1 += __shfl_xor_sync(0xffffffffu, ps1, 2);
        l0 = l0 * a0 + ps0;
        l1 = l1 * a1 + ps1;
        #pragma unroll
        for (int nt = 0; nt < 8; nt++) {
            O[nt][0] *= a0; O[nt][1] *= a0;
            O[nt][2] *= a1; O[nt][3] *= a1;
        }
        // ---- P -> bf16 hi/lo A-fragments ----
        uint32_t pH[4][4], pL[4][4];
        #pragma unroll
        for (int ks = 0; ks < 4; ks++) {
            #pragma unroll
            for (int half = 0; half < 2; half++) {
                const int nt = 2*ks + half;
                bf16 h0 = __float2bfloat16(s[nt][0]);
                bf16 h1 = __float2bfloat16(s[nt][1]);
                bf16 h2 = __float2bfloat16(s[nt][2]);
                bf16 h3 = __float2bfloat16(s[nt][3]);
                pH[ks][2*half]   = (uint32_t)bfbits(h0) | ((uint32_t)bfbits(h1) << 16);
                pH[ks][2*half+1] = (uint32_t)bfbits(h2) | ((uint32_t)bfbits(h3) << 16);
                bf16 e0 = __float2bfloat16(s[nt][0] - __bfloat162float(h0));
                bf16 e1 = __float2bfloat16(s[nt][1] - __bfloat162float(h1));
                bf16 e2 = __float2bfloat16(s[nt][2] - __bfloat162float(h2));
                bf16 e3 = __float2bfloat16(s[nt][3] - __bfloat162float(h3));
                pL[ks][2*half]   = (uint32_t)bfbits(e0) | ((uint32_t)bfbits(e1) << 16);
                pL[ks][2*half+1] = (uint32_t)bfbits(e2) | ((uint32_t)bfbits(e3) << 16);
            }
        }
        // ---- O += P V^T ----
        #pragma unroll
        for (int nt = 0; nt < 8; nt++) {
            const int nr = (nt*8 + g) * 36;
            #pragma unroll
            for (int ks = 0; ks < 4; ks++) {
                uint32_t bh[2] = { V32h[nr + ks*8 + t4], V32h[nr + ks*8 + 4 + t4] };
                uint32_t bl[2] = { V32l[nr + ks*8 + t4], V32l[nr + ks*8 + 4 + t4] };
                mma16816(O[nt], pH[ks], bh);
                mma16816(O[nt], pH[ks], bl);
                mma16816(O[nt], pL[ks], bh);
            }
        }
    }

    // ---- epilogue ----
    const float il0 = 1.0f / l0, il1 = 1.0f / l1;
    const size_t row0 = (size_t)(b*SEQ + q0 + wid*16 + g);
    const size_t row8 = row0 + 8;
    #pragma unroll
    for (int nt = 0; nt < 8; nt++) {
        const int col = h*64 + nt*8 + 2*t4;
        bf16 h0, l0b, h1, l1b;
        split(O[nt][0] * il0, &h0, &l0b);
        split(O[nt][1] * il0, &h1, &l1b);
        *(uint32_t*)(g_ctx_h + row0*1024 + col) =
            (uint32_t)bfbits(h0) | ((uint32_t)bfbits(h1) << 16);
        *(uint32_t*)(g_ctx_l + row0*1024 + col) =
            (uint32_t)bfbits(l0b) | ((uint32_t)bfbits(l1b) << 16);
        split(O[nt][2] * il1, &h0, &l0b);
        split(O[nt][3] * il1, &h1, &l1b);
        *(uint32_t*)(g_ctx_h + row8*1024 + col) =
            (uint32_t)bfbits(h0) | ((uint32_t)bfbits(h1) << 16);
        *(uint32_t*)(g_ctx_l + row8*1024 + col) =
            (uint32_t)bfbits(l0b) | ((uint32_t)bfbits(l1b) << 16);
    }
}

// ---------------------------------------------------------------------------
// mma.sync GEMM core (identical to R7/R9)
// ---------------------------------------------------------------------------
template<int NT, int EPI>
__device__ __forceinline__ void tcore(
    const bf16* __restrict__ Ah, const bf16* __restrict__ Al, int lda,
    const bf16* __restrict__ Bh, const bf16* __restrict__ Bl, int ldb,
    int K, int bm, int bn,
    float* __restrict__ Cf, int ldc,
    bf16* __restrict__ Oh, bf16* __restrict__ Ol, int ldo,
    const float* __restrict__ bias, const float* __restrict__ resid)
{
    constexpr int RS   = 40;
    constexpr int WN   = NT / 2;
    constexpr int NTIL = WN / 8;
    __shared__ __align__(16) uint16_t sAh[128*RS], sAl[128*RS];
    __shared__ __align__(16) uint16_t sBh[NT*RS],  sBl[NT*RS];

    const int tid = threadIdx.x, wid = tid >> 5, lane = tid & 31;
    const int wm = wid & 3, wn = wid >> 2;
    const int g = lane >> 2, t4 = lane & 3;

    const int ar = tid >> 1, akq = (tid & 1) * 16;
    const int br128 = tid >> 1, bkq128 = (tid & 1) * 16;
    const int br64 = tid >> 2, bkq64 = (tid & 3) * 8;

    float acc[2][NTIL][4];
    #pragma unroll
    for (int i = 0; i < 2; i++)
        #pragma unroll
        for (int j = 0; j < NTIL; j++)
            #pragma unroll
            for (int e = 0; e < 4; e++) acc[i][j][e] = 0.f;

    uint4 pAh[2], pAl[2], pBh[2], pBl[2];
    auto prefetch = [&](int k0) {
        const bf16* a_h = Ah + (size_t)(bm + ar) * lda + k0 + akq;
        const bf16* a_l = Al + (size_t)(bm + ar) * lda + k0 + akq;
        pAh[0] = *(const uint4*)a_h;       pAh[1] = *(const uint4*)(a_h + 8);
        pAl[0] = *(const uint4*)a_l;       pAl[1] = *(const uint4*)(a_l + 8);
        if (NT == 128) {
            const bf16* b_h = Bh + (size_t)(bn + br128) * ldb + k0 + bkq128;
            const bf16* b_l = Bl + (size_t)(bn + br128) * ldb + k0 + bkq128;
            pBh[0] = *(const uint4*)b_h;   pBh[1] = *(const uint4*)(b_h + 8);
            pBl[0] = *(const uint4*)b_l;   pBl[1] = *(const uint4*)(b_l + 8);
        } else {
            pBh[0] = *(const uint4*)(Bh + (size_t)(bn + br64) * ldb + k0 + bkq64);
            pBl[0] = *(const uint4*)(Bl + (size_t)(bn + br64) * ldb + k0 + bkq64);
        }
    };
    auto store_smem = [&]() {
        *(uint4*)&sAh[ar*RS + akq]     = pAh[0];
        *(uint4*)&sAh[ar*RS + akq + 8] = pAh[1];
        *(uint4*)&sAl[ar*RS + akq]     = pAl[0];
        *(uint4*)&sAl[ar*RS + akq + 8] = pAl[1];
        if (NT == 128) {
            *(uint4*)&sBh[br128*RS + bkq128]     = pBh[0];
            *(uint4*)&sBh[br128*RS + bkq128 + 8] = pBh[1];
            *(uint4*)&sBl[br128*RS + bkq128]     = pBl[0];
            *(uint4*)&sBl[br128*RS + bkq128 + 8] = pBl[1];
        } else {
            *(uint4*)&sBh[br64*RS + bkq64] = pBh[0];
            *(uint4*)&sBl[br64*RS + bkq64] = pBl[0];
        }
    };

    const uint32_t* A32h = (const uint32_t*)sAh;
    const uint32_t* A32l = (const uint32_t*)sAl;
    const uint32_t* B32h = (const uint32_t*)sBh;
    const uint32_t* B32l = (const uint32_t*)sBl;
    const int RS2 = RS / 2;

    const int nch = K >> 5;
    prefetch(0);
    for (int c = 0; c < nch; c++) {
        __syncthreads();
        store_smem();
        __syncthreads();
        if (c + 1 < nch) prefetch((c + 1) << 5);

        #pragma unroll
        for (int kh = 0; kh < 2; kh++) {
            const int ko = kh * 8;
            uint32_t aH[2][4], aL[2][4];
            #pragma unroll
            for (int mt = 0; mt < 2; mt++) {
                const int r = wm*32 + mt*16 + g;
                aH[mt][0] = A32h[r*RS2 + ko + t4];
                aH[mt][1] = A32h[(r+8)*RS2 + ko + t4];
                aH[mt][2] = A32h[r*RS2 + ko + 4 + t4];
                aH[mt][3] = A32h[(r+8)*RS2 + ko + 4 + t4];
                aL[mt][0] = A32l[r*RS2 + ko + t4];
                aL[mt][1] = A32l[(r+8)*RS2 + ko + t4];
                aL[mt][2] = A32l[r*RS2 + ko + 4 + t4];
                aL[mt][3] = A32l[(r+8)*RS2 + ko + 4 + t4];
            }
            #pragma unroll
            for (int nt = 0; nt < NTIL; nt++) {
                const int nr = wn*WN + nt*8 + g;
                uint32_t bH[2], bL[2];
                bH[0] = B32h[nr*RS2 + ko + t4];
                bH[1] = B32h[nr*RS2 + ko + 4 + t4];
                bL[0] = B32l[nr*RS2 + ko + t4];
                bL[1] = B32l[nr*RS2 + ko + 4 + t4];
                #pragma unroll
                for (int mt = 0; mt < 2; mt++) {
                    mma16816(acc[mt][nt], aH[mt], bH);
                    mma16816(acc[mt][nt], aH[mt], bL);
                    mma16816(acc[mt][nt], aL[mt], bH);
                }
            }
        }
    }

    auto wr = [&](int row, int col, float v0, float v1) {
        if (EPI == 0 || EPI == 1) {
            if (EPI == 1) {
                v0 = fmaxf(v0 + bias[col], 0.f);
                v1 = fmaxf(v1 + bias[col + 1], 0.f);
            }
            bf16 h0, l0, h1, l1;
            split(v0, &h0, &l0); split(v1, &h1, &l1);
            *(uint32_t*)(Oh + (size_t)row * ldo + col) =
                (uint32_t)bfbits(h0) | ((uint32_t)bfbits(h1) << 16);
            *(uint32_t*)(Ol + (size_t)row * ldo + col) =
                (uint32_t)bfbits(l0) | ((uint32_t)bfbits(l1) << 16);
        } else if (EPI == 2) {
            bf16 h0, l0, h1, l1;
            split(v0, &h0, &l0); split(v1, &h1, &l1);
            Oh[(size_t)col * ldo + row] = h0;
            Ol[(size_t)col * ldo + row] = l0;
            Oh[(size_t)(col + 1) * ldo + row] = h1;
            Ol[(size_t)(col + 1) * ldo + row] = l1;
        } else {
            const float* rr = resid + (size_t)row * ldc + col;
            float2 o;
            o.x = v0 + rr[0]; o.y = v1 + rr[1];
            if (EPI == 5) { o.x += bias[col]; o.y += bias[col + 1]; }
            *(float2*)(Cf + (size_t)row * ldc + col) = o;
        }
    };
    #pragma unroll
    for (int mt = 0; mt < 2; mt++) {
        #pragma unroll
        for (int nt = 0; nt < NTIL; nt++) {
            const int row = bm + wm*32 + mt*16 + g;
            const int col = bn + wn*WN + nt*8 + 2*t4;
            wr(row,     col, acc[mt][nt][0], acc[mt][nt][1]);
            wr(row + 8, col, acc[mt][nt][2], acc[mt][nt][3]);
        }
    }
}

// ---------------- wrappers ----------------
__global__ void __launch_bounds__(256) kt_qkv() {
    const int bm = blockIdx.y * 128, bn = blockIdx.x * 128;
    if (blockIdx.z == 0)
        tcore<128,0>(g_xn_h, g_xn_l, 1024, g_wqt_h, g_wqt_l, 1024, 1024,
                     bm, bn, nullptr, 0, g_q_h, g_q_l, 1024, nullptr, nullptr);
    else if (blockIdx.z == 1)
        tcore<128,0>(g_xn_h, g_xn_l, 1024, g_wkt_h, g_wkt_l, 1024, 1024,
                     bm, bn, nullptr, 0, g_k_h, g_k_l, 1024, nullptr, nullptr);
    else
        tcore<128,2>(g_xn_h, g_xn_l, 1024, g_wvt_h, g_wvt_l, 1024, 1024,
                     bm, bn, nullptr, 0, g_vt_h, g_vt_l, 4096, nullptr, nullptr);
}
__global__ void __launch_bounds__(256) kt_wo(const float* __restrict__ x) {
    tcore<128,4>(g_ctx_h, g_ctx_l, 1024, g_wot_h, g_wot_l, 1024, 1024,
                 blockIdx.y*128, blockIdx.x*128,
                 g_x1, 1024, nullptr, nullptr, 0, nullptr, x);
}
__global__ void __launch_bounds__(256) kt_ffn1(const float* __restrict__ b1) {
    tcore<128,1>(g_xn_h, g_xn_l, 1024, g_w1t_h, g_w1t_l, 1024, 1024,
                 blockIdx.y*128, blockIdx.x*128,
                 nullptr, 0, g_ffh_h, g_ffh_l, 4096, b1, nullptr);
}
__global__ void __launch_bounds__(256) kt_ffn2(const float* __restrict__ b2,
                                               float* __restrict__ out) {
    tcore<128,5>(g_ffh_h, g_ffh_l, 4096, g_w2t_h, g_w2t_l, 4096, 4096,
                 blockIdx.y*128, blockIdx.x*128,
                 out, 1024, nullptr, nullptr, 0, b2, g_x1);
}

// ---------------- launch ----------------
extern "C" void kernel_launch(void* const* d_in, const int* in_sizes, int n_in,
                              void* d_out, int out_size)
{
    const float* x      = (const float*)d_in[0];
    const int*   mask   = (const int*)  d_in[1];
    const float* wq     = (const float*)d_in[2];
    const float* wk     = (const float*)d_in[3];
    const float* wv     = (const float*)d_in[4];
    const float* wo     = (const float*)d_in[5];
    const float* w1     = (const float*)d_in[6];
    const float* b1     = (const float*)d_in[7];
    const float* w2     = (const float*)d_in[8];
    const float* b2     = (const float*)d_in[9];
    const float* alpha1 = (const float*)d_in[10];
    const float* bias1  = (const float*)d_in[11];
    const float* alpha2 = (const float*)d_in[12];
    const float* bias2  = (const float*)d_in[13];
    float* out = (float*)d_out;

    k_prep_all<<<12288, 256>>>(wq, wk, wv, wo, w1, w2);

    // sublayer 1
    k_ln<<<NTOK, 256>>>(x, 0, alpha1, bias1);
    kt_qkv<<<dim3(8, 32, 3), 256>>>();
    kt_attn<<<dim3(16, 32), 256>>>(mask);
    kt_wo<<<dim3(8, 32), 256>>>(x);

    // sublayer 2
    k_ln<<<NTOK, 256>>>(x, 1, alpha2, bias2);
    kt_ffn1<<<dim3(32, 32), 256>>>(b1);
    kt_ffn2<<<dim3(8, 32), 256>>>(b2, out);
}

// round 11
// speedup vs baseline: 1.0632x; 1.0632x over previous
#include <cuda_runtime.h>
#include <cuda_bf16.h>
#include <math.h>
#include <stdint.h>

#define DMODEL 1024
#define DFF 4096
#define SEQ 2048
#define NTOK 4096
#define LN_EPS 1e-5f
typedef __nv_bfloat16 bf16;

// ---------------- device-global scratch ----------------
__device__ bf16 g_wqt_h[1u<<20], g_wqt_l[1u<<20];   // [N,K] K-major (wq pre-scaled 0.125)
__device__ bf16 g_wkt_h[1u<<20], g_wkt_l[1u<<20];
__device__ bf16 g_wvt_h[1u<<20], g_wvt_l[1u<<20];
__device__ bf16 g_wot_h[1u<<20], g_wot_l[1u<<20];
__device__ bf16 g_w1t_h[1u<<22], g_w1t_l[1u<<22];   // [4096,1024]
__device__ bf16 g_w2t_h[1u<<22], g_w2t_l[1u<<22];   // [1024,4096]
__device__ bf16 g_xn_h [1u<<22], g_xn_l [1u<<22];
__device__ bf16 g_q_h  [1u<<22], g_q_l  [1u<<22];
__device__ bf16 g_k_h  [1u<<22], g_k_l  [1u<<22];
__device__ bf16 g_vt_h [1u<<22], g_vt_l [1u<<22];   // [1024 dk, 4096 tok]
__device__ bf16 g_ctx_h[1u<<22], g_ctx_l[1u<<22];
__device__ bf16 g_ffh_h[1u<<24], g_ffh_l[1u<<24];   // [4096,4096]
__device__ float g_x1[1u<<22];

// ---------------- helpers ----------------
__device__ __forceinline__ void mma16816(float* d, const uint32_t* a, const uint32_t* b) {
    asm volatile(
        "mma.sync.aligned.m16n8k16.row.col.f32.bf16.bf16.f32 "
        "{%0,%1,%2,%3}, {%4,%5,%6,%7}, {%8,%9}, {%0,%1,%2,%3};"
        : "+f"(d[0]), "+f"(d[1]), "+f"(d[2]), "+f"(d[3])
        : "r"(a[0]), "r"(a[1]), "r"(a[2]), "r"(a[3]), "r"(b[0]), "r"(b[1]));
}
__device__ __forceinline__ uint16_t bfbits(bf16 v) { return __bfloat16_as_ushort(v); }
__device__ __forceinline__ void split(float f, bf16* h, bf16* l) {
    bf16 hh = __float2bfloat16(f);
    *h = hh; *l = __float2bfloat16(f - __bfloat162float(hh));
}
__device__ __forceinline__ void cpa16(uint32_t dst, const void* src) {
    asm volatile("cp.async.cg.shared.global [%0], [%1], 16;" :: "r"(dst), "l"(src) : "memory");
}
#define CP_COMMIT() asm volatile("cp.async.commit_group;" ::: "memory")
#define CP_WAIT(n)  asm volatile("cp.async.wait_group %0;" :: "n"(n) : "memory")

__device__ __forceinline__ float warpSum(float v) {
    #pragma unroll
    for (int o = 16; o > 0; o >>= 1) v += __shfl_down_sync(0xffffffffu, v, o);
    return v;
}
__device__ __forceinline__ float blockSum(float v) {
    __shared__ float sh[8];
    int l = threadIdx.x & 31, w = threadIdx.x >> 5;
    v = warpSum(v);
    if (l == 0) sh[w] = v;
    __syncthreads();
    if (w == 0) { float t = (l < 8) ? sh[l] : 0.f; t = warpSum(t); if (l == 0) sh[0] = t; }
    __syncthreads();
    float r = sh[0]; __syncthreads();
    return r;
}

// ---------------- weight prep: ONE launch for all six weights ----------------
__global__ void __launch_bounds__(256) k_prep_all(
    const float* __restrict__ wq, const float* __restrict__ wk,
    const float* __restrict__ wv, const float* __restrict__ wo,
    const float* __restrict__ w1, const float* __restrict__ w2)
{
    int t = blockIdx.x;
    const float* w; bf16 *th, *tl;
    int K, N, local;
    float scale = 1.0f;
    if (t < 4096) {
        int seg = t >> 10; local = t & 1023;
        K = 1024; N = 1024;
        switch (seg) {
            case 0: w = wq; th = g_wqt_h; tl = g_wqt_l; scale = 0.125f; break;
            case 1: w = wk; th = g_wkt_h; tl = g_wkt_l; break;
            case 2: w = wv; th = g_wvt_h; tl = g_wvt_l; break;
            default: w = wo; th = g_wot_h; tl = g_wot_l; break;
        }
    } else if (t < 8192) {
        local = t - 4096; w = w1; th = g_w1t_h; tl = g_w1t_l; K = 1024; N = 4096;
    } else {
        local = t - 8192; w = w2; th = g_w2t_h; tl = g_w2t_l; K = 4096; N = 1024;
    }
    const int xt = N >> 5;
    const int n0 = (local % xt) * 32, k0 = (local / xt) * 32;

    __shared__ float ts[32][33];
    int tx = threadIdx.x & 31, ty = threadIdx.x >> 5;
    #pragma unroll
    for (int i = 0; i < 4; i++)
        ts[ty + 8*i][tx] = w[(size_t)(k0 + ty + 8*i) * N + n0 + tx];
    __syncthreads();
    #pragma unroll
    for (int i = 0; i < 4; i++) {
        int n = n0 + ty + 8*i, k = k0 + tx;
        split(ts[tx][ty + 8*i] * scale, &th[(size_t)n * K + k], &tl[(size_t)n * K + k]);
    }
}

// ---------------- LayerNorm -> bf16 hi/lo ----------------
__global__ void __launch_bounds__(256) k_ln(const float* __restrict__ xin, int use_x1,
                                            const float* __restrict__ ap,
                                            const float* __restrict__ bp)
{
    const float* src = use_x1 ? g_x1 : xin;
    int row = blockIdx.x, t = threadIdx.x;
    const float* xr = src + (size_t)row * DMODEL;
    float v[4], s = 0.f, sq = 0.f;
    #pragma unroll
    for (int i = 0; i < 4; i++) { v[i] = xr[t + 256*i]; s += v[i]; sq += v[i]*v[i]; }
    s = blockSum(s); sq = blockSum(sq);
    float mean = s * (1.0f / DMODEL);
    float var = fmaxf((sq - (float)DMODEL * mean * mean) * (1.0f / (DMODEL - 1)), 0.f);
    float sc = ap[0] / (sqrtf(var) + LN_EPS);
    float bi = bp[0];
    #pragma unroll
    for (int i = 0; i < 4; i++) {
        size_t o = (size_t)row * DMODEL + t + 256*i;
        split((v[i] - mean) * sc + bi, &g_xn_h[o], &g_xn_l[o]);
    }
}

// ---------------------------------------------------------------------------
// Fused flash attention, cp.async double-buffered K/V (zero register cost).
// Dynamic smem layout (80 KB):
//   [0, 36864)      buffer 0: sKh(9216) sKl(9216) sVh(9216) sVl(9216)
//   [36864, 73728)  buffer 1
//   [73728, 81920)  mask (2048 ints)
// 2 CTAs/SM: 160 KB smem, 128 regs (forced by launch_bounds).
// ---------------------------------------------------------------------------
#define ATTN_SMEM 81920
#define BUFB 36864u
#define TILEB 9216u

__global__ void __launch_bounds__(256, 2) kt_attn(const int* __restrict__ mask)
{
    extern __shared__ __align__(16) uint8_t dynsm[];
    const int z = blockIdx.y, b = z >> 4, h = z & 15;
    const int q0 = blockIdx.x * 128;
    const int tid = threadIdx.x, wid = tid >> 5, lane = tid & 31;
    const int g = lane >> 2, t4 = lane & 3;

    uint32_t sbase;
    asm("{ .reg .u64 t; cvta.to.shared.u64 t, %1; cvt.u32.u64 %0, t; }"
        : "=r"(sbase) : "l"(dynsm));
    int* s_mask = (int*)(dynsm + 2*BUFB);

    for (int i = tid; i < SEQ/4; i += 256)
        *(int4*)&s_mask[i*4] = *(const int4*)&mask[b*SEQ + i*4];

    // Q fragments, register-resident
    uint32_t qh[4][4], ql[4][4];
    {
        const uint32_t* Q32h = (const uint32_t*)g_q_h;
        const uint32_t* Q32l = (const uint32_t*)g_q_l;
        size_t r0 = ((size_t)(b*SEQ + q0 + wid*16 + g)) * 512 + h*32;
        size_t r8 = r0 + 8*512;
        #pragma unroll
        for (int s = 0; s < 4; s++) {
            qh[s][0] = Q32h[r0 + s*8 + t4];
            qh[s][1] = Q32h[r8 + s*8 + t4];
            qh[s][2] = Q32h[r0 + s*8 + 4 + t4];
            qh[s][3] = Q32h[r8 + s*8 + 4 + t4];
            ql[s][0] = Q32l[r0 + s*8 + t4];
            ql[s][1] = Q32l[r8 + s*8 + t4];
            ql[s][2] = Q32l[r0 + s*8 + 4 + t4];
            ql[s][3] = Q32l[r8 + s*8 + 4 + t4];
        }
    }

    float O[8][4];
    #pragma unroll
    for (int i = 0; i < 8; i++)
        #pragma unroll
        for (int j = 0; j < 4; j++) O[i][j] = 0.f;
    float m0 = -INFINITY, m1 = -INFINITY, l0 = 0.f, l1 = 0.f;

    const int krow = tid >> 2, kcb = (tid & 3) * 16;
    const uint32_t soff = (uint32_t)(krow*72 + kcb) * 2u;   // byte offset in tile

    auto load_tile = [&](int kt, int p) {
        const uint32_t base = sbase + p*BUFB;
        size_t gk = ((size_t)(b*SEQ + kt*64 + krow)) * 1024 + h*64 + kcb;
        cpa16(base + 0*TILEB + soff,      &g_k_h[gk]);
        cpa16(base + 0*TILEB + soff + 16, &g_k_h[gk + 8]);
        cpa16(base + 1*TILEB + soff,      &g_k_l[gk]);
        cpa16(base + 1*TILEB + soff + 16, &g_k_l[gk + 8]);
        size_t gv = ((size_t)(h*64 + krow)) * 4096 + b*SEQ + kt*64 + kcb;
        cpa16(base + 2*TILEB + soff,      &g_vt_h[gv]);
        cpa16(base + 2*TILEB + soff + 16, &g_vt_h[gv + 8]);
        cpa16(base + 3*TILEB + soff,      &g_vt_l[gv]);
        cpa16(base + 3*TILEB + soff + 16, &g_vt_l[gv + 8]);
        CP_COMMIT();
    };

    load_tile(0, 0);
    for (int kt = 0; kt < SEQ/64; kt++) {
        __syncthreads();               // all threads done reading buffer (kt+1)&1
        if (kt + 1 < SEQ/64) {
            load_tile(kt + 1, (kt + 1) & 1);
            CP_WAIT(1);                // tile kt resident
        } else {
            CP_WAIT(0);
        }
        __syncthreads();

        const uint8_t* buf = dynsm + (kt & 1) * BUFB;
        const uint32_t* K32h = (const uint32_t*)(buf);
        const uint32_t* K32l = (const uint32_t*)(buf + TILEB);
        const uint32_t* V32h = (const uint32_t*)(buf + 2*TILEB);
        const uint32_t* V32l = (const uint32_t*)(buf + 3*TILEB);

        // ---- S = Q K^T ----
        float s[8][4];
        #pragma unroll
        for (int nt = 0; nt < 8; nt++) {
            s[nt][0] = s[nt][1] = s[nt][2] = s[nt][3] = 0.f;
            const int nr = (nt*8 + g) * 36;
            #pragma unroll
            for (int ks = 0; ks < 4; ks++) {
                uint32_t bh[2] = { K32h[nr + ks*8 + t4], K32h[nr + ks*8 + 4 + t4] };
                uint32_t bl[2] = { K32l[nr + ks*8 + t4], K32l[nr + ks*8 + 4 + t4] };
                mma16816(s[nt], qh[ks], bh);
                mma16816(s[nt], qh[ks], bl);
                mma16816(s[nt], ql[ks], bh);
            }
        }
        // ---- mask ----
        #pragma unroll
        for (int nt = 0; nt < 8; nt++) {
            const int c = kt*64 + nt*8 + 2*t4;
            if (s_mask[c]   == 0) { s[nt][0] = -1e9f; s[nt][2] = -1e9f; }
            if (s_mask[c+1] == 0) { s[nt][1] = -1e9f; s[nt][3] = -1e9f; }
        }
        // ---- online softmax ----
        float mx0 = -INFINITY, mx1 = -INFINITY;
        #pragma unroll
        for (int nt = 0; nt < 8; nt++) {
            mx0 = fmaxf(mx0, fmaxf(s[nt][0], s[nt][1]));
            mx1 = fmaxf(mx1, fmaxf(s[nt][2], s[nt][3]));
        }
        mx0 = fmaxf(mx0, __shfl_xor_sync(0xffffffffu, mx0, 1));
        mx0 = fmaxf(mx0, __shfl_xor_sync(0xffffffffu, mx0, 2));
        mx1 = fmaxf(mx1, __shfl_xor_sync(0xffffffffu, mx1, 1));
        mx1 = fmaxf(mx1, __shfl_xor_sync(0xffffffffu, mx1, 2));
        float nm0 = fmaxf(m0, mx0), nm1 = fmaxf(m1, mx1);
        float a0 = __expf(m0 - nm0), a1 = __expf(m1 - nm1);
        m0 = nm0; m1 = nm1;
        float ps0 = 0.f, ps1 = 0.f;
        #pragma unroll
        for (int nt = 0; nt < 8; nt++) {
            s[nt][0] = __expf(s[nt][0] - nm0);
            s[nt][1] = __expf(s[nt][1] - nm0);
            s[nt][2] = __expf(s[nt][2] - nm1);
            s[nt][3] = __expf(s[nt][3] - nm1);
            ps0 += s[nt][0] + s[nt][1];
            ps1 += s[nt][2] + s[nt][3];
        }
        ps0 += __shfl_xor_sync(0xffffffffu, ps0, 1);
        ps0 += __shfl_xor_sync(0xffffffffu, ps0, 2);
        ps1 += __shfl_xor_sync(0xffffffffu, ps1, 1);
        ps1 += __shfl_xor_sync(0xffffffffu, ps1, 2);
        l0 = l0 * a0 + ps0;
        l1 = l1 * a1 + ps1;
        #pragma unroll
        for (int nt = 0; nt < 8; nt++) {
            O[nt][0] *= a0; O[nt][1] *= a0;
            O[nt][2] *= a1; O[nt][3] *= a1;
        }
        // ---- P -> bf16 hi/lo A-fragments ----
        uint32_t pH[4][4], pL[4][4];
        #pragma unroll
        for (int ks = 0; ks < 4; ks++) {
            #pragma unroll
            for (int half = 0; half < 2; half++) {
                const int nt = 2*ks + half;
                bf16 h0 = __float2bfloat16(s[nt][0]);
                bf16 h1 = __float2bfloat16(s[nt][1]);
                bf16 h2 = __float2bfloat16(s[nt][2]);
                bf16 h3 = __float2bfloat16(s[nt][3]);
                pH[ks][2*half]   = (uint32_t)bfbits(h0) | ((uint32_t)bfbits(h1) << 16);
                pH[ks][2*half+1] = (uint32_t)bfbits(h2) | ((uint32_t)bfbits(h3) << 16);
                bf16 e0 = __float2bfloat16(s[nt][0] - __bfloat162float(h0));
                bf16 e1 = __float2bfloat16(s[nt][1] - __bfloat162float(h1));
                bf16 e2 = __float2bfloat16(s[nt][2] - __bfloat162float(h2));
                bf16 e3 = __float2bfloat16(s[nt][3] - __bfloat162float(h3));
                pL[ks][2*half]   = (uint32_t)bfbits(e0) | ((uint32_t)bfbits(e1) << 16);
                pL[ks][2*half+1] = (uint32_t)bfbits(e2) | ((uint32_t)bfbits(e3) << 16);
            }
        }
        // ---- O += P V^T ----
        #pragma unroll
        for (int nt = 0; nt < 8; nt++) {
            const int nr = (nt*8 + g) * 36;
            #pragma unroll
            for (int ks = 0; ks < 4; ks++) {
                uint32_t bh[2] = { V32h[nr + ks*8 + t4], V32h[nr + ks*8 + 4 + t4] };
                uint32_t bl[2] = { V32l[nr + ks*8 + t4], V32l[nr + ks*8 + 4 + t4] };
                mma16816(O[nt], pH[ks], bh);
                mma16816(O[nt], pH[ks], bl);
                mma16816(O[nt], pL[ks], bh);
            }
        }
    }

    // ---- epilogue ----
    const float il0 = 1.0f / l0, il1 = 1.0f / l1;
    const size_t row0 = (size_t)(b*SEQ + q0 + wid*16 + g);
    const size_t row8 = row0 + 8;
    #pragma unroll
    for (int nt = 0; nt < 8; nt++) {
        const int col = h*64 + nt*8 + 2*t4;
        bf16 h0, l0b, h1, l1b;
        split(O[nt][0] * il0, &h0, &l0b);
        split(O[nt][1] * il0, &h1, &l1b);
        *(uint32_t*)(g_ctx_h + row0*1024 + col) =
            (uint32_t)bfbits(h0) | ((uint32_t)bfbits(h1) << 16);
        *(uint32_t*)(g_ctx_l + row0*1024 + col) =
            (uint32_t)bfbits(l0b) | ((uint32_t)bfbits(l1b) << 16);
        split(O[nt][2] * il1, &h0, &l0b);
        split(O[nt][3] * il1, &h1, &l1b);
        *(uint32_t*)(g_ctx_h + row8*1024 + col) =
            (uint32_t)bfbits(h0) | ((uint32_t)bfbits(h1) << 16);
        *(uint32_t*)(g_ctx_l + row8*1024 + col) =
            (uint32_t)bfbits(l0b) | ((uint32_t)bfbits(l1b) << 16);
    }
}

// ---------------------------------------------------------------------------
// mma.sync GEMM core (identical to R7/R9)
// ---------------------------------------------------------------------------
template<int NT, int EPI>
__device__ __forceinline__ void tcore(
    const bf16* __restrict__ Ah, const bf16* __restrict__ Al, int lda,
    const bf16* __restrict__ Bh, const bf16* __restrict__ Bl, int ldb,
    int K, int bm, int bn,
    float* __restrict__ Cf, int ldc,
    bf16* __restrict__ Oh, bf16* __restrict__ Ol, int ldo,
    const float* __restrict__ bias, const float* __restrict__ resid)
{
    constexpr int RS   = 40;
    constexpr int WN   = NT / 2;
    constexpr int NTIL = WN / 8;
    __shared__ __align__(16) uint16_t sAh[128*RS], sAl[128*RS];
    __shared__ __align__(16) uint16_t sBh[NT*RS],  sBl[NT*RS];

    const int tid = threadIdx.x, wid = tid >> 5, lane = tid & 31;
    const int wm = wid & 3, wn = wid >> 2;
    const int g = lane >> 2, t4 = lane & 3;

    const int ar = tid >> 1, akq = (tid & 1) * 16;
    const int br128 = tid >> 1, bkq128 = (tid & 1) * 16;
    const int br64 = tid >> 2, bkq64 = (tid & 3) * 8;

    float acc[2][NTIL][4];
    #pragma unroll
    for (int i = 0; i < 2; i++)
        #pragma unroll
        for (int j = 0; j < NTIL; j++)
            #pragma unroll
            for (int e = 0; e < 4; e++) acc[i][j][e] = 0.f;

    uint4 pAh[2], pAl[2], pBh[2], pBl[2];
    auto prefetch = [&](int k0) {
        const bf16* a_h = Ah + (size_t)(bm + ar) * lda + k0 + akq;
        const bf16* a_l = Al + (size_t)(bm + ar) * lda + k0 + akq;
        pAh[0] = *(const uint4*)a_h;       pAh[1] = *(const uint4*)(a_h + 8);
        pAl[0] = *(const uint4*)a_l;       pAl[1] = *(const uint4*)(a_l + 8);
        if (NT == 128) {
            const bf16* b_h = Bh + (size_t)(bn + br128) * ldb + k0 + bkq128;
            const bf16* b_l = Bl + (size_t)(bn + br128) * ldb + k0 + bkq128;
            pBh[0] = *(const uint4*)b_h;   pBh[1] = *(const uint4*)(b_h + 8);
            pBl[0] = *(const uint4*)b_l;   pBl[1] = *(const uint4*)(b_l + 8);
        } else {
            pBh[0] = *(const uint4*)(Bh + (size_t)(bn + br64) * ldb + k0 + bkq64);
            pBl[0] = *(const uint4*)(Bl + (size_t)(bn + br64) * ldb + k0 + bkq64);
        }
    };
    auto store_smem = [&]() {
        *(uint4*)&sAh[ar*RS + akq]     = pAh[0];
        *(uint4*)&sAh[ar*RS + akq + 8] = pAh[1];
        *(uint4*)&sAl[ar*RS + akq]     = pAl[0];
        *(uint4*)&sAl[ar*RS + akq + 8] = pAl[1];
        if (NT == 128) {
            *(uint4*)&sBh[br128*RS + bkq128]     = pBh[0];
            *(uint4*)&sBh[br128*RS + bkq128 + 8] = pBh[1];
            *(uint4*)&sBl[br128*RS + bkq128]     = pBl[0];
            *(uint4*)&sBl[br128*RS + bkq128 + 8] = pBl[1];
        } else {
            *(uint4*)&sBh[br64*RS + bkq64] = pBh[0];
            *(uint4*)&sBl[br64*RS + bkq64] = pBl[0];
        }
    };

    const uint32_t* A32h = (const uint32_t*)sAh;
    const uint32_t* A32l = (const uint32_t*)sAl;
    const uint32_t* B32h = (const uint32_t*)sBh;
    const uint32_t* B32l = (const uint32_t*)sBl;
    const int RS2 = RS / 2;

    const int nch = K >> 5;
    prefetch(0);
    for (int c = 0; c < nch; c++) {
        __syncthreads();
        store_smem();
        __syncthreads();
        if (c + 1 < nch) prefetch((c + 1) << 5);

        #pragma unroll
        for (int kh = 0; kh < 2; kh++) {
            const int ko = kh * 8;
            uint32_t aH[2][4], aL[2][4];
            #pragma unroll
            for (int mt = 0; mt < 2; mt++) {
                const int r = wm*32 + mt*16 + g;
                aH[mt][0] = A32h[r*RS2 + ko + t4];
                aH[mt][1] = A32h[(r+8)*RS2 + ko + t4];
                aH[mt][2] = A32h[r*RS2 + ko + 4 + t4];
                aH[mt][3] = A32h[(r+8)*RS2 + ko + 4 + t4];
                aL[mt][0] = A32l[r*RS2 + ko + t4];
                aL[mt][1] = A32l[(r+8)*RS2 + ko + t4];
                aL[mt][2] = A32l[r*RS2 + ko + 4 + t4];
                aL[mt][3] = A32l[(r+8)*RS2 + ko + 4 + t4];
            }
            #pragma unroll
            for (int nt = 0; nt < NTIL; nt++) {
                const int nr = wn*WN + nt*8 + g;
                uint32_t bH[2], bL[2];
                bH[0] = B32h[nr*RS2 + ko + t4];
                bH[1] = B32h[nr*RS2 + ko + 4 + t4];
                bL[0] = B32l[nr*RS2 + ko + t4];
                bL[1] = B32l[nr*RS2 + ko + 4 + t4];
                #pragma unroll
                for (int mt = 0; mt < 2; mt++) {
                    mma16816(acc[mt][nt], aH[mt], bH);
                    mma16816(acc[mt][nt], aH[mt], bL);
                    mma16816(acc[mt][nt], aL[mt], bH);
                }
            }
        }
    }

    auto wr = [&](int row, int col, float v0, float v1) {
        if (EPI == 0 || EPI == 1) {
            if (EPI == 1) {
                v0 = fmaxf(v0 + bias[col], 0.f);
                v1 = fmaxf(v1 + bias[col + 1], 0.f);
            }
            bf16 h0, l0, h1, l1;
            split(v0, &h0, &l0); split(v1, &h1, &l1);
            *(uint32_t*)(Oh + (size_t)row * ldo + col) =
                (uint32_t)bfbits(h0) | ((uint32_t)bfbits(h1) << 16);
            *(uint32_t*)(Ol + (size_t)row * ldo + col) =
                (uint32_t)bfbits(l0) | ((uint32_t)bfbits(l1) << 16);
        } else if (EPI == 2) {
            bf16 h0, l0, h1, l1;
            split(v0, &h0, &l0); split(v1, &h1, &l1);
            Oh[(size_t)col * ldo + row] = h0;
            Ol[(size_t)col * ldo + row] = l0;
            Oh[(size_t)(col + 1) * ldo + row] = h1;
            Ol[(size_t)(col + 1) * ldo + row] = l1;
        } else {
            const float* rr = resid + (size_t)row * ldc + col;
            float2 o;
            o.x = v0 + rr[0]; o.y = v1 + rr[1];
            if (EPI == 5) { o.x += bias[col]; o.y += bias[col + 1]; }
            *(float2*)(Cf + (size_t)row * ldc + col) = o;
        }
    };
    #pragma unroll
    for (int mt = 0; mt < 2; mt++) {
        #pragma unroll
        for (int nt = 0; nt < NTIL; nt++) {
            const int row = bm + wm*32 + mt*16 + g;
            const int col = bn + wn*WN + nt*8 + 2*t4;
            wr(row,     col, acc[mt][nt][0], acc[mt][nt][1]);
            wr(row + 8, col, acc[mt][nt][2], acc[mt][nt][3]);
        }
    }
}

// ---------------- wrappers ----------------
__global__ void __launch_bounds__(256) kt_qkv() {
    const int bm = blockIdx.y * 128, bn = blockIdx.x * 128;
    if (blockIdx.z == 0)
        tcore<128,0>(g_xn_h, g_xn_l, 1024, g_wqt_h, g_wqt_l, 1024, 1024,
                     bm, bn, nullptr, 0, g_q_h, g_q_l, 1024, nullptr, nullptr);
    else if (blockIdx.z == 1)
        tcore<128,0>(g_xn_h, g_xn_l, 1024, g_wkt_h, g_wkt_l, 1024, 1024,
                     bm, bn, nullptr, 0, g_k_h, g_k_l, 1024, nullptr, nullptr);
    else
        tcore<128,2>(g_xn_h, g_xn_l, 1024, g_wvt_h, g_wvt_l, 1024, 1024,
                     bm, bn, nullptr, 0, g_vt_h, g_vt_l, 4096, nullptr, nullptr);
}
__global__ void __launch_bounds__(256) kt_wo(const float* __restrict__ x) {
    tcore<128,4>(g_ctx_h, g_ctx_l, 1024, g_wot_h, g_wot_l, 1024, 1024,
                 blockIdx.y*128, blockIdx.x*128,
                 g_x1, 1024, nullptr, nullptr, 0, nullptr, x);
}
__global__ void __launch_bounds__(256) kt_ffn1(const float* __restrict__ b1) {
    tcore<128,1>(g_xn_h, g_xn_l, 1024, g_w1t_h, g_w1t_l, 1024, 1024,
                 blockIdx.y*128, blockIdx.x*128,
                 nullptr, 0, g_ffh_h, g_ffh_l, 4096, b1, nullptr);
}
__global__ void __launch_bounds__(256) kt_ffn2(const float* __restrict__ b2,
                                               float* __restrict__ out) {
    tcore<128,5>(g_ffh_h, g_ffh_l, 4096, g_w2t_h, g_w2t_l, 4096, 4096,
                 blockIdx.y*128, blockIdx.x*128,
                 out, 1024, nullptr, nullptr, 0, b2, g_x1);
}

// ---------------- launch ----------------
extern "C" void kernel_launch(void* const* d_in, const int* in_sizes, int n_in,
                              void* d_out, int out_size)
{
    const float* x      = (const float*)d_in[0];
    const int*   mask   = (const int*)  d_in[1];
    const float* wq     = (const float*)d_in[2];
    const float* wk     = (const float*)d_in[3];
    const float* wv     = (const float*)d_in[4];
    const float* wo     = (const float*)d_in[5];
    const float* w1     = (const float*)d_in[6];
    const float* b1     = (const float*)d_in[7];
    const float* w2     = (const float*)d_in[8];
    const float* b2     = (const float*)d_in[9];
    const float* alpha1 = (const float*)d_in[10];
    const float* bias1  = (const float*)d_in[11];
    const float* alpha2 = (const float*)d_in[12];
    const float* bias2  = (const float*)d_in[13];
    float* out = (float*)d_out;

    static int smem_set = 0;
    if (!smem_set) {
        cudaFuncSetAttribute(kt_attn, cudaFuncAttributeMaxDynamicSharedMemorySize, ATTN_SMEM);
        smem_set = 1;
    }

    k_prep_all<<<12288, 256>>>(wq, wk, wv, wo, w1, w2);

    // sublayer 1
    k_ln<<<NTOK, 256>>>(x, 0, alpha1, bias1);
    kt_qkv<<<dim3(8, 32, 3), 256>>>();
    kt_attn<<<dim3(16, 32), 256, ATTN_SMEM>>>(mask);
    kt_wo<<<dim3(8, 32), 256>>>(x);

    // sublayer 2
    k_ln<<<NTOK, 256>>>(x, 1, alpha2, bias2);
    kt_ffn1<<<dim3(32, 32), 256>>>(b1);
    kt_ffn2<<<dim3(8, 32), 256>>>(b2, out);
}

// round 12
// speedup vs baseline: 1.1689x; 1.0994x over previous
#include <cuda_runtime.h>
#include <cuda_bf16.h>
#include <math.h>
#include <stdint.h>

#define DMODEL 1024
#define DFF 4096
#define SEQ 2048
#define NTOK 4096
#define LN_EPS 1e-5f
typedef __nv_bfloat16 bf16;

// ---------------- device-global scratch ----------------
__device__ bf16 g_wqt_h[1u<<20], g_wqt_l[1u<<20];   // [N,K] K-major (wq pre-scaled 0.125)
__device__ bf16 g_wkt_h[1u<<20], g_wkt_l[1u<<20];
__device__ bf16 g_wvt_h[1u<<20], g_wvt_l[1u<<20];
__device__ bf16 g_wot_h[1u<<20], g_wot_l[1u<<20];
__device__ bf16 g_w1t_h[1u<<22], g_w1t_l[1u<<22];   // [4096,1024]
__device__ bf16 g_w2t_h[1u<<22], g_w2t_l[1u<<22];   // [1024,4096]
__device__ bf16 g_xn_h [1u<<22], g_xn_l [1u<<22];
__device__ bf16 g_q_h  [1u<<22], g_q_l  [1u<<22];
__device__ bf16 g_k_h  [1u<<22], g_k_l  [1u<<22];
__device__ bf16 g_vt_h [1u<<22], g_vt_l [1u<<22];   // [1024 dk, 4096 tok]
__device__ bf16 g_ctx_h[1u<<22], g_ctx_l[1u<<22];
__device__ bf16 g_ffh_h[1u<<24], g_ffh_l[1u<<24];   // [4096,4096]
__device__ float g_x1[1u<<22];

// ---------------- helpers ----------------
__device__ __forceinline__ void mma16816(float* d, const uint32_t* a, const uint32_t* b) {
    asm volatile(
        "mma.sync.aligned.m16n8k16.row.col.f32.bf16.bf16.f32 "
        "{%0,%1,%2,%3}, {%4,%5,%6,%7}, {%8,%9}, {%0,%1,%2,%3};"
        : "+f"(d[0]), "+f"(d[1]), "+f"(d[2]), "+f"(d[3])
        : "r"(a[0]), "r"(a[1]), "r"(a[2]), "r"(a[3]), "r"(b[0]), "r"(b[1]));
}
__device__ __forceinline__ uint16_t bfbits(bf16 v) { return __bfloat16_as_ushort(v); }
__device__ __forceinline__ void split(float f, bf16* h, bf16* l) {
    bf16 hh = __float2bfloat16(f);
    *h = hh; *l = __float2bfloat16(f - __bfloat162float(hh));
}
__device__ __forceinline__ void cpa16(uint32_t dst, const void* src) {
    asm volatile("cp.async.cg.shared.global [%0], [%1], 16;" :: "r"(dst), "l"(src) : "memory");
}
#define CP_COMMIT() asm volatile("cp.async.commit_group;" ::: "memory")
#define CP_WAIT(n)  asm volatile("cp.async.wait_group %0;" :: "n"(n) : "memory")
__device__ __forceinline__ uint32_t smem_u32(const void* p) {
    uint32_t a;
    asm("{ .reg .u64 t; cvta.to.shared.u64 t, %1; cvt.u32.u64 %0, t; }" : "=r"(a) : "l"(p));
    return a;
}

__device__ __forceinline__ float warpSum(float v) {
    #pragma unroll
    for (int o = 16; o > 0; o >>= 1) v += __shfl_down_sync(0xffffffffu, v, o);
    return v;
}
__device__ __forceinline__ float blockSum(float v) {
    __shared__ float sh[8];
    int l = threadIdx.x & 31, w = threadIdx.x >> 5;
    v = warpSum(v);
    if (l == 0) sh[w] = v;
    __syncthreads();
    if (w == 0) { float t = (l < 8) ? sh[l] : 0.f; t = warpSum(t); if (l == 0) sh[0] = t; }
    __syncthreads();
    float r = sh[0]; __syncthreads();
    return r;
}

// ---------------- weight prep: ONE launch for all six weights ----------------
__global__ void __launch_bounds__(256) k_prep_all(
    const float* __restrict__ wq, const float* __restrict__ wk,
    const float* __restrict__ wv, const float* __restrict__ wo,
    const float* __restrict__ w1, const float* __restrict__ w2)
{
    int t = blockIdx.x;
    const float* w; bf16 *th, *tl;
    int K, N, local;
    float scale = 1.0f;
    if (t < 4096) {
        int seg = t >> 10; local = t & 1023;
        K = 1024; N = 1024;
        switch (seg) {
            case 0: w = wq; th = g_wqt_h; tl = g_wqt_l; scale = 0.125f; break;
            case 1: w = wk; th = g_wkt_h; tl = g_wkt_l; break;
            case 2: w = wv; th = g_wvt_h; tl = g_wvt_l; break;
            default: w = wo; th = g_wot_h; tl = g_wot_l; break;
        }
    } else if (t < 8192) {
        local = t - 4096; w = w1; th = g_w1t_h; tl = g_w1t_l; K = 1024; N = 4096;
    } else {
        local = t - 8192; w = w2; th = g_w2t_h; tl = g_w2t_l; K = 4096; N = 1024;
    }
    const int xt = N >> 5;
    const int n0 = (local % xt) * 32, k0 = (local / xt) * 32;

    __shared__ float ts[32][33];
    int tx = threadIdx.x & 31, ty = threadIdx.x >> 5;
    #pragma unroll
    for (int i = 0; i < 4; i++)
        ts[ty + 8*i][tx] = w[(size_t)(k0 + ty + 8*i) * N + n0 + tx];
    __syncthreads();
    #pragma unroll
    for (int i = 0; i < 4; i++) {
        int n = n0 + ty + 8*i, k = k0 + tx;
        split(ts[tx][ty + 8*i] * scale, &th[(size_t)n * K + k], &tl[(size_t)n * K + k]);
    }
}

// ---------------- LayerNorm -> bf16 hi/lo ----------------
__global__ void __launch_bounds__(256) k_ln(const float* __restrict__ xin, int use_x1,
                                            const float* __restrict__ ap,
                                            const float* __restrict__ bp)
{
    const float* src = use_x1 ? g_x1 : xin;
    int row = blockIdx.x, t = threadIdx.x;
    const float* xr = src + (size_t)row * DMODEL;
    float v[4], s = 0.f, sq = 0.f;
    #pragma unroll
    for (int i = 0; i < 4; i++) { v[i] = xr[t + 256*i]; s += v[i]; sq += v[i]*v[i]; }
    s = blockSum(s); sq = blockSum(sq);
    float mean = s * (1.0f / DMODEL);
    float var = fmaxf((sq - (float)DMODEL * mean * mean) * (1.0f / (DMODEL - 1)), 0.f);
    float sc = ap[0] / (sqrtf(var) + LN_EPS);
    float bi = bp[0];
    #pragma unroll
    for (int i = 0; i < 4; i++) {
        size_t o = (size_t)row * DMODEL + t + 256*i;
        split((v[i] - mean) * sc + bi, &g_xn_h[o], &g_xn_l[o]);
    }
}

// ---------------------------------------------------------------------------
// Fused flash attention, cp.async double-buffered K/V (identical to R11).
// ---------------------------------------------------------------------------
#define ATTN_SMEM 81920
#define BUFB 36864u
#define TILEB 9216u

__global__ void __launch_bounds__(256, 2) kt_attn(const int* __restrict__ mask)
{
    extern __shared__ __align__(16) uint8_t dynsm[];
    const int z = blockIdx.y, b = z >> 4, h = z & 15;
    const int q0 = blockIdx.x * 128;
    const int tid = threadIdx.x, wid = tid >> 5, lane = tid & 31;
    const int g = lane >> 2, t4 = lane & 3;

    uint32_t sbase = smem_u32(dynsm);
    int* s_mask = (int*)(dynsm + 2*BUFB);

    for (int i = tid; i < SEQ/4; i += 256)
        *(int4*)&s_mask[i*4] = *(const int4*)&mask[b*SEQ + i*4];

    uint32_t qh[4][4], ql[4][4];
    {
        const uint32_t* Q32h = (const uint32_t*)g_q_h;
        const uint32_t* Q32l = (const uint32_t*)g_q_l;
        size_t r0 = ((size_t)(b*SEQ + q0 + wid*16 + g)) * 512 + h*32;
        size_t r8 = r0 + 8*512;
        #pragma unroll
        for (int s = 0; s < 4; s++) {
            qh[s][0] = Q32h[r0 + s*8 + t4];
            qh[s][1] = Q32h[r8 + s*8 + t4];
            qh[s][2] = Q32h[r0 + s*8 + 4 + t4];
            qh[s][3] = Q32h[r8 + s*8 + 4 + t4];
            ql[s][0] = Q32l[r0 + s*8 + t4];
            ql[s][1] = Q32l[r8 + s*8 + t4];
            ql[s][2] = Q32l[r0 + s*8 + 4 + t4];
            ql[s][3] = Q32l[r8 + s*8 + 4 + t4];
        }
    }

    float O[8][4];
    #pragma unroll
    for (int i = 0; i < 8; i++)
        #pragma unroll
        for (int j = 0; j < 4; j++) O[i][j] = 0.f;
    float m0 = -INFINITY, m1 = -INFINITY, l0 = 0.f, l1 = 0.f;

    const int krow = tid >> 2, kcb = (tid & 3) * 16;
    const uint32_t soff = (uint32_t)(krow*72 + kcb) * 2u;

    auto load_tile = [&](int kt, int p) {
        const uint32_t base = sbase + p*BUFB;
        size_t gk = ((size_t)(b*SEQ + kt*64 + krow)) * 1024 + h*64 + kcb;
        cpa16(base + 0*TILEB + soff,      &g_k_h[gk]);
        cpa16(base + 0*TILEB + soff + 16, &g_k_h[gk + 8]);
        cpa16(base + 1*TILEB + soff,      &g_k_l[gk]);
        cpa16(base + 1*TILEB + soff + 16, &g_k_l[gk + 8]);
        size_t gv = ((size_t)(h*64 + krow)) * 4096 + b*SEQ + kt*64 + kcb;
        cpa16(base + 2*TILEB + soff,      &g_vt_h[gv]);
        cpa16(base + 2*TILEB + soff + 16, &g_vt_h[gv + 8]);
        cpa16(base + 3*TILEB + soff,      &g_vt_l[gv]);
        cpa16(base + 3*TILEB + soff + 16, &g_vt_l[gv + 8]);
        CP_COMMIT();
    };

    load_tile(0, 0);
    for (int kt = 0; kt < SEQ/64; kt++) {
        __syncthreads();
        if (kt + 1 < SEQ/64) {
            load_tile(kt + 1, (kt + 1) & 1);
            CP_WAIT(1);
        } else {
            CP_WAIT(0);
        }
        __syncthreads();

        const uint8_t* buf = dynsm + (kt & 1) * BUFB;
        const uint32_t* K32h = (const uint32_t*)(buf);
        const uint32_t* K32l = (const uint32_t*)(buf + TILEB);
        const uint32_t* V32h = (const uint32_t*)(buf + 2*TILEB);
        const uint32_t* V32l = (const uint32_t*)(buf + 3*TILEB);

        float s[8][4];
        #pragma unroll
        for (int nt = 0; nt < 8; nt++) {
            s[nt][0] = s[nt][1] = s[nt][2] = s[nt][3] = 0.f;
            const int nr = (nt*8 + g) * 36;
            #pragma unroll
            for (int ks = 0; ks < 4; ks++) {
                uint32_t bh[2] = { K32h[nr + ks*8 + t4], K32h[nr + ks*8 + 4 + t4] };
                uint32_t bl[2] = { K32l[nr + ks*8 + t4], K32l[nr + ks*8 + 4 + t4] };
                mma16816(s[nt], qh[ks], bh);
                mma16816(s[nt], qh[ks], bl);
                mma16816(s[nt], ql[ks], bh);
            }
        }
        #pragma unroll
        for (int nt = 0; nt < 8; nt++) {
            const int c = kt*64 + nt*8 + 2*t4;
            if (s_mask[c]   == 0) { s[nt][0] = -1e9f; s[nt][2] = -1e9f; }
            if (s_mask[c+1] == 0) { s[nt][1] = -1e9f; s[nt][3] = -1e9f; }
        }
        float mx0 = -INFINITY, mx1 = -INFINITY;
        #pragma unroll
        for (int nt = 0; nt < 8; nt++) {
            mx0 = fmaxf(mx0, fmaxf(s[nt][0], s[nt][1]));
            mx1 = fmaxf(mx1, fmaxf(s[nt][2], s[nt][3]));
        }
        mx0 = fmaxf(mx0, __shfl_xor_sync(0xffffffffu, mx0, 1));
        mx0 = fmaxf(mx0, __shfl_xor_sync(0xffffffffu, mx0, 2));
        mx1 = fmaxf(mx1, __shfl_xor_sync(0xffffffffu, mx1, 1));
        mx1 = fmaxf(mx1, __shfl_xor_sync(0xffffffffu, mx1, 2));
        float nm0 = fmaxf(m0, mx0), nm1 = fmaxf(m1, mx1);
        float a0 = __expf(m0 - nm0), a1 = __expf(m1 - nm1);
        m0 = nm0; m1 = nm1;
        float ps0 = 0.f, ps1 = 0.f;
        #pragma unroll
        for (int nt = 0; nt < 8; nt++) {
            s[nt][0] = __expf(s[nt][0] - nm0);
            s[nt][1] = __expf(s[nt][1] - nm0);
            s[nt][2] = __expf(s[nt][2] - nm1);
            s[nt][3] = __expf(s[nt][3] - nm1);
            ps0 += s[nt][0] + s[nt][1];
            ps1 += s[nt][2] + s[nt][3];
        }
        ps0 += __shfl_xor_sync(0xffffffffu, ps0, 1);
        ps0 += __shfl_xor_sync(0xffffffffu, ps0, 2);
        ps1 += __shfl_xor_sync(0xffffffffu, ps1, 1);
        ps1 += __shfl_xor_sync(0xffffffffu, ps1, 2);
        l0 = l0 * a0 + ps0;
        l1 = l1 * a1 + ps1;
        #pragma unroll
        for (int nt = 0; nt < 8; nt++) {
            O[nt][0] *= a0; O[nt][1] *= a0;
            O[nt][2] *= a1; O[nt][3] *= a1;
        }
        uint32_t pH[4][4], pL[4][4];
        #pragma unroll
        for (int ks = 0; ks < 4; ks++) {
            #pragma unroll
            for (int half = 0; half < 2; half++) {
                const int nt = 2*ks + half;
                bf16 h0 = __float2bfloat16(s[nt][0]);
                bf16 h1 = __float2bfloat16(s[nt][1]);
                bf16 h2 = __float2bfloat16(s[nt][2]);
                bf16 h3 = __float2bfloat16(s[nt][3]);
                pH[ks][2*half]   = (uint32_t)bfbits(h0) | ((uint32_t)bfbits(h1) << 16);
                pH[ks][2*half+1] = (uint32_t)bfbits(h2) | ((uint32_t)bfbits(h3) << 16);
                bf16 e0 = __float2bfloat16(s[nt][0] - __bfloat162float(h0));
                bf16 e1 = __float2bfloat16(s[nt][1] - __bfloat162float(h1));
                bf16 e2 = __float2bfloat16(s[nt][2] - __bfloat162float(h2));
                bf16 e3 = __float2bfloat16(s[nt][3] - __bfloat162float(h3));
                pL[ks][2*half]   = (uint32_t)bfbits(e0) | ((uint32_t)bfbits(e1) << 16);
                pL[ks][2*half+1] = (uint32_t)bfbits(e2) | ((uint32_t)bfbits(e3) << 16);
            }
        }
        #pragma unroll
        for (int nt = 0; nt < 8; nt++) {
            const int nr = (nt*8 + g) * 36;
            #pragma unroll
            for (int ks = 0; ks < 4; ks++) {
                uint32_t bh[2] = { V32h[nr + ks*8 + t4], V32h[nr + ks*8 + 4 + t4] };
                uint32_t bl[2] = { V32l[nr + ks*8 + t4], V32l[nr + ks*8 + 4 + t4] };
                mma16816(O[nt], pH[ks], bh);
                mma16816(O[nt], pH[ks], bl);
                mma16816(O[nt], pL[ks], bh);
            }
        }
    }

    const float il0 = 1.0f / l0, il1 = 1.0f / l1;
    const size_t row0 = (size_t)(b*SEQ + q0 + wid*16 + g);
    const size_t row8 = row0 + 8;
    #pragma unroll
    for (int nt = 0; nt < 8; nt++) {
        const int col = h*64 + nt*8 + 2*t4;
        bf16 h0, l0b, h1, l1b;
        split(O[nt][0] * il0, &h0, &l0b);
        split(O[nt][1] * il0, &h1, &l1b);
        *(uint32_t*)(g_ctx_h + row0*1024 + col) =
            (uint32_t)bfbits(h0) | ((uint32_t)bfbits(h1) << 16);
        *(uint32_t*)(g_ctx_l + row0*1024 + col) =
            (uint32_t)bfbits(l0b) | ((uint32_t)bfbits(l1b) << 16);
        split(O[nt][2] * il1, &h0, &l0b);
        split(O[nt][3] * il1, &h1, &l1b);
        *(uint32_t*)(g_ctx_h + row8*1024 + col) =
            (uint32_t)bfbits(h0) | ((uint32_t)bfbits(h1) << 16);
        *(uint32_t*)(g_ctx_l + row8*1024 + col) =
            (uint32_t)bfbits(l0b) | ((uint32_t)bfbits(l1b) << 16);
    }
}

// ---------------------------------------------------------------------------
// mma.sync GEMM core, cp.async 2-stage pipeline (NT=128 fixed).
// Dynamic smem: 2 stages x 40960 B; stage = sAh(10240) sAl sBh sBl.
// EPI: 0 pair-out | 1 bias+relu pair-out | 2 pair-out transposed
//      4 fp32+resid | 5 fp32+bias+resid
// ---------------------------------------------------------------------------
#define GEMM_SMEM 81920
#define GSTAGE 40960u
#define GTILE 10240u

template<int EPI>
__device__ __forceinline__ void tcore(
    uint8_t* dynsm,
    const bf16* __restrict__ Ah, const bf16* __restrict__ Al, int lda,
    const bf16* __restrict__ Bh, const bf16* __restrict__ Bl, int ldb,
    int K, int bm, int bn,
    float* __restrict__ Cf, int ldc,
    bf16* __restrict__ Oh, bf16* __restrict__ Ol, int ldo,
    const float* __restrict__ bias, const float* __restrict__ resid)
{
    const int tid = threadIdx.x, wid = tid >> 5, lane = tid & 31;
    const int wm = wid & 3, wn = wid >> 2;
    const int g = lane >> 2, t4 = lane & 3;
    const int ar = tid >> 1, akq = (tid & 1) * 16;

    const uint32_t sbase = smem_u32(dynsm);
    const uint32_t doff = (uint32_t)(ar*40 + akq) * 2u;   // byte offset within tile

    float acc[2][8][4];
    #pragma unroll
    for (int i = 0; i < 2; i++)
        #pragma unroll
        for (int j = 0; j < 8; j++)
            #pragma unroll
            for (int e = 0; e < 4; e++) acc[i][j][e] = 0.f;

    auto load_chunk = [&](int k0, int p) {
        const uint32_t base = sbase + p*GSTAGE + doff;
        const bf16* a_h = Ah + (size_t)(bm + ar) * lda + k0 + akq;
        const bf16* a_l = Al + (size_t)(bm + ar) * lda + k0 + akq;
        cpa16(base + 0*GTILE,      a_h);
        cpa16(base + 0*GTILE + 16, a_h + 8);
        cpa16(base + 1*GTILE,      a_l);
        cpa16(base + 1*GTILE + 16, a_l + 8);
        const bf16* b_h = Bh + (size_t)(bn + ar) * ldb + k0 + akq;
        const bf16* b_l = Bl + (size_t)(bn + ar) * ldb + k0 + akq;
        cpa16(base + 2*GTILE,      b_h);
        cpa16(base + 2*GTILE + 16, b_h + 8);
        cpa16(base + 3*GTILE,      b_l);
        cpa16(base + 3*GTILE + 16, b_l + 8);
        CP_COMMIT();
    };

    const int nch = K >> 5;
    load_chunk(0, 0);
    for (int c = 0; c < nch; c++) {
        if (c + 1 < nch) {
            load_chunk((c + 1) << 5, (c + 1) & 1);
            CP_WAIT(1);
        } else {
            CP_WAIT(0);
        }
        __syncthreads();

        const uint8_t* st = dynsm + (c & 1) * GSTAGE;
        const uint32_t* A32h = (const uint32_t*)(st);
        const uint32_t* A32l = (const uint32_t*)(st + GTILE);
        const uint32_t* B32h = (const uint32_t*)(st + 2*GTILE);
        const uint32_t* B32l = (const uint32_t*)(st + 3*GTILE);

        #pragma unroll
        for (int kh = 0; kh < 2; kh++) {
            const int ko = kh * 8;
            uint32_t aH[2][4], aL[2][4];
            #pragma unroll
            for (int mt = 0; mt < 2; mt++) {
                const int r = wm*32 + mt*16 + g;
                aH[mt][0] = A32h[r*20 + ko + t4];
                aH[mt][1] = A32h[(r+8)*20 + ko + t4];
                aH[mt][2] = A32h[r*20 + ko + 4 + t4];
                aH[mt][3] = A32h[(r+8)*20 + ko + 4 + t4];
                aL[mt][0] = A32l[r*20 + ko + t4];
                aL[mt][1] = A32l[(r+8)*20 + ko + t4];
                aL[mt][2] = A32l[r*20 + ko + 4 + t4];
                aL[mt][3] = A32l[(r+8)*20 + ko + 4 + t4];
            }
            #pragma unroll
            for (int nt = 0; nt < 8; nt++) {
                const int nr = wn*64 + nt*8 + g;
                uint32_t bH[2], bL[2];
                bH[0] = B32h[nr*20 + ko + t4];
                bH[1] = B32h[nr*20 + ko + 4 + t4];
                bL[0] = B32l[nr*20 + ko + t4];
                bL[1] = B32l[nr*20 + ko + 4 + t4];
                #pragma unroll
                for (int mt = 0; mt < 2; mt++) {
                    mma16816(acc[mt][nt], aH[mt], bH);
                    mma16816(acc[mt][nt], aH[mt], bL);
                    mma16816(acc[mt][nt], aL[mt], bH);
                }
            }
        }
        __syncthreads();
    }

    auto wr = [&](int row, int col, float v0, float v1) {
        if (EPI == 0 || EPI == 1) {
            if (EPI == 1) {
                v0 = fmaxf(v0 + bias[col], 0.f);
                v1 = fmaxf(v1 + bias[col + 1], 0.f);
            }
            bf16 h0, l0, h1, l1;
            split(v0, &h0, &l0); split(v1, &h1, &l1);
            *(uint32_t*)(Oh + (size_t)row * ldo + col) =
                (uint32_t)bfbits(h0) | ((uint32_t)bfbits(h1) << 16);
            *(uint32_t*)(Ol + (size_t)row * ldo + col) =
                (uint32_t)bfbits(l0) | ((uint32_t)bfbits(l1) << 16);
        } else if (EPI == 2) {
            bf16 h0, l0, h1, l1;
            split(v0, &h0, &l0); split(v1, &h1, &l1);
            Oh[(size_t)col * ldo + row] = h0;
            Ol[(size_t)col * ldo + row] = l0;
            Oh[(size_t)(col + 1) * ldo + row] = h1;
            Ol[(size_t)(col + 1) * ldo + row] = l1;
        } else {
            const float* rr = resid + (size_t)row * ldc + col;
            float2 o;
            o.x = v0 + rr[0]; o.y = v1 + rr[1];
            if (EPI == 5) { o.x += bias[col]; o.y += bias[col + 1]; }
            *(float2*)(Cf + (size_t)row * ldc + col) = o;
        }
    };
    #pragma unroll
    for (int mt = 0; mt < 2; mt++) {
        #pragma unroll
        for (int nt = 0; nt < 8; nt++) {
            const int row = bm + wm*32 + mt*16 + g;
            const int col = bn + wn*64 + nt*8 + 2*t4;
            wr(row,     col, acc[mt][nt][0], acc[mt][nt][1]);
            wr(row + 8, col, acc[mt][nt][2], acc[mt][nt][3]);
        }
    }
}

// ---------------- wrappers ----------------
__global__ void __launch_bounds__(256, 2) kt_qkv() {
    extern __shared__ __align__(16) uint8_t dynsm[];
    const int bm = blockIdx.y * 128, bn = blockIdx.x * 128;
    if (blockIdx.z == 0)
        tcore<0>(dynsm, g_xn_h, g_xn_l, 1024, g_wqt_h, g_wqt_l, 1024, 1024,
                 bm, bn, nullptr, 0, g_q_h, g_q_l, 1024, nullptr, nullptr);
    else if (blockIdx.z == 1)
        tcore<0>(dynsm, g_xn_h, g_xn_l, 1024, g_wkt_h, g_wkt_l, 1024, 1024,
                 bm, bn, nullptr, 0, g_k_h, g_k_l, 1024, nullptr, nullptr);
    else
        tcore<2>(dynsm, g_xn_h, g_xn_l, 1024, g_wvt_h, g_wvt_l, 1024, 1024,
                 bm, bn, nullptr, 0, g_vt_h, g_vt_l, 4096, nullptr, nullptr);
}
__global__ void __launch_bounds__(256, 2) kt_wo(const float* __restrict__ x) {
    extern __shared__ __align__(16) uint8_t dynsm[];
    tcore<4>(dynsm, g_ctx_h, g_ctx_l, 1024, g_wot_h, g_wot_l, 1024, 1024,
             blockIdx.y*128, blockIdx.x*128,
             g_x1, 1024, nullptr, nullptr, 0, nullptr, x);
}
__global__ void __launch_bounds__(256, 2) kt_ffn1(const float* __restrict__ b1) {
    extern __shared__ __align__(16) uint8_t dynsm[];
    tcore<1>(dynsm, g_xn_h, g_xn_l, 1024, g_w1t_h, g_w1t_l, 1024, 1024,
             blockIdx.y*128, blockIdx.x*128,
             nullptr, 0, g_ffh_h, g_ffh_l, 4096, b1, nullptr);
}
__global__ void __launch_bounds__(256, 2) kt_ffn2(const float* __restrict__ b2,
                                                  float* __restrict__ out) {
    extern __shared__ __align__(16) uint8_t dynsm[];
    tcore<5>(dynsm, g_ffh_h, g_ffh_l, 4096, g_w2t_h, g_w2t_l, 4096, 4096,
             blockIdx.y*128, blockIdx.x*128,
             out, 1024, nullptr, nullptr, 0, b2, g_x1);
}

// ---------------- launch ----------------
extern "C" void kernel_launch(void* const* d_in, const int* in_sizes, int n_in,
                              void* d_out, int out_size)
{
    const float* x      = (const float*)d_in[0];
    const int*   mask   = (const int*)  d_in[1];
    const float* wq     = (const float*)d_in[2];
    const float* wk     = (const float*)d_in[3];
    const float* wv     = (const float*)d_in[4];
    const float* wo     = (const float*)d_in[5];
    const float* w1     = (const float*)d_in[6];
    const float* b1     = (const float*)d_in[7];
    const float* w2     = (const float*)d_in[8];
    const float* b2     = (const float*)d_in[9];
    const float* alpha1 = (const float*)d_in[10];
    const float* bias1  = (const float*)d_in[11];
    const float* alpha2 = (const float*)d_in[12];
    const float* bias2  = (const float*)d_in[13];
    float* out = (float*)d_out;

    static int attr_set = 0;
    if (!attr_set) {
        cudaFuncSetAttribute(kt_attn, cudaFuncAttributeMaxDynamicSharedMemorySize, ATTN_SMEM);
        cudaFuncSetAttribute(kt_qkv,  cudaFuncAttributeMaxDynamicSharedMemorySize, GEMM_SMEM);
        cudaFuncSetAttribute(kt_wo,   cudaFuncAttributeMaxDynamicSharedMemorySize, GEMM_SMEM);
        cudaFuncSetAttribute(kt_ffn1, cudaFuncAttributeMaxDynamicSharedMemorySize, GEMM_SMEM);
        cudaFuncSetAttribute(kt_ffn2, cudaFuncAttributeMaxDynamicSharedMemorySize, GEMM_SMEM);
        attr_set = 1;
    }

    k_prep_all<<<12288, 256>>>(wq, wk, wv, wo, w1, w2);

    // sublayer 1
    k_ln<<<NTOK, 256>>>(x, 0, alpha1, bias1);
    kt_qkv<<<dim3(8, 32, 3), 256, GEMM_SMEM>>>();
    kt_attn<<<dim3(16, 32), 256, ATTN_SMEM>>>(mask);
    kt_wo<<<dim3(8, 32), 256, GEMM_SMEM>>>(x);

    // sublayer 2
    k_ln<<<NTOK, 256>>>(x, 1, alpha2, bias2);
    kt_ffn1<<<dim3(32, 32), 256, GEMM_SMEM>>>(b1);
    kt_ffn2<<<dim3(8, 32), 256, GEMM_SMEM>>>(b2, out);
}

// round 13
// speedup vs baseline: 1.4046x; 1.2017x over previous
#include <cuda_runtime.h>
#include <cuda_bf16.h>
#include <cuda_fp16.h>
#include <math.h>
#include <stdint.h>

#define DMODEL 1024
#define DFF 4096
#define SEQ 2048
#define NTOK 4096
#define LN_EPS 1e-5f
typedef __nv_bfloat16 bf16;
typedef __half fp16;

// ---------------- device-global scratch ----------------
// wq/wk/wv: bf16 hi/lo (3-MMA path).  wo/w1/w2: fp16 hi only (2-MMA path).
__device__ bf16 g_wqt_h[1u<<20], g_wqt_l[1u<<20];   // [N,K] K-major (wq pre-scaled 0.125)
__device__ bf16 g_wkt_h[1u<<20], g_wkt_l[1u<<20];
__device__ bf16 g_wvt_h[1u<<20], g_wvt_l[1u<<20];
__device__ fp16 g_wot_h[1u<<20];
__device__ fp16 g_w1t_h[1u<<22];                    // [4096,1024]
__device__ fp16 g_w2t_h[1u<<22];                    // [1024,4096]
__device__ bf16 g_xn_h [1u<<22], g_xn_l [1u<<22];   // LN1: bf16 pairs (QKV)
__device__ fp16 g_xn2_h[1u<<22], g_xn2_l[1u<<22];   // LN2: fp16 pairs (FFN1)
__device__ bf16 g_q_h  [1u<<22], g_q_l  [1u<<22];
__device__ bf16 g_k_h  [1u<<22], g_k_l  [1u<<22];
__device__ bf16 g_vt_h [1u<<22], g_vt_l [1u<<22];   // [1024 dk, 4096 tok]
__device__ fp16 g_ctx_h[1u<<22], g_ctx_l[1u<<22];   // fp16 pairs (Wo input)
__device__ fp16 g_ffh_h[1u<<24], g_ffh_l[1u<<24];   // fp16 pairs [4096,4096]
__device__ float g_x1[1u<<22];

// ---------------- helpers ----------------
__device__ __forceinline__ void mma_bf(float* d, const uint32_t* a, const uint32_t* b) {
    asm volatile(
        "mma.sync.aligned.m16n8k16.row.col.f32.bf16.bf16.f32 "
        "{%0,%1,%2,%3}, {%4,%5,%6,%7}, {%8,%9}, {%0,%1,%2,%3};"
        : "+f"(d[0]), "+f"(d[1]), "+f"(d[2]), "+f"(d[3])
        : "r"(a[0]), "r"(a[1]), "r"(a[2]), "r"(a[3]), "r"(b[0]), "r"(b[1]));
}
__device__ __forceinline__ void mma_hf(float* d, const uint32_t* a, const uint32_t* b) {
    asm volatile(
        "mma.sync.aligned.m16n8k16.row.col.f32.f16.f16.f32 "
        "{%0,%1,%2,%3}, {%4,%5,%6,%7}, {%8,%9}, {%0,%1,%2,%3};"
        : "+f"(d[0]), "+f"(d[1]), "+f"(d[2]), "+f"(d[3])
        : "r"(a[0]), "r"(a[1]), "r"(a[2]), "r"(a[3]), "r"(b[0]), "r"(b[1]));
}
__device__ __forceinline__ uint16_t bfbits(bf16 v) { return __bfloat16_as_ushort(v); }
__device__ __forceinline__ uint16_t hfbits(fp16 v) { return __half_as_ushort(v); }
__device__ __forceinline__ void split(float f, bf16* h, bf16* l) {
    bf16 hh = __float2bfloat16(f);
    *h = hh; *l = __float2bfloat16(f - __bfloat162float(hh));
}
__device__ __forceinline__ void splith(float f, fp16* h, fp16* l) {
    fp16 hh = __float2half_rn(f);
    *h = hh; *l = __float2half_rn(f - __half2float(hh));
}
__device__ __forceinline__ void cpa16(uint32_t dst, const void* src) {
    asm volatile("cp.async.cg.shared.global [%0], [%1], 16;" :: "r"(dst), "l"(src) : "memory");
}
#define CP_COMMIT() asm volatile("cp.async.commit_group;" ::: "memory")
#define CP_WAIT(n)  asm volatile("cp.async.wait_group %0;" :: "n"(n) : "memory")
__device__ __forceinline__ uint32_t smem_u32(const void* p) {
    uint32_t a;
    asm("{ .reg .u64 t; cvta.to.shared.u64 t, %1; cvt.u32.u64 %0, t; }" : "=r"(a) : "l"(p));
    return a;
}
__device__ __forceinline__ float warpSum(float v) {
    #pragma unroll
    for (int o = 16; o > 0; o >>= 1) v += __shfl_down_sync(0xffffffffu, v, o);
    return v;
}
__device__ __forceinline__ float blockSum(float v) {
    __shared__ float sh[8];
    int l = threadIdx.x & 31, w = threadIdx.x >> 5;
    v = warpSum(v);
    if (l == 0) sh[w] = v;
    __syncthreads();
    if (w == 0) { float t = (l < 8) ? sh[l] : 0.f; t = warpSum(t); if (l == 0) sh[0] = t; }
    __syncthreads();
    float r = sh[0]; __syncthreads();
    return r;
}

// ---------------- weight prep: ONE launch ----------------
__global__ void __launch_bounds__(256) k_prep_all(
    const float* __restrict__ wq, const float* __restrict__ wk,
    const float* __restrict__ wv, const float* __restrict__ wo,
    const float* __restrict__ w1, const float* __restrict__ w2)
{
    int t = blockIdx.x;
    const float* w;
    bf16 *th = nullptr, *tl = nullptr;
    fp16 *fh = nullptr;
    int K, N, local;
    float scale = 1.0f;
    if (t < 4096) {
        int seg = t >> 10; local = t & 1023;
        K = 1024; N = 1024;
        switch (seg) {
            case 0: w = wq; th = g_wqt_h; tl = g_wqt_l; scale = 0.125f; break;
            case 1: w = wk; th = g_wkt_h; tl = g_wkt_l; break;
            case 2: w = wv; th = g_wvt_h; tl = g_wvt_l; break;
            default: w = wo; fh = g_wot_h; break;
        }
    } else if (t < 8192) {
        local = t - 4096; w = w1; fh = g_w1t_h; K = 1024; N = 4096;
    } else {
        local = t - 8192; w = w2; fh = g_w2t_h; K = 4096; N = 1024;
    }
    const int xt = N >> 5;
    const int n0 = (local % xt) * 32, k0 = (local / xt) * 32;

    __shared__ float ts[32][33];
    int tx = threadIdx.x & 31, ty = threadIdx.x >> 5;
    #pragma unroll
    for (int i = 0; i < 4; i++)
        ts[ty + 8*i][tx] = w[(size_t)(k0 + ty + 8*i) * N + n0 + tx];
    __syncthreads();
    #pragma unroll
    for (int i = 0; i < 4; i++) {
        int n = n0 + ty + 8*i, k = k0 + tx;
        float v = ts[tx][ty + 8*i] * scale;
        if (fh) fh[(size_t)n * K + k] = __float2half_rn(v);
        else    split(v, &th[(size_t)n * K + k], &tl[(size_t)n * K + k]);
    }
}

// ---------------- LayerNorm: fmt 0 -> bf16 pairs (g_xn), 1 -> fp16 pairs (g_xn2) ----------------
__global__ void __launch_bounds__(256) k_ln(const float* __restrict__ xin, int fmt,
                                            const float* __restrict__ ap,
                                            const float* __restrict__ bp)
{
    const float* src = fmt ? g_x1 : xin;
    int row = blockIdx.x, t = threadIdx.x;
    const float* xr = src + (size_t)row * DMODEL;
    float v[4], s = 0.f, sq = 0.f;
    #pragma unroll
    for (int i = 0; i < 4; i++) { v[i] = xr[t + 256*i]; s += v[i]; sq += v[i]*v[i]; }
    s = blockSum(s); sq = blockSum(sq);
    float mean = s * (1.0f / DMODEL);
    float var = fmaxf((sq - (float)DMODEL * mean * mean) * (1.0f / (DMODEL - 1)), 0.f);
    float sc = ap[0] / (sqrtf(var) + LN_EPS);
    float bi = bp[0];
    #pragma unroll
    for (int i = 0; i < 4; i++) {
        size_t o = (size_t)row * DMODEL + t + 256*i;
        float y = (v[i] - mean) * sc + bi;
        if (fmt) splith(y, &g_xn2_h[o], &g_xn2_l[o]);
        else     split(y,  &g_xn_h[o],  &g_xn_l[o]);
    }
}

// ---------------------------------------------------------------------------
// Fused flash attention, cp.async double-buffered K/V (bf16 3-MMA, as R11/R12).
// Epilogue now emits fp16 hi/lo ctx pairs for the fp16 Wo GEMM.
// ---------------------------------------------------------------------------
#define ATTN_SMEM 81920
#define BUFB 36864u
#define TILEB 9216u

__global__ void __launch_bounds__(256, 2) kt_attn(const int* __restrict__ mask)
{
    extern __shared__ __align__(16) uint8_t dynsm[];
    const int z = blockIdx.y, b = z >> 4, h = z & 15;
    const int q0 = blockIdx.x * 128;
    const int tid = threadIdx.x, wid = tid >> 5, lane = tid & 31;
    const int g = lane >> 2, t4 = lane & 3;

    uint32_t sbase = smem_u32(dynsm);
    int* s_mask = (int*)(dynsm + 2*BUFB);

    for (int i = tid; i < SEQ/4; i += 256)
        *(int4*)&s_mask[i*4] = *(const int4*)&mask[b*SEQ + i*4];

    uint32_t qh[4][4], ql[4][4];
    {
        const uint32_t* Q32h = (const uint32_t*)g_q_h;
        const uint32_t* Q32l = (const uint32_t*)g_q_l;
        size_t r0 = ((size_t)(b*SEQ + q0 + wid*16 + g)) * 512 + h*32;
        size_t r8 = r0 + 8*512;
        #pragma unroll
        for (int s = 0; s < 4; s++) {
            qh[s][0] = Q32h[r0 + s*8 + t4];
            qh[s][1] = Q32h[r8 + s*8 + t4];
            qh[s][2] = Q32h[r0 + s*8 + 4 + t4];
            qh[s][3] = Q32h[r8 + s*8 + 4 + t4];
            ql[s][0] = Q32l[r0 + s*8 + t4];
            ql[s][1] = Q32l[r8 + s*8 + t4];
            ql[s][2] = Q32l[r0 + s*8 + 4 + t4];
            ql[s][3] = Q32l[r8 + s*8 + 4 + t4];
        }
    }

    float O[8][4];
    #pragma unroll
    for (int i = 0; i < 8; i++)
        #pragma unroll
        for (int j = 0; j < 4; j++) O[i][j] = 0.f;
    float m0 = -INFINITY, m1 = -INFINITY, l0 = 0.f, l1 = 0.f;

    const int krow = tid >> 2, kcb = (tid & 3) * 16;
    const uint32_t soff = (uint32_t)(krow*72 + kcb) * 2u;

    auto load_tile = [&](int kt, int p) {
        const uint32_t base = sbase + p*BUFB;
        size_t gk = ((size_t)(b*SEQ + kt*64 + krow)) * 1024 + h*64 + kcb;
        cpa16(base + 0*TILEB + soff,      &g_k_h[gk]);
        cpa16(base + 0*TILEB + soff + 16, &g_k_h[gk + 8]);
        cpa16(base + 1*TILEB + soff,      &g_k_l[gk]);
        cpa16(base + 1*TILEB + soff + 16, &g_k_l[gk + 8]);
        size_t gv = ((size_t)(h*64 + krow)) * 4096 + b*SEQ + kt*64 + kcb;
        cpa16(base + 2*TILEB + soff,      &g_vt_h[gv]);
        cpa16(base + 2*TILEB + soff + 16, &g_vt_h[gv + 8]);
        cpa16(base + 3*TILEB + soff,      &g_vt_l[gv]);
        cpa16(base + 3*TILEB + soff + 16, &g_vt_l[gv + 8]);
        CP_COMMIT();
    };

    load_tile(0, 0);
    for (int kt = 0; kt < SEQ/64; kt++) {
        __syncthreads();
        if (kt + 1 < SEQ/64) {
            load_tile(kt + 1, (kt + 1) & 1);
            CP_WAIT(1);
        } else {
            CP_WAIT(0);
        }
        __syncthreads();

        const uint8_t* buf = dynsm + (kt & 1) * BUFB;
        const uint32_t* K32h = (const uint32_t*)(buf);
        const uint32_t* K32l = (const uint32_t*)(buf + TILEB);
        const uint32_t* V32h = (const uint32_t*)(buf + 2*TILEB);
        const uint32_t* V32l = (const uint32_t*)(buf + 3*TILEB);

        float s[8][4];
        #pragma unroll
        for (int nt = 0; nt < 8; nt++) {
            s[nt][0] = s[nt][1] = s[nt][2] = s[nt][3] = 0.f;
            const int nr = (nt*8 + g) * 36;
            #pragma unroll
            for (int ks = 0; ks < 4; ks++) {
                uint32_t bh[2] = { K32h[nr + ks*8 + t4], K32h[nr + ks*8 + 4 + t4] };
                uint32_t bl[2] = { K32l[nr + ks*8 + t4], K32l[nr + ks*8 + 4 + t4] };
                mma_bf(s[nt], qh[ks], bh);
                mma_bf(s[nt], qh[ks], bl);
                mma_bf(s[nt], ql[ks], bh);
            }
        }
        #pragma unroll
        for (int nt = 0; nt < 8; nt++) {
            const int c = kt*64 + nt*8 + 2*t4;
            if (s_mask[c]   == 0) { s[nt][0] = -1e9f; s[nt][2] = -1e9f; }
            if (s_mask[c+1] == 0) { s[nt][1] = -1e9f; s[nt][3] = -1e9f; }
        }
        float mx0 = -INFINITY, mx1 = -INFINITY;
        #pragma unroll
        for (int nt = 0; nt < 8; nt++) {
            mx0 = fmaxf(mx0, fmaxf(s[nt][0], s[nt][1]));
            mx1 = fmaxf(mx1, fmaxf(s[nt][2], s[nt][3]));
        }
        mx0 = fmaxf(mx0, __shfl_xor_sync(0xffffffffu, mx0, 1));
        mx0 = fmaxf(mx0, __shfl_xor_sync(0xffffffffu, mx0, 2));
        mx1 = fmaxf(mx1, __shfl_xor_sync(0xffffffffu, mx1, 1));
        mx1 = fmaxf(mx1, __shfl_xor_sync(0xffffffffu, mx1, 2));
        float nm0 = fmaxf(m0, mx0), nm1 = fmaxf(m1, mx1);
        float a0 = __expf(m0 - nm0), a1 = __expf(m1 - nm1);
        m0 = nm0; m1 = nm1;
        float ps0 = 0.f, ps1 = 0.f;
        #pragma unroll
        for (int nt = 0; nt < 8; nt++) {
            s[nt][0] = __expf(s[nt][0] - nm0);
            s[nt][1] = __expf(s[nt][1] - nm0);
            s[nt][2] = __expf(s[nt][2] - nm1);
            s[nt][3] = __expf(s[nt][3] - nm1);
            ps0 += s[nt][0] + s[nt][1];
            ps1 += s[nt][2] + s[nt][3];
        }
        ps0 += __shfl_xor_sync(0xffffffffu, ps0, 1);
        ps0 += __shfl_xor_sync(0xffffffffu, ps0, 2);
        ps1 += __shfl_xor_sync(0xffffffffu, ps1, 1);
        ps1 += __shfl_xor_sync(0xffffffffu, ps1, 2);
        l0 = l0 * a0 + ps0;
        l1 = l1 * a1 + ps1;
        #pragma unroll
        for (int nt = 0; nt < 8; nt++) {
            O[nt][0] *= a0; O[nt][1] *= a0;
            O[nt][2] *= a1; O[nt][3] *= a1;
        }
        uint32_t pH[4][4], pL[4][4];
        #pragma unroll
        for (int ks = 0; ks < 4; ks++) {
            #pragma unroll
            for (int half = 0; half < 2; half++) {
                const int nt = 2*ks + half;
                bf16 h0 = __float2bfloat16(s[nt][0]);
                bf16 h1 = __float2bfloat16(s[nt][1]);
                bf16 h2 = __float2bfloat16(s[nt][2]);
                bf16 h3 = __float2bfloat16(s[nt][3]);
                pH[ks][2*half]   = (uint32_t)bfbits(h0) | ((uint32_t)bfbits(h1) << 16);
                pH[ks][2*half+1] = (uint32_t)bfbits(h2) | ((uint32_t)bfbits(h3) << 16);
                bf16 e0 = __float2bfloat16(s[nt][0] - __bfloat162float(h0));
                bf16 e1 = __float2bfloat16(s[nt][1] - __bfloat162float(h1));
                bf16 e2 = __float2bfloat16(s[nt][2] - __bfloat162float(h2));
                bf16 e3 = __float2bfloat16(s[nt][3] - __bfloat162float(h3));
                pL[ks][2*half]   = (uint32_t)bfbits(e0) | ((uint32_t)bfbits(e1) << 16);
                pL[ks][2*half+1] = (uint32_t)bfbits(e2) | ((uint32_t)bfbits(e3) << 16);
            }
        }
        #pragma unroll
        for (int nt = 0; nt < 8; nt++) {
            const int nr = (nt*8 + g) * 36;
            #pragma unroll
            for (int ks = 0; ks < 4; ks++) {
                uint32_t bh[2] = { V32h[nr + ks*8 + t4], V32h[nr + ks*8 + 4 + t4] };
                uint32_t bl[2] = { V32l[nr + ks*8 + t4], V32l[nr + ks*8 + 4 + t4] };
                mma_bf(O[nt], pH[ks], bh);
                mma_bf(O[nt], pH[ks], bl);
                mma_bf(O[nt], pL[ks], bh);
            }
        }
    }

    // ---- epilogue: ctx = O / l, fp16 hi/lo pairs ----
    const float il0 = 1.0f / l0, il1 = 1.0f / l1;
    const size_t row0 = (size_t)(b*SEQ + q0 + wid*16 + g);
    const size_t row8 = row0 + 8;
    #pragma unroll
    for (int nt = 0; nt < 8; nt++) {
        const int col = h*64 + nt*8 + 2*t4;
        fp16 h0, l0b, h1, l1b;
        splith(O[nt][0] * il0, &h0, &l0b);
        splith(O[nt][1] * il0, &h1, &l1b);
        *(uint32_t*)(g_ctx_h + row0*1024 + col) =
            (uint32_t)hfbits(h0) | ((uint32_t)hfbits(h1) << 16);
        *(uint32_t*)(g_ctx_l + row0*1024 + col) =
            (uint32_t)hfbits(l0b) | ((uint32_t)hfbits(l1b) << 16);
        splith(O[nt][2] * il1, &h0, &l0b);
        splith(O[nt][3] * il1, &h1, &l1b);
        *(uint32_t*)(g_ctx_h + row8*1024 + col) =
            (uint32_t)hfbits(h0) | ((uint32_t)hfbits(h1) << 16);
        *(uint32_t*)(g_ctx_l + row8*1024 + col) =
            (uint32_t)hfbits(l0b) | ((uint32_t)hfbits(l1b) << 16);
    }
}

// ---------------------------------------------------------------------------
// bf16 3-MMA GEMM core, cp.async 2-stage (identical to R12) — used for QKV.
// ---------------------------------------------------------------------------
#define GEMM_SMEM 81920
#define GSTAGE 40960u
#define GTILE 10240u

template<int EPI>   // 0 pair-out bf16 | 2 pair-out bf16 transposed
__device__ __forceinline__ void tcore(
    uint8_t* dynsm,
    const bf16* __restrict__ Ah, const bf16* __restrict__ Al, int lda,
    const bf16* __restrict__ Bh, const bf16* __restrict__ Bl, int ldb,
    int K, int bm, int bn,
    bf16* __restrict__ Oh, bf16* __restrict__ Ol, int ldo)
{
    const int tid = threadIdx.x, wid = tid >> 5, lane = tid & 31;
    const int wm = wid & 3, wn = wid >> 2;
    const int g = lane >> 2, t4 = lane & 3;
    const int ar = tid >> 1, akq = (tid & 1) * 16;

    const uint32_t sbase = smem_u32(dynsm);
    const uint32_t doff = (uint32_t)(ar*40 + akq) * 2u;

    float acc[2][8][4];
    #pragma unroll
    for (int i = 0; i < 2; i++)
        #pragma unroll
        for (int j = 0; j < 8; j++)
            #pragma unroll
            for (int e = 0; e < 4; e++) acc[i][j][e] = 0.f;

    auto load_chunk = [&](int k0, int p) {
        const uint32_t base = sbase + p*GSTAGE + doff;
        const bf16* a_h = Ah + (size_t)(bm + ar) * lda + k0 + akq;
        const bf16* a_l = Al + (size_t)(bm + ar) * lda + k0 + akq;
        cpa16(base + 0*GTILE,      a_h);
        cpa16(base + 0*GTILE + 16, a_h + 8);
        cpa16(base + 1*GTILE,      a_l);
        cpa16(base + 1*GTILE + 16, a_l + 8);
        const bf16* b_h = Bh + (size_t)(bn + ar) * ldb + k0 + akq;
        const bf16* b_l = Bl + (size_t)(bn + ar) * ldb + k0 + akq;
        cpa16(base + 2*GTILE,      b_h);
        cpa16(base + 2*GTILE + 16, b_h + 8);
        cpa16(base + 3*GTILE,      b_l);
        cpa16(base + 3*GTILE + 16, b_l + 8);
        CP_COMMIT();
    };

    const int nch = K >> 5;
    load_chunk(0, 0);
    for (int c = 0; c < nch; c++) {
        if (c + 1 < nch) { load_chunk((c + 1) << 5, (c + 1) & 1); CP_WAIT(1); }
        else             { CP_WAIT(0); }
        __syncthreads();

        const uint8_t* st = dynsm + (c & 1) * GSTAGE;
        const uint32_t* A32h = (const uint32_t*)(st);
        const uint32_t* A32l = (const uint32_t*)(st + GTILE);
        const uint32_t* B32h = (const uint32_t*)(st + 2*GTILE);
        const uint32_t* B32l = (const uint32_t*)(st + 3*GTILE);

        #pragma unroll
        for (int kh = 0; kh < 2; kh++) {
            const int ko = kh * 8;
            uint32_t aH[2][4], aL[2][4];
            #pragma unroll
            for (int mt = 0; mt < 2; mt++) {
                const int r = wm*32 + mt*16 + g;
                aH[mt][0] = A32h[r*20 + ko + t4];
                aH[mt][1] = A32h[(r+8)*20 + ko + t4];
                aH[mt][2] = A32h[r*20 + ko + 4 + t4];
                aH[mt][3] = A32h[(r+8)*20 + ko + 4 + t4];
                aL[mt][0] = A32l[r*20 + ko + t4];
                aL[mt][1] = A32l[(r+8)*20 + ko + t4];
                aL[mt][2] = A32l[r*20 + ko + 4 + t4];
                aL[mt][3] = A32l[(r+8)*20 + ko + 4 + t4];
            }
            #pragma unroll
            for (int nt = 0; nt < 8; nt++) {
                const int nr = wn*64 + nt*8 + g;
                uint32_t bH[2], bL[2];
                bH[0] = B32h[nr*20 + ko + t4];
                bH[1] = B32h[nr*20 + ko + 4 + t4];
                bL[0] = B32l[nr*20 + ko + t4];
                bL[1] = B32l[nr*20 + ko + 4 + t4];
                #pragma unroll
                for (int mt = 0; mt < 2; mt++) {
                    mma_bf(acc[mt][nt], aH[mt], bH);
                    mma_bf(acc[mt][nt], aH[mt], bL);
                    mma_bf(acc[mt][nt], aL[mt], bH);
                }
            }
        }
        __syncthreads();
    }

    auto wr = [&](int row, int col, float v0, float v1) {
        if (EPI == 0) {
            bf16 h0, l0, h1, l1;
            split(v0, &h0, &l0); split(v1, &h1, &l1);
            *(uint32_t*)(Oh + (size_t)row * ldo + col) =
                (uint32_t)bfbits(h0) | ((uint32_t)bfbits(h1) << 16);
            *(uint32_t*)(Ol + (size_t)row * ldo + col) =
                (uint32_t)bfbits(l0) | ((uint32_t)bfbits(l1) << 16);
        } else {
            bf16 h0, l0, h1, l1;
            split(v0, &h0, &l0); split(v1, &h1, &l1);
            Oh[(size_t)col * ldo + row] = h0;
            Ol[(size_t)col * ldo + row] = l0;
            Oh[(size_t)(col + 1) * ldo + row] = h1;
            Ol[(size_t)(col + 1) * ldo + row] = l1;
        }
    };
    #pragma unroll
    for (int mt = 0; mt < 2; mt++) {
        #pragma unroll
        for (int nt = 0; nt < 8; nt++) {
            const int row = bm + wm*32 + mt*16 + g;
            const int col = bn + wn*64 + nt*8 + 2*t4;
            wr(row,     col, acc[mt][nt][0], acc[mt][nt][1]);
            wr(row + 8, col, acc[mt][nt][2], acc[mt][nt][3]);
        }
    }
}

// ---------------------------------------------------------------------------
// fp16 2-MMA GEMM core: A·B ≈ (Ah+Al)·Bh. Stage = Ah, Al, Bh (3 tiles, 30 KB).
// EPI: 4 fp32+resid | 5 fp32+bias+resid | 11 bias+relu fp16 pair-out
// ---------------------------------------------------------------------------
#define GEMM2_SMEM 61440
#define G2STAGE 30720u

template<int EPI>
__device__ __forceinline__ void fcore(
    uint8_t* dynsm,
    const fp16* __restrict__ Ah, const fp16* __restrict__ Al, int lda,
    const fp16* __restrict__ Bh, int ldb,
    int K, int bm, int bn,
    float* __restrict__ Cf, int ldc,
    fp16* __restrict__ Oh, fp16* __restrict__ Ol, int ldo,
    const float* __restrict__ bias, const float* __restrict__ resid)
{
    const int tid = threadIdx.x, wid = tid >> 5, lane = tid & 31;
    const int wm = wid & 3, wn = wid >> 2;
    const int g = lane >> 2, t4 = lane & 3;
    const int ar = tid >> 1, akq = (tid & 1) * 16;

    const uint32_t sbase = smem_u32(dynsm);
    const uint32_t doff = (uint32_t)(ar*40 + akq) * 2u;

    float acc[2][8][4];
    #pragma unroll
    for (int i = 0; i < 2; i++)
        #pragma unroll
        for (int j = 0; j < 8; j++)
            #pragma unroll
            for (int e = 0; e < 4; e++) acc[i][j][e] = 0.f;

    auto load_chunk = [&](int k0, int p) {
        const uint32_t base = sbase + p*G2STAGE + doff;
        const fp16* a_h = Ah + (size_t)(bm + ar) * lda + k0 + akq;
        const fp16* a_l = Al + (size_t)(bm + ar) * lda + k0 + akq;
        cpa16(base + 0*GTILE,      a_h);
        cpa16(base + 0*GTILE + 16, a_h + 8);
        cpa16(base + 1*GTILE,      a_l);
        cpa16(base + 1*GTILE + 16, a_l + 8);
        const fp16* b_h = Bh + (size_t)(bn + ar) * ldb + k0 + akq;
        cpa16(base + 2*GTILE,      b_h);
        cpa16(base + 2*GTILE + 16, b_h + 8);
        CP_COMMIT();
    };

    const int nch = K >> 5;
    load_chunk(0, 0);
    for (int c = 0; c < nch; c++) {
        if (c + 1 < nch) { load_chunk((c + 1) << 5, (c + 1) & 1); CP_WAIT(1); }
        else             { CP_WAIT(0); }
        __syncthreads();

        const uint8_t* st = dynsm + (c & 1) * G2STAGE;
        const uint32_t* A32h = (const uint32_t*)(st);
        const uint32_t* A32l = (const uint32_t*)(st + GTILE);
        const uint32_t* B32h = (const uint32_t*)(st + 2*GTILE);

        #pragma unroll
        for (int kh = 0; kh < 2; kh++) {
            const int ko = kh * 8;
            uint32_t aH[2][4], aL[2][4];
            #pragma unroll
            for (int mt = 0; mt < 2; mt++) {
                const int r = wm*32 + mt*16 + g;
                aH[mt][0] = A32h[r*20 + ko + t4];
                aH[mt][1] = A32h[(r+8)*20 + ko + t4];
                aH[mt][2] = A32h[r*20 + ko + 4 + t4];
                aH[mt][3] = A32h[(r+8)*20 + ko + 4 + t4];
                aL[mt][0] = A32l[r*20 + ko + t4];
                aL[mt][1] = A32l[(r+8)*20 + ko + t4];
                aL[mt][2] = A32l[r*20 + ko + 4 + t4];
                aL[mt][3] = A32l[(r+8)*20 + ko + 4 + t4];
            }
            #pragma unroll
            for (int nt = 0; nt < 8; nt++) {
                const int nr = wn*64 + nt*8 + g;
                uint32_t bH[2];
                bH[0] = B32h[nr*20 + ko + t4];
                bH[1] = B32h[nr*20 + ko + 4 + t4];
                #pragma unroll
                for (int mt = 0; mt < 2; mt++) {
                    mma_hf(acc[mt][nt], aH[mt], bH);
                    mma_hf(acc[mt][nt], aL[mt], bH);
                }
            }
        }
        __syncthreads();
    }

    auto wr = [&](int row, int col, float v0, float v1) {
        if (EPI == 11) {
            float f0 = fmaxf(v0 + bias[col], 0.f);
            float f1 = fmaxf(v1 + bias[col + 1], 0.f);
            fp16 h0, l0, h1, l1;
            splith(f0, &h0, &l0); splith(f1, &h1, &l1);
            *(uint32_t*)(Oh + (size_t)row * ldo + col) =
                (uint32_t)hfbits(h0) | ((uint32_t)hfbits(h1) << 16);
            *(uint32_t*)(Ol + (size_t)row * ldo + col) =
                (uint32_t)hfbits(l0) | ((uint32_t)hfbits(l1) << 16);
        } else {
            const float* rr = resid + (size_t)row * ldc + col;
            float2 o;
            o.x = v0 + rr[0]; o.y = v1 + rr[1];
            if (EPI == 5) { o.x += bias[col]; o.y += bias[col + 1]; }
            *(float2*)(Cf + (size_t)row * ldc + col) = o;
        }
    };
    #pragma unroll
    for (int mt = 0; mt < 2; mt++) {
        #pragma unroll
        for (int nt = 0; nt < 8; nt++) {
            const int row = bm + wm*32 + mt*16 + g;
            const int col = bn + wn*64 + nt*8 + 2*t4;
            wr(row,     col, acc[mt][nt][0], acc[mt][nt][1]);
            wr(row + 8, col, acc[mt][nt][2], acc[mt][nt][3]);
        }
    }
}

// ---------------- wrappers ----------------
__global__ void __launch_bounds__(256, 2) kt_qkv() {
    extern __shared__ __align__(16) uint8_t dynsm[];
    const int bm = blockIdx.y * 128, bn = blockIdx.x * 128;
    if (blockIdx.z == 0)
        tcore<0>(dynsm, g_xn_h, g_xn_l, 1024, g_wqt_h, g_wqt_l, 1024, 1024,
                 bm, bn, g_q_h, g_q_l, 1024);
    else if (blockIdx.z == 1)
        tcore<0>(dynsm, g_xn_h, g_xn_l, 1024, g_wkt_h, g_wkt_l, 1024, 1024,
                 bm, bn, g_k_h, g_k_l, 1024);
    else
        tcore<2>(dynsm, g_xn_h, g_xn_l, 1024, g_wvt_h, g_wvt_l, 1024, 1024,
                 bm, bn, g_vt_h, g_vt_l, 4096);
}
__global__ void __launch_bounds__(256, 2) kt_wo(const float* __restrict__ x) {
    extern __shared__ __align__(16) uint8_t dynsm[];
    fcore<4>(dynsm, g_ctx_h, g_ctx_l, 1024, g_wot_h, 1024, 1024,
             blockIdx.y*128, blockIdx.x*128,
             g_x1, 1024, nullptr, nullptr, 0, nullptr, x);
}
__global__ void __launch_bounds__(256, 2) kt_ffn1(const float* __restrict__ b1) {
    extern __shared__ __align__(16) uint8_t dynsm[];
    fcore<11>(dynsm, g_xn2_h, g_xn2_l, 1024, g_w1t_h, 1024, 1024,
              blockIdx.y*128, blockIdx.x*128,
              nullptr, 0, g_ffh_h, g_ffh_l, 4096, b1, nullptr);
}
__global__ void __launch_bounds__(256, 2) kt_ffn2(const float* __restrict__ b2,
                                                  float* __restrict__ out) {
    extern __shared__ __align__(16) uint8_t dynsm[];
    fcore<5>(dynsm, g_ffh_h, g_ffh_l, 4096, g_w2t_h, 4096, 4096,
             blockIdx.y*128, blockIdx.x*128,
             out, 1024, nullptr, nullptr, 0, b2, g_x1);
}

// ---------------- launch ----------------
extern "C" void kernel_launch(void* const* d_in, const int* in_sizes, int n_in,
                              void* d_out, int out_size)
{
    const float* x      = (const float*)d_in[0];
    const int*   mask   = (const int*)  d_in[1];
    const float* wq     = (const float*)d_in[2];
    const float* wk     = (const float*)d_in[3];
    const float* wv     = (const float*)d_in[4];
    const float* wo     = (const float*)d_in[5];
    const float* w1     = (const float*)d_in[6];
    const float* b1     = (const float*)d_in[7];
    const float* w2     = (const float*)d_in[8];
    const float* b2     = (const float*)d_in[9];
    const float* alpha1 = (const float*)d_in[10];
    const float* bias1  = (const float*)d_in[11];
    const float* alpha2 = (const float*)d_in[12];
    const float* bias2  = (const float*)d_in[13];
    float* out = (float*)d_out;

    static int attr_set = 0;
    if (!attr_set) {
        cudaFuncSetAttribute(kt_attn, cudaFuncAttributeMaxDynamicSharedMemorySize, ATTN_SMEM);
        cudaFuncSetAttribute(kt_qkv,  cudaFuncAttributeMaxDynamicSharedMemorySize, GEMM_SMEM);
        cudaFuncSetAttribute(kt_wo,   cudaFuncAttributeMaxDynamicSharedMemorySize, GEMM2_SMEM);
        cudaFuncSetAttribute(kt_ffn1, cudaFuncAttributeMaxDynamicSharedMemorySize, GEMM2_SMEM);
        cudaFuncSetAttribute(kt_ffn2, cudaFuncAttributeMaxDynamicSharedMemorySize, GEMM2_SMEM);
        attr_set = 1;
    }

    k_prep_all<<<12288, 256>>>(wq, wk, wv, wo, w1, w2);

    // sublayer 1
    k_ln<<<NTOK, 256>>>(x, 0, alpha1, bias1);
    kt_qkv<<<dim3(8, 32, 3), 256, GEMM_SMEM>>>();
    kt_attn<<<dim3(16, 32), 256, ATTN_SMEM>>>(mask);
    kt_wo<<<dim3(8, 32), 256, GEMM2_SMEM>>>(x);

    // sublayer 2
    k_ln<<<NTOK, 256>>>(x, 1, alpha2, bias2);
    kt_ffn1<<<dim3(32, 32), 256, GEMM2_SMEM>>>(b1);
    kt_ffn2<<<dim3(8, 32), 256, GEMM2_SMEM>>>(b2, out);
}

// round 14
// speedup vs baseline: 1.6350x; 1.1640x over previous
#include <cuda_runtime.h>
#include <cuda_fp16.h>
#include <math.h>
#include <stdint.h>

#define DMODEL 1024
#define DFF 4096
#define SEQ 2048
#define NTOK 4096
#define LN_EPS 1e-5f
typedef __half fp16;

// ---------------- device-global scratch (all fp16 2-MMA scheme) ----------------
__device__ fp16 g_wqt[1u<<20];                      // [N,K] K-major, pre-scaled 0.125
__device__ fp16 g_wkt[1u<<20];
__device__ fp16 g_wvt[1u<<20];
__device__ fp16 g_wot[1u<<20];
__device__ fp16 g_w1t[1u<<22];                      // [4096,1024]
__device__ fp16 g_w2t[1u<<22];                      // [1024,4096]
__device__ fp16 g_xn_h[1u<<22], g_xn_l[1u<<22];     // LN out, fp16 pairs
__device__ fp16 g_q_h [1u<<22], g_q_l [1u<<22];     // Q fp16 pairs
__device__ fp16 g_k   [1u<<22];                     // K fp16 hi only
__device__ fp16 g_vt  [1u<<22];                     // V^T fp16 hi only [1024 dk, 4096 tok]
__device__ fp16 g_ctx_h[1u<<22], g_ctx_l[1u<<22];   // ctx fp16 pairs
__device__ fp16 g_ffh_h[1u<<24], g_ffh_l[1u<<24];   // ffn hidden fp16 pairs
__device__ float g_x1[1u<<22];

// ---------------- helpers ----------------
__device__ __forceinline__ void mma_hf(float* d, const uint32_t* a, const uint32_t* b) {
    asm volatile(
        "mma.sync.aligned.m16n8k16.row.col.f32.f16.f16.f32 "
        "{%0,%1,%2,%3}, {%4,%5,%6,%7}, {%8,%9}, {%0,%1,%2,%3};"
        : "+f"(d[0]), "+f"(d[1]), "+f"(d[2]), "+f"(d[3])
        : "r"(a[0]), "r"(a[1]), "r"(a[2]), "r"(a[3]), "r"(b[0]), "r"(b[1]));
}
__device__ __forceinline__ uint16_t hfbits(fp16 v) { return __half_as_ushort(v); }
__device__ __forceinline__ void splith(float f, fp16* h, fp16* l) {
    fp16 hh = __float2half_rn(f);
    *h = hh; *l = __float2half_rn(f - __half2float(hh));
}
__device__ __forceinline__ void cpa16(uint32_t dst, const void* src) {
    asm volatile("cp.async.cg.shared.global [%0], [%1], 16;" :: "r"(dst), "l"(src) : "memory");
}
#define CP_COMMIT() asm volatile("cp.async.commit_group;" ::: "memory")
#define CP_WAIT(n)  asm volatile("cp.async.wait_group %0;" :: "n"(n) : "memory")
__device__ __forceinline__ uint32_t smem_u32(const void* p) {
    uint32_t a;
    asm("{ .reg .u64 t; cvta.to.shared.u64 t, %1; cvt.u32.u64 %0, t; }" : "=r"(a) : "l"(p));
    return a;
}
__device__ __forceinline__ float warpSum(float v) {
    #pragma unroll
    for (int o = 16; o > 0; o >>= 1) v += __shfl_down_sync(0xffffffffu, v, o);
    return v;
}
__device__ __forceinline__ float blockSum(float v) {
    __shared__ float sh[8];
    int l = threadIdx.x & 31, w = threadIdx.x >> 5;
    v = warpSum(v);
    if (l == 0) sh[w] = v;
    __syncthreads();
    if (w == 0) { float t = (l < 8) ? sh[l] : 0.f; t = warpSum(t); if (l == 0) sh[0] = t; }
    __syncthreads();
    float r = sh[0]; __syncthreads();
    return r;
}

// ---------------- weight prep: ONE launch, all six -> fp16 hi ----------------
__global__ void __launch_bounds__(256) k_prep_all(
    const float* __restrict__ wq, const float* __restrict__ wk,
    const float* __restrict__ wv, const float* __restrict__ wo,
    const float* __restrict__ w1, const float* __restrict__ w2)
{
    int t = blockIdx.x;
    const float* w; fp16* fh;
    int K, N, local;
    float scale = 1.0f;
    if (t < 4096) {
        int seg = t >> 10; local = t & 1023;
        K = 1024; N = 1024;
        switch (seg) {
            case 0: w = wq; fh = g_wqt; scale = 0.125f; break;
            case 1: w = wk; fh = g_wkt; break;
            case 2: w = wv; fh = g_wvt; break;
            default: w = wo; fh = g_wot; break;
        }
    } else if (t < 8192) {
        local = t - 4096; w = w1; fh = g_w1t; K = 1024; N = 4096;
    } else {
        local = t - 8192; w = w2; fh = g_w2t; K = 4096; N = 1024;
    }
    const int xt = N >> 5;
    const int n0 = (local % xt) * 32, k0 = (local / xt) * 32;

    __shared__ float ts[32][33];
    int tx = threadIdx.x & 31, ty = threadIdx.x >> 5;
    #pragma unroll
    for (int i = 0; i < 4; i++)
        ts[ty + 8*i][tx] = w[(size_t)(k0 + ty + 8*i) * N + n0 + tx];
    __syncthreads();
    #pragma unroll
    for (int i = 0; i < 4; i++) {
        int n = n0 + ty + 8*i, k = k0 + tx;
        fh[(size_t)n * K + k] = __float2half_rn(ts[tx][ty + 8*i] * scale);
    }
}

// ---------------- LayerNorm -> fp16 hi/lo pairs ----------------
__global__ void __launch_bounds__(256) k_ln(const float* __restrict__ xin, int use_x1,
                                            const float* __restrict__ ap,
                                            const float* __restrict__ bp)
{
    const float* src = use_x1 ? g_x1 : xin;
    int row = blockIdx.x, t = threadIdx.x;
    const float* xr = src + (size_t)row * DMODEL;
    float v[4], s = 0.f, sq = 0.f;
    #pragma unroll
    for (int i = 0; i < 4; i++) { v[i] = xr[t + 256*i]; s += v[i]; sq += v[i]*v[i]; }
    s = blockSum(s); sq = blockSum(sq);
    float mean = s * (1.0f / DMODEL);
    float var = fmaxf((sq - (float)DMODEL * mean * mean) * (1.0f / (DMODEL - 1)), 0.f);
    float sc = ap[0] / (sqrtf(var) + LN_EPS);
    float bi = bp[0];
    #pragma unroll
    for (int i = 0; i < 4; i++) {
        size_t o = (size_t)row * DMODEL + t + 256*i;
        splith((v[i] - mean) * sc + bi, &g_xn_h[o], &g_xn_l[o]);
    }
}

// ---------------------------------------------------------------------------
// Fused flash attention, full fp16 2-MMA:
//   S = (Qh+Ql)·Kh   (2 MMAs),  O += (Ph+Pl)·Vh  (2 MMAs)
// K/V tiles hi-only -> buffer = Kh + Vh = 18432 B; double-buffered + mask.
// ---------------------------------------------------------------------------
#define ATTN_SMEM 45056
#define BUFB 18432u
#define TILEB 9216u

__global__ void __launch_bounds__(256, 2) kt_attn(const int* __restrict__ mask)
{
    extern __shared__ __align__(16) uint8_t dynsm[];
    const int z = blockIdx.y, b = z >> 4, h = z & 15;
    const int q0 = blockIdx.x * 128;
    const int tid = threadIdx.x, wid = tid >> 5, lane = tid & 31;
    const int g = lane >> 2, t4 = lane & 3;

    uint32_t sbase = smem_u32(dynsm);
    int* s_mask = (int*)(dynsm + 2*BUFB);

    for (int i = tid; i < SEQ/4; i += 256)
        *(int4*)&s_mask[i*4] = *(const int4*)&mask[b*SEQ + i*4];

    // Q fragments (fp16 pairs), register-resident
    uint32_t qh[4][4], ql[4][4];
    {
        const uint32_t* Q32h = (const uint32_t*)g_q_h;
        const uint32_t* Q32l = (const uint32_t*)g_q_l;
        size_t r0 = ((size_t)(b*SEQ + q0 + wid*16 + g)) * 512 + h*32;
        size_t r8 = r0 + 8*512;
        #pragma unroll
        for (int s = 0; s < 4; s++) {
            qh[s][0] = Q32h[r0 + s*8 + t4];
            qh[s][1] = Q32h[r8 + s*8 + t4];
            qh[s][2] = Q32h[r0 + s*8 + 4 + t4];
            qh[s][3] = Q32h[r8 + s*8 + 4 + t4];
            ql[s][0] = Q32l[r0 + s*8 + t4];
            ql[s][1] = Q32l[r8 + s*8 + t4];
            ql[s][2] = Q32l[r0 + s*8 + 4 + t4];
            ql[s][3] = Q32l[r8 + s*8 + 4 + t4];
        }
    }

    float O[8][4];
    #pragma unroll
    for (int i = 0; i < 8; i++)
        #pragma unroll
        for (int j = 0; j < 4; j++) O[i][j] = 0.f;
    float m0 = -INFINITY, m1 = -INFINITY, l0 = 0.f, l1 = 0.f;

    const int krow = tid >> 2, kcb = (tid & 3) * 16;
    const uint32_t soff = (uint32_t)(krow*72 + kcb) * 2u;

    auto load_tile = [&](int kt, int p) {
        const uint32_t base = sbase + p*BUFB;
        size_t gk = ((size_t)(b*SEQ + kt*64 + krow)) * 1024 + h*64 + kcb;
        cpa16(base + soff,      &g_k[gk]);
        cpa16(base + soff + 16, &g_k[gk + 8]);
        size_t gv = ((size_t)(h*64 + krow)) * 4096 + b*SEQ + kt*64 + kcb;
        cpa16(base + TILEB + soff,      &g_vt[gv]);
        cpa16(base + TILEB + soff + 16, &g_vt[gv + 8]);
        CP_COMMIT();
    };

    load_tile(0, 0);
    for (int kt = 0; kt < SEQ/64; kt++) {
        __syncthreads();
        if (kt + 1 < SEQ/64) { load_tile(kt + 1, (kt + 1) & 1); CP_WAIT(1); }
        else                 { CP_WAIT(0); }
        __syncthreads();

        const uint8_t* buf = dynsm + (kt & 1) * BUFB;
        const uint32_t* K32 = (const uint32_t*)(buf);
        const uint32_t* V32 = (const uint32_t*)(buf + TILEB);

        // ---- S = (Qh+Ql) K^T ----
        float s[8][4];
        #pragma unroll
        for (int nt = 0; nt < 8; nt++) {
            s[nt][0] = s[nt][1] = s[nt][2] = s[nt][3] = 0.f;
            const int nr = (nt*8 + g) * 36;
            #pragma unroll
            for (int ks = 0; ks < 4; ks++) {
                uint32_t bh[2] = { K32[nr + ks*8 + t4], K32[nr + ks*8 + 4 + t4] };
                mma_hf(s[nt], qh[ks], bh);
                mma_hf(s[nt], ql[ks], bh);
            }
        }
        // ---- mask ----
        #pragma unroll
        for (int nt = 0; nt < 8; nt++) {
            const int c = kt*64 + nt*8 + 2*t4;
            if (s_mask[c]   == 0) { s[nt][0] = -1e9f; s[nt][2] = -1e9f; }
            if (s_mask[c+1] == 0) { s[nt][1] = -1e9f; s[nt][3] = -1e9f; }
        }
        // ---- online softmax ----
        float mx0 = -INFINITY, mx1 = -INFINITY;
        #pragma unroll
        for (int nt = 0; nt < 8; nt++) {
            mx0 = fmaxf(mx0, fmaxf(s[nt][0], s[nt][1]));
            mx1 = fmaxf(mx1, fmaxf(s[nt][2], s[nt][3]));
        }
        mx0 = fmaxf(mx0, __shfl_xor_sync(0xffffffffu, mx0, 1));
        mx0 = fmaxf(mx0, __shfl_xor_sync(0xffffffffu, mx0, 2));
        mx1 = fmaxf(mx1, __shfl_xor_sync(0xffffffffu, mx1, 1));
        mx1 = fmaxf(mx1, __shfl_xor_sync(0xffffffffu, mx1, 2));
        float nm0 = fmaxf(m0, mx0), nm1 = fmaxf(m1, mx1);
        float a0 = __expf(m0 - nm0), a1 = __expf(m1 - nm1);
        m0 = nm0; m1 = nm1;
        float ps0 = 0.f, ps1 = 0.f;
        #pragma unroll
        for (int nt = 0; nt < 8; nt++) {
            s[nt][0] = __expf(s[nt][0] - nm0);
            s[nt][1] = __expf(s[nt][1] - nm0);
            s[nt][2] = __expf(s[nt][2] - nm1);
            s[nt][3] = __expf(s[nt][3] - nm1);
            ps0 += s[nt][0] + s[nt][1];
            ps1 += s[nt][2] + s[nt][3];
        }
        ps0 += __shfl_xor_sync(0xffffffffu, ps0, 1);
        ps0 += __shfl_xor_sync(0xffffffffu, ps0, 2);
        ps1 += __shfl_xor_sync(0xffffffffu, ps1, 1);
        ps1 += __shfl_xor_sync(0xffffffffu, ps1, 2);
        l0 = l0 * a0 + ps0;
        l1 = l1 * a1 + ps1;
        #pragma unroll
        for (int nt = 0; nt < 8; nt++) {
            O[nt][0] *= a0; O[nt][1] *= a0;
            O[nt][2] *= a1; O[nt][3] *= a1;
        }
        // ---- P -> fp16 hi/lo A-fragments ----
        uint32_t pH[4][4], pL[4][4];
        #pragma unroll
        for (int ks = 0; ks < 4; ks++) {
            #pragma unroll
            for (int half = 0; half < 2; half++) {
                const int nt = 2*ks + half;
                fp16 h0 = __float2half_rn(s[nt][0]);
                fp16 h1 = __float2half_rn(s[nt][1]);
                fp16 h2 = __float2half_rn(s[nt][2]);
                fp16 h3 = __float2half_rn(s[nt][3]);
                pH[ks][2*half]   = (uint32_t)hfbits(h0) | ((uint32_t)hfbits(h1) << 16);
                pH[ks][2*half+1] = (uint32_t)hfbits(h2) | ((uint32_t)hfbits(h3) << 16);
                fp16 e0 = __float2half_rn(s[nt][0] - __half2float(h0));
                fp16 e1 = __float2half_rn(s[nt][1] - __half2float(h1));
                fp16 e2 = __float2half_rn(s[nt][2] - __half2float(h2));
                fp16 e3 = __float2half_rn(s[nt][3] - __half2float(h3));
                pL[ks][2*half]   = (uint32_t)hfbits(e0) | ((uint32_t)hfbits(e1) << 16);
                pL[ks][2*half+1] = (uint32_t)hfbits(e2) | ((uint32_t)hfbits(e3) << 16);
            }
        }
        // ---- O += (Ph+Pl) V^T ----
        #pragma unroll
        for (int nt = 0; nt < 8; nt++) {
            const int nr = (nt*8 + g) * 36;
            #pragma unroll
            for (int ks = 0; ks < 4; ks++) {
                uint32_t bh[2] = { V32[nr + ks*8 + t4], V32[nr + ks*8 + 4 + t4] };
                mma_hf(O[nt], pH[ks], bh);
                mma_hf(O[nt], pL[ks], bh);
            }
        }
    }

    // ---- epilogue: ctx = O / l, fp16 pairs ----
    const float il0 = 1.0f / l0, il1 = 1.0f / l1;
    const size_t row0 = (size_t)(b*SEQ + q0 + wid*16 + g);
    const size_t row8 = row0 + 8;
    #pragma unroll
    for (int nt = 0; nt < 8; nt++) {
        const int col = h*64 + nt*8 + 2*t4;
        fp16 h0, l0b, h1, l1b;
        splith(O[nt][0] * il0, &h0, &l0b);
        splith(O[nt][1] * il0, &h1, &l1b);
        *(uint32_t*)(g_ctx_h + row0*1024 + col) =
            (uint32_t)hfbits(h0) | ((uint32_t)hfbits(h1) << 16);
        *(uint32_t*)(g_ctx_l + row0*1024 + col) =
            (uint32_t)hfbits(l0b) | ((uint32_t)hfbits(l1b) << 16);
        splith(O[nt][2] * il1, &h0, &l0b);
        splith(O[nt][3] * il1, &h1, &l1b);
        *(uint32_t*)(g_ctx_h + row8*1024 + col) =
            (uint32_t)hfbits(h0) | ((uint32_t)hfbits(h1) << 16);
        *(uint32_t*)(g_ctx_l + row8*1024 + col) =
            (uint32_t)hfbits(l0b) | ((uint32_t)hfbits(l1b) << 16);
    }
}

// ---------------------------------------------------------------------------
// fp16 2-MMA GEMM core: A·B ≈ (Ah+Al)·Bh. Stage = Ah, Al, Bh (30 KB).
// EPI: 4 fp32+resid | 5 fp32+bias+resid | 10 fp16 pair-out | 11 bias+relu pair-out
//      12 fp16 hi-only out | 13 fp16 hi-only transposed out
// ---------------------------------------------------------------------------
#define GEMM2_SMEM 61440
#define G2STAGE 30720u
#define GTILE 10240u

template<int EPI>
__device__ __forceinline__ void fcore(
    uint8_t* dynsm,
    const fp16* __restrict__ Ah, const fp16* __restrict__ Al, int lda,
    const fp16* __restrict__ Bh, int ldb,
    int K, int bm, int bn,
    float* __restrict__ Cf, int ldc,
    fp16* __restrict__ Oh, fp16* __restrict__ Ol, int ldo,
    const float* __restrict__ bias, const float* __restrict__ resid)
{
    const int tid = threadIdx.x, wid = tid >> 5, lane = tid & 31;
    const int wm = wid & 3, wn = wid >> 2;
    const int g = lane >> 2, t4 = lane & 3;
    const int ar = tid >> 1, akq = (tid & 1) * 16;

    const uint32_t sbase = smem_u32(dynsm);
    const uint32_t doff = (uint32_t)(ar*40 + akq) * 2u;

    float acc[2][8][4];
    #pragma unroll
    for (int i = 0; i < 2; i++)
        #pragma unroll
        for (int j = 0; j < 8; j++)
            #pragma unroll
            for (int e = 0; e < 4; e++) acc[i][j][e] = 0.f;

    auto load_chunk = [&](int k0, int p) {
        const uint32_t base = sbase + p*G2STAGE + doff;
        const fp16* a_h = Ah + (size_t)(bm + ar) * lda + k0 + akq;
        const fp16* a_l = Al + (size_t)(bm + ar) * lda + k0 + akq;
        cpa16(base + 0*GTILE,      a_h);
        cpa16(base + 0*GTILE + 16, a_h + 8);
        cpa16(base + 1*GTILE,      a_l);
        cpa16(base + 1*GTILE + 16, a_l + 8);
        const fp16* b_h = Bh + (size_t)(bn + ar) * ldb + k0 + akq;
        cpa16(base + 2*GTILE,      b_h);
        cpa16(base + 2*GTILE + 16, b_h + 8);
        CP_COMMIT();
    };

    const int nch = K >> 5;
    load_chunk(0, 0);
    for (int c = 0; c < nch; c++) {
        if (c + 1 < nch) { load_chunk((c + 1) << 5, (c + 1) & 1); CP_WAIT(1); }
        else             { CP_WAIT(0); }
        __syncthreads();

        const uint8_t* st = dynsm + (c & 1) * G2STAGE;
        const uint32_t* A32h = (const uint32_t*)(st);
        const uint32_t* A32l = (const uint32_t*)(st + GTILE);
        const uint32_t* B32h = (const uint32_t*)(st + 2*GTILE);

        #pragma unroll
        for (int kh = 0; kh < 2; kh++) {
            const int ko = kh * 8;
            uint32_t aH[2][4], aL[2][4];
            #pragma unroll
            for (int mt = 0; mt < 2; mt++) {
                const int r = wm*32 + mt*16 + g;
                aH[mt][0] = A32h[r*20 + ko + t4];
                aH[mt][1] = A32h[(r+8)*20 + ko + t4];
                aH[mt][2] = A32h[r*20 + ko + 4 + t4];
                aH[mt][3] = A32h[(r+8)*20 + ko + 4 + t4];
                aL[mt][0] = A32l[r*20 + ko + t4];
                aL[mt][1] = A32l[(r+8)*20 + ko + t4];
                aL[mt][2] = A32l[r*20 + ko + 4 + t4];
                aL[mt][3] = A32l[(r+8)*20 + ko + 4 + t4];
            }
            #pragma unroll
            for (int nt = 0; nt < 8; nt++) {
                const int nr = wn*64 + nt*8 + g;
                uint32_t bH[2];
                bH[0] = B32h[nr*20 + ko + t4];
                bH[1] = B32h[nr*20 + ko + 4 + t4];
                #pragma unroll
                for (int mt = 0; mt < 2; mt++) {
                    mma_hf(acc[mt][nt], aH[mt], bH);
                    mma_hf(acc[mt][nt], aL[mt], bH);
                }
            }
        }
        __syncthreads();
    }

    auto wr = [&](int row, int col, float v0, float v1) {
        if (EPI == 10 || EPI == 11) {
            if (EPI == 11) {
                v0 = fmaxf(v0 + bias[col], 0.f);
                v1 = fmaxf(v1 + bias[col + 1], 0.f);
            }
            fp16 h0, l0, h1, l1;
            splith(v0, &h0, &l0); splith(v1, &h1, &l1);
            *(uint32_t*)(Oh + (size_t)row * ldo + col) =
                (uint32_t)hfbits(h0) | ((uint32_t)hfbits(h1) << 16);
            *(uint32_t*)(Ol + (size_t)row * ldo + col) =
                (uint32_t)hfbits(l0) | ((uint32_t)hfbits(l1) << 16);
        } else if (EPI == 12) {
            *(uint32_t*)(Oh + (size_t)row * ldo + col) =
                (uint32_t)hfbits(__float2half_rn(v0)) |
                ((uint32_t)hfbits(__float2half_rn(v1)) << 16);
        } else if (EPI == 13) {
            Oh[(size_t)col * ldo + row]       = __float2half_rn(v0);
            Oh[(size_t)(col + 1) * ldo + row] = __float2half_rn(v1);
        } else {
            const float* rr = resid + (size_t)row * ldc + col;
            float2 o;
            o.x = v0 + rr[0]; o.y = v1 + rr[1];
            if (EPI == 5) { o.x += bias[col]; o.y += bias[col + 1]; }
            *(float2*)(Cf + (size_t)row * ldc + col) = o;
        }
    };
    #pragma unroll
    for (int mt = 0; mt < 2; mt++) {
        #pragma unroll
        for (int nt = 0; nt < 8; nt++) {
            const int row = bm + wm*32 + mt*16 + g;
            const int col = bn + wn*64 + nt*8 + 2*t4;
            wr(row,     col, acc[mt][nt][0], acc[mt][nt][1]);
            wr(row + 8, col, acc[mt][nt][2], acc[mt][nt][3]);
        }
    }
}

// ---------------- wrappers ----------------
__global__ void __launch_bounds__(256, 2) kt_qkv() {
    extern __shared__ __align__(16) uint8_t dynsm[];
    const int bm = blockIdx.y * 128, bn = blockIdx.x * 128;
    if (blockIdx.z == 0)
        fcore<10>(dynsm, g_xn_h, g_xn_l, 1024, g_wqt, 1024, 1024,
                  bm, bn, nullptr, 0, g_q_h, g_q_l, 1024, nullptr, nullptr);
    else if (blockIdx.z == 1)
        fcore<12>(dynsm, g_xn_h, g_xn_l, 1024, g_wkt, 1024, 1024,
                  bm, bn, nullptr, 0, g_k, nullptr, 1024, nullptr, nullptr);
    else
        fcore<13>(dynsm, g_xn_h, g_xn_l, 1024, g_wvt, 1024, 1024,
                  bm, bn, nullptr, 0, g_vt, nullptr, 4096, nullptr, nullptr);
}
__global__ void __launch_bounds__(256, 2) kt_wo(const float* __restrict__ x) {
    extern __shared__ __align__(16) uint8_t dynsm[];
    fcore<4>(dynsm, g_ctx_h, g_ctx_l, 1024, g_wot, 1024, 1024,
             blockIdx.y*128, blockIdx.x*128,
             g_x1, 1024, nullptr, nullptr, 0, nullptr, x);
}
__global__ void __launch_bounds__(256, 2) kt_ffn1(const float* __restrict__ b1) {
    extern __shared__ __align__(16) uint8_t dynsm[];
    fcore<11>(dynsm, g_xn_h, g_xn_l, 1024, g_w1t, 1024, 1024,
              blockIdx.y*128, blockIdx.x*128,
              nullptr, 0, g_ffh_h, g_ffh_l, 4096, b1, nullptr);
}
__global__ void __launch_bounds__(256, 2) kt_ffn2(const float* __restrict__ b2,
                                                  float* __restrict__ out) {
    extern __shared__ __align__(16) uint8_t dynsm[];
    fcore<5>(dynsm, g_ffh_h, g_ffh_l, 4096, g_w2t, 4096, 4096,
             blockIdx.y*128, blockIdx.x*128,
             out, 1024, nullptr, nullptr, 0, b2, g_x1);
}

// ---------------- launch ----------------
extern "C" void kernel_launch(void* const* d_in, const int* in_sizes, int n_in,
                              void* d_out, int out_size)
{
    const float* x      = (const float*)d_in[0];
    const int*   mask   = (const int*)  d_in[1];
    const float* wq     = (const float*)d_in[2];
    const float* wk     = (const float*)d_in[3];
    const float* wv     = (const float*)d_in[4];
    const float* wo     = (const float*)d_in[5];
    const float* w1     = (const float*)d_in[6];
    const float* b1     = (const float*)d_in[7];
    const float* w2     = (const float*)d_in[8];
    const float* b2     = (const float*)d_in[9];
    const float* alpha1 = (const float*)d_in[10];
    const float* bias1  = (const float*)d_in[11];
    const float* alpha2 = (const float*)d_in[12];
    const float* bias2  = (const float*)d_in[13];
    float* out = (float*)d_out;

    static int attr_set = 0;
    if (!attr_set) {
        cudaFuncSetAttribute(kt_attn, cudaFuncAttributeMaxDynamicSharedMemorySize, ATTN_SMEM);
        cudaFuncSetAttribute(kt_qkv,  cudaFuncAttributeMaxDynamicSharedMemorySize, GEMM2_SMEM);
        cudaFuncSetAttribute(kt_wo,   cudaFuncAttributeMaxDynamicSharedMemorySize, GEMM2_SMEM);
        cudaFuncSetAttribute(kt_ffn1, cudaFuncAttributeMaxDynamicSharedMemorySize, GEMM2_SMEM);
        cudaFuncSetAttribute(kt_ffn2, cudaFuncAttributeMaxDynamicSharedMemorySize, GEMM2_SMEM);
        attr_set = 1;
    }

    k_prep_all<<<12288, 256>>>(wq, wk, wv, wo, w1, w2);

    // sublayer 1
    k_ln<<<NTOK, 256>>>(x, 0, alpha1, bias1);
    kt_qkv<<<dim3(8, 32, 3), 256, GEMM2_SMEM>>>();
    kt_attn<<<dim3(16, 32), 256, ATTN_SMEM>>>(mask);
    kt_wo<<<dim3(8, 32), 256, GEMM2_SMEM>>>(x);

    // sublayer 2
    k_ln<<<NTOK, 256>>>(x, 1, alpha2, bias2);
    kt_ffn1<<<dim3(32, 32), 256, GEMM2_SMEM>>>(b1);
    kt_ffn2<<<dim3(8, 32), 256, GEMM2_SMEM>>>(b2, out);
}

// round 15
// speedup vs baseline: 2.2314x; 1.3648x over previous
#include <cuda_runtime.h>
#include <cuda_fp16.h>
#include <math.h>
#include <stdint.h>

#define DMODEL 1024
#define DFF 4096
#define SEQ 2048
#define NTOK 4096
#define LN_EPS 1e-5f
typedef __half fp16;

// ---------------- device-global scratch ----------------
__device__ fp16 g_wqt[1u<<20];                      // [N,K] K-major, pre-scaled 0.125
__device__ fp16 g_wkt[1u<<20];
__device__ fp16 g_wvt[1u<<20];
__device__ fp16 g_wot[1u<<20];
__device__ fp16 g_w1t[1u<<22];                      // [4096,1024]
__device__ fp16 g_w2t[1u<<22];                      // [1024,4096]
__device__ fp16 g_xn [1u<<22];                      // LN out, fp16 hi only
__device__ fp16 g_q_h[1u<<22], g_q_l[1u<<22];       // Q fp16 pairs (attn 2-MMA)
__device__ fp16 g_k  [1u<<22];                      // K fp16 hi only
__device__ fp16 g_vt [1u<<22];                      // V^T fp16 hi only [1024 dk, 4096 tok]
__device__ fp16 g_ctx[1u<<22];                      // ctx fp16 hi only
__device__ fp16 g_ffh[1u<<24];                      // ffn hidden fp16 hi only
__device__ float g_x1[1u<<22];

// ---------------- helpers ----------------
__device__ __forceinline__ void mma_hf(float* d, const uint32_t* a, const uint32_t* b) {
    asm volatile(
        "mma.sync.aligned.m16n8k16.row.col.f32.f16.f16.f32 "
        "{%0,%1,%2,%3}, {%4,%5,%6,%7}, {%8,%9}, {%0,%1,%2,%3};"
        : "+f"(d[0]), "+f"(d[1]), "+f"(d[2]), "+f"(d[3])
        : "r"(a[0]), "r"(a[1]), "r"(a[2]), "r"(a[3]), "r"(b[0]), "r"(b[1]));
}
__device__ __forceinline__ uint16_t hfbits(fp16 v) { return __half_as_ushort(v); }
__device__ __forceinline__ void splith(float f, fp16* h, fp16* l) {
    fp16 hh = __float2half_rn(f);
    *h = hh; *l = __float2half_rn(f - __half2float(hh));
}
__device__ __forceinline__ void cpa16(uint32_t dst, const void* src) {
    asm volatile("cp.async.cg.shared.global [%0], [%1], 16;" :: "r"(dst), "l"(src) : "memory");
}
#define CP_COMMIT() asm volatile("cp.async.commit_group;" ::: "memory")
#define CP_WAIT(n)  asm volatile("cp.async.wait_group %0;" :: "n"(n) : "memory")
__device__ __forceinline__ uint32_t smem_u32(const void* p) {
    uint32_t a;
    asm("{ .reg .u64 t; cvta.to.shared.u64 t, %1; cvt.u32.u64 %0, t; }" : "=r"(a) : "l"(p));
    return a;
}
__device__ __forceinline__ float warpSum(float v) {
    #pragma unroll
    for (int o = 16; o > 0; o >>= 1) v += __shfl_down_sync(0xffffffffu, v, o);
    return v;
}
__device__ __forceinline__ float blockSum(float v) {
    __shared__ float sh[8];
    int l = threadIdx.x & 31, w = threadIdx.x >> 5;
    v = warpSum(v);
    if (l == 0) sh[w] = v;
    __syncthreads();
    if (w == 0) { float t = (l < 8) ? sh[l] : 0.f; t = warpSum(t); if (l == 0) sh[0] = t; }
    __syncthreads();
    float r = sh[0]; __syncthreads();
    return r;
}

// ---------------- weight prep: ONE launch, all six -> fp16 ----------------
__global__ void __launch_bounds__(256) k_prep_all(
    const float* __restrict__ wq, const float* __restrict__ wk,
    const float* __restrict__ wv, const float* __restrict__ wo,
    const float* __restrict__ w1, const float* __restrict__ w2)
{
    int t = blockIdx.x;
    const float* w; fp16* fh;
    int K, N, local;
    float scale = 1.0f;
    if (t < 4096) {
        int seg = t >> 10; local = t & 1023;
        K = 1024; N = 1024;
        switch (seg) {
            case 0: w = wq; fh = g_wqt; scale = 0.125f; break;
            case 1: w = wk; fh = g_wkt; break;
            case 2: w = wv; fh = g_wvt; break;
            default: w = wo; fh = g_wot; break;
        }
    } else if (t < 8192) {
        local = t - 4096; w = w1; fh = g_w1t; K = 1024; N = 4096;
    } else {
        local = t - 8192; w = w2; fh = g_w2t; K = 4096; N = 1024;
    }
    const int xt = N >> 5;
    const int n0 = (local % xt) * 32, k0 = (local / xt) * 32;

    __shared__ float ts[32][33];
    int tx = threadIdx.x & 31, ty = threadIdx.x >> 5;
    #pragma unroll
    for (int i = 0; i < 4; i++)
        ts[ty + 8*i][tx] = w[(size_t)(k0 + ty + 8*i) * N + n0 + tx];
    __syncthreads();
    #pragma unroll
    for (int i = 0; i < 4; i++) {
        int n = n0 + ty + 8*i, k = k0 + tx;
        fh[(size_t)n * K + k] = __float2half_rn(ts[tx][ty + 8*i] * scale);
    }
}

// ---------------- LayerNorm -> fp16 (hi only) ----------------
__global__ void __launch_bounds__(256) k_ln(const float* __restrict__ xin, int use_x1,
                                            const float* __restrict__ ap,
                                            const float* __restrict__ bp)
{
    const float* src = use_x1 ? g_x1 : xin;
    int row = blockIdx.x, t = threadIdx.x;
    const float* xr = src + (size_t)row * DMODEL;
    float v[4], s = 0.f, sq = 0.f;
    #pragma unroll
    for (int i = 0; i < 4; i++) { v[i] = xr[t + 256*i]; s += v[i]; sq += v[i]*v[i]; }
    s = blockSum(s); sq = blockSum(sq);
    float mean = s * (1.0f / DMODEL);
    float var = fmaxf((sq - (float)DMODEL * mean * mean) * (1.0f / (DMODEL - 1)), 0.f);
    float sc = ap[0] / (sqrtf(var) + LN_EPS);
    float bi = bp[0];
    #pragma unroll
    for (int i = 0; i < 4; i++) {
        size_t o = (size_t)row * DMODEL + t + 256*i;
        g_xn[o] = __float2half_rn((v[i] - mean) * sc + bi);
    }
}

// ---------------------------------------------------------------------------
// Fused flash attention (fp16 2-MMA, as R14). ctx output hi-only.
// ---------------------------------------------------------------------------
#define ATTN_SMEM 45056
#define BUFB 18432u
#define TILEB 9216u

__global__ void __launch_bounds__(256, 2) kt_attn(const int* __restrict__ mask)
{
    extern __shared__ __align__(16) uint8_t dynsm[];
    const int z = blockIdx.y, b = z >> 4, h = z & 15;
    const int q0 = blockIdx.x * 128;
    const int tid = threadIdx.x, wid = tid >> 5, lane = tid & 31;
    const int g = lane >> 2, t4 = lane & 3;

    uint32_t sbase = smem_u32(dynsm);
    int* s_mask = (int*)(dynsm + 2*BUFB);

    for (int i = tid; i < SEQ/4; i += 256)
        *(int4*)&s_mask[i*4] = *(const int4*)&mask[b*SEQ + i*4];

    uint32_t qh[4][4], ql[4][4];
    {
        const uint32_t* Q32h = (const uint32_t*)g_q_h;
        const uint32_t* Q32l = (const uint32_t*)g_q_l;
        size_t r0 = ((size_t)(b*SEQ + q0 + wid*16 + g)) * 512 + h*32;
        size_t r8 = r0 + 8*512;
        #pragma unroll
        for (int s = 0; s < 4; s++) {
            qh[s][0] = Q32h[r0 + s*8 + t4];
            qh[s][1] = Q32h[r8 + s*8 + t4];
            qh[s][2] = Q32h[r0 + s*8 + 4 + t4];
            qh[s][3] = Q32h[r8 + s*8 + 4 + t4];
            ql[s][0] = Q32l[r0 + s*8 + t4];
            ql[s][1] = Q32l[r8 + s*8 + t4];
            ql[s][2] = Q32l[r0 + s*8 + 4 + t4];
            ql[s][3] = Q32l[r8 + s*8 + 4 + t4];
        }
    }

    float O[8][4];
    #pragma unroll
    for (int i = 0; i < 8; i++)
        #pragma unroll
        for (int j = 0; j < 4; j++) O[i][j] = 0.f;
    float m0 = -INFINITY, m1 = -INFINITY, l0 = 0.f, l1 = 0.f;

    const int krow = tid >> 2, kcb = (tid & 3) * 16;
    const uint32_t soff = (uint32_t)(krow*72 + kcb) * 2u;

    auto load_tile = [&](int kt, int p) {
        const uint32_t base = sbase + p*BUFB;
        size_t gk = ((size_t)(b*SEQ + kt*64 + krow)) * 1024 + h*64 + kcb;
        cpa16(base + soff,      &g_k[gk]);
        cpa16(base + soff + 16, &g_k[gk + 8]);
        size_t gv = ((size_t)(h*64 + krow)) * 4096 + b*SEQ + kt*64 + kcb;
        cpa16(base + TILEB + soff,      &g_vt[gv]);
        cpa16(base + TILEB + soff + 16, &g_vt[gv + 8]);
        CP_COMMIT();
    };

    load_tile(0, 0);
    for (int kt = 0; kt < SEQ/64; kt++) {
        __syncthreads();
        if (kt + 1 < SEQ/64) { load_tile(kt + 1, (kt + 1) & 1); CP_WAIT(1); }
        else                 { CP_WAIT(0); }
        __syncthreads();

        const uint8_t* buf = dynsm + (kt & 1) * BUFB;
        const uint32_t* K32 = (const uint32_t*)(buf);
        const uint32_t* V32 = (const uint32_t*)(buf + TILEB);

        float s[8][4];
        #pragma unroll
        for (int nt = 0; nt < 8; nt++) {
            s[nt][0] = s[nt][1] = s[nt][2] = s[nt][3] = 0.f;
            const int nr = (nt*8 + g) * 36;
            #pragma unroll
            for (int ks = 0; ks < 4; ks++) {
                uint32_t bh[2] = { K32[nr + ks*8 + t4], K32[nr + ks*8 + 4 + t4] };
                mma_hf(s[nt], qh[ks], bh);
                mma_hf(s[nt], ql[ks], bh);
            }
        }
        #pragma unroll
        for (int nt = 0; nt < 8; nt++) {
            const int c = kt*64 + nt*8 + 2*t4;
            if (s_mask[c]   == 0) { s[nt][0] = -1e9f; s[nt][2] = -1e9f; }
            if (s_mask[c+1] == 0) { s[nt][1] = -1e9f; s[nt][3] = -1e9f; }
        }
        float mx0 = -INFINITY, mx1 = -INFINITY;
        #pragma unroll
        for (int nt = 0; nt < 8; nt++) {
            mx0 = fmaxf(mx0, fmaxf(s[nt][0], s[nt][1]));
            mx1 = fmaxf(mx1, fmaxf(s[nt][2], s[nt][3]));
        }
        mx0 = fmaxf(mx0, __shfl_xor_sync(0xffffffffu, mx0, 1));
        mx0 = fmaxf(mx0, __shfl_xor_sync(0xffffffffu, mx0, 2));
        mx1 = fmaxf(mx1, __shfl_xor_sync(0xffffffffu, mx1, 1));
        mx1 = fmaxf(mx1, __shfl_xor_sync(0xffffffffu, mx1, 2));
        float nm0 = fmaxf(m0, mx0), nm1 = fmaxf(m1, mx1);
        float a0 = __expf(m0 - nm0), a1 = __expf(m1 - nm1);
        m0 = nm0; m1 = nm1;
        float ps0 = 0.f, ps1 = 0.f;
        #pragma unroll
        for (int nt = 0; nt < 8; nt++) {
            s[nt][0] = __expf(s[nt][0] - nm0);
            s[nt][1] = __expf(s[nt][1] - nm0);
            s[nt][2] = __expf(s[nt][2] - nm1);
            s[nt][3] = __expf(s[nt][3] - nm1);
            ps0 += s[nt][0] + s[nt][1];
            ps1 += s[nt][2] + s[nt][3];
        }
        ps0 += __shfl_xor_sync(0xffffffffu, ps0, 1);
        ps0 += __shfl_xor_sync(0xffffffffu, ps0, 2);
        ps1 += __shfl_xor_sync(0xffffffffu, ps1, 1);
        ps1 += __shfl_xor_sync(0xffffffffu, ps1, 2);
        l0 = l0 * a0 + ps0;
        l1 = l1 * a1 + ps1;
        #pragma unroll
        for (int nt = 0; nt < 8; nt++) {
            O[nt][0] *= a0; O[nt][1] *= a0;
            O[nt][2] *= a1; O[nt][3] *= a1;
        }
        uint32_t pH[4][4], pL[4][4];
        #pragma unroll
        for (int ks = 0; ks < 4; ks++) {
            #pragma unroll
            for (int half = 0; half < 2; half++) {
                const int nt = 2*ks + half;
                fp16 h0 = __float2half_rn(s[nt][0]);
                fp16 h1 = __float2half_rn(s[nt][1]);
                fp16 h2 = __float2half_rn(s[nt][2]);
                fp16 h3 = __float2half_rn(s[nt][3]);
                pH[ks][2*half]   = (uint32_t)hfbits(h0) | ((uint32_t)hfbits(h1) << 16);
                pH[ks][2*half+1] = (uint32_t)hfbits(h2) | ((uint32_t)hfbits(h3) << 16);
                fp16 e0 = __float2half_rn(s[nt][0] - __half2float(h0));
                fp16 e1 = __float2half_rn(s[nt][1] - __half2float(h1));
                fp16 e2 = __float2half_rn(s[nt][2] - __half2float(h2));
                fp16 e3 = __float2half_rn(s[nt][3] - __half2float(h3));
                pL[ks][2*half]   = (uint32_t)hfbits(e0) | ((uint32_t)hfbits(e1) << 16);
                pL[ks][2*half+1] = (uint32_t)hfbits(e2) | ((uint32_t)hfbits(e3) << 16);
            }
        }
        #pragma unroll
        for (int nt = 0; nt < 8; nt++) {
            const int nr = (nt*8 + g) * 36;
            #pragma unroll
            for (int ks = 0; ks < 4; ks++) {
                uint32_t bh[2] = { V32[nr + ks*8 + t4], V32[nr + ks*8 + 4 + t4] };
                mma_hf(O[nt], pH[ks], bh);
                mma_hf(O[nt], pL[ks], bh);
            }
        }
    }

    // ---- epilogue: ctx = O / l, fp16 hi only ----
    const float il0 = 1.0f / l0, il1 = 1.0f / l1;
    const size_t row0 = (size_t)(b*SEQ + q0 + wid*16 + g);
    const size_t row8 = row0 + 8;
    #pragma unroll
    for (int nt = 0; nt < 8; nt++) {
        const int col = h*64 + nt*8 + 2*t4;
        *(uint32_t*)(g_ctx + row0*1024 + col) =
            (uint32_t)hfbits(__float2half_rn(O[nt][0] * il0)) |
            ((uint32_t)hfbits(__float2half_rn(O[nt][1] * il0)) << 16);
        *(uint32_t*)(g_ctx + row8*1024 + col) =
            (uint32_t)hfbits(__float2half_rn(O[nt][2] * il1)) |
            ((uint32_t)hfbits(__float2half_rn(O[nt][3] * il1)) << 16);
    }
}

// ---------------------------------------------------------------------------
// fp16 1-MMA GEMM core: A·B with both operands fp16. Stage = Ah + Bh (20 KB).
// EPI: 4 fp32+resid | 5 fp32+bias+resid | 10 fp16 pair-out
//      12 fp16 hi out | 13 fp16 hi transposed out | 14 bias+relu hi out
// ---------------------------------------------------------------------------
#define GEMM1_SMEM 40960
#define G1STAGE 20480u
#define GTILE 10240u

template<int EPI>
__device__ __forceinline__ void fcore1(
    uint8_t* dynsm,
    const fp16* __restrict__ Ah, int lda,
    const fp16* __restrict__ Bh, int ldb,
    int K, int bm, int bn,
    float* __restrict__ Cf, int ldc,
    fp16* __restrict__ Oh, fp16* __restrict__ Ol, int ldo,
    const float* __restrict__ bias, const float* __restrict__ resid)
{
    const int tid = threadIdx.x, wid = tid >> 5, lane = tid & 31;
    const int wm = wid & 3, wn = wid >> 2;
    const int g = lane >> 2, t4 = lane & 3;
    const int ar = tid >> 1, akq = (tid & 1) * 16;

    const uint32_t sbase = smem_u32(dynsm);
    const uint32_t doff = (uint32_t)(ar*40 + akq) * 2u;

    float acc[2][8][4];
    #pragma unroll
    for (int i = 0; i < 2; i++)
        #pragma unroll
        for (int j = 0; j < 8; j++)
            #pragma unroll
            for (int e = 0; e < 4; e++) acc[i][j][e] = 0.f;

    auto load_chunk = [&](int k0, int p) {
        const uint32_t base = sbase + p*G1STAGE + doff;
        const fp16* a_h = Ah + (size_t)(bm + ar) * lda + k0 + akq;
        cpa16(base,            a_h);
        cpa16(base + 16,       a_h + 8);
        const fp16* b_h = Bh + (size_t)(bn + ar) * ldb + k0 + akq;
        cpa16(base + GTILE,      b_h);
        cpa16(base + GTILE + 16, b_h + 8);
        CP_COMMIT();
    };

    const int nch = K >> 5;
    load_chunk(0, 0);
    for (int c = 0; c < nch; c++) {
        if (c + 1 < nch) { load_chunk((c + 1) << 5, (c + 1) & 1); CP_WAIT(1); }
        else             { CP_WAIT(0); }
        __syncthreads();

        const uint8_t* st = dynsm + (c & 1) * G1STAGE;
        const uint32_t* A32 = (const uint32_t*)(st);
        const uint32_t* B32 = (const uint32_t*)(st + GTILE);

        #pragma unroll
        for (int kh = 0; kh < 2; kh++) {
            const int ko = kh * 8;
            uint32_t aH[2][4];
            #pragma unroll
            for (int mt = 0; mt < 2; mt++) {
                const int r = wm*32 + mt*16 + g;
                aH[mt][0] = A32[r*20 + ko + t4];
                aH[mt][1] = A32[(r+8)*20 + ko + t4];
                aH[mt][2] = A32[r*20 + ko + 4 + t4];
                aH[mt][3] = A32[(r+8)*20 + ko + 4 + t4];
            }
            #pragma unroll
            for (int nt = 0; nt < 8; nt++) {
                const int nr = wn*64 + nt*8 + g;
                uint32_t bH[2];
                bH[0] = B32[nr*20 + ko + t4];
                bH[1] = B32[nr*20 + ko + 4 + t4];
                #pragma unroll
                for (int mt = 0; mt < 2; mt++)
                    mma_hf(acc[mt][nt], aH[mt], bH);
            }
        }
        __syncthreads();
    }

    auto wr = [&](int row, int col, float v0, float v1) {
        if (EPI == 10) {
            fp16 h0, l0, h1, l1;
            splith(v0, &h0, &l0); splith(v1, &h1, &l1);
            *(uint32_t*)(Oh + (size_t)row * ldo + col) =
                (uint32_t)hfbits(h0) | ((uint32_t)hfbits(h1) << 16);
            *(uint32_t*)(Ol + (size_t)row * ldo + col) =
                (uint32_t)hfbits(l0) | ((uint32_t)hfbits(l1) << 16);
        } else if (EPI == 12 || EPI == 14) {
            if (EPI == 14) {
                v0 = fmaxf(v0 + bias[col], 0.f);
                v1 = fmaxf(v1 + bias[col + 1], 0.f);
            }
            *(uint32_t*)(Oh + (size_t)row * ldo + col) =
                (uint32_t)hfbits(__float2half_rn(v0)) |
                ((uint32_t)hfbits(__float2half_rn(v1)) << 16);
        } else if (EPI == 13) {
            Oh[(size_t)col * ldo + row]       = __float2half_rn(v0);
            Oh[(size_t)(col + 1) * ldo + row] = __float2half_rn(v1);
        } else {
            const float* rr = resid + (size_t)row * ldc + col;
            float2 o;
            o.x = v0 + rr[0]; o.y = v1 + rr[1];
            if (EPI == 5) { o.x += bias[col]; o.y += bias[col + 1]; }
            *(float2*)(Cf + (size_t)row * ldc + col) = o;
        }
    };
    #pragma unroll
    for (int mt = 0; mt < 2; mt++) {
        #pragma unroll
        for (int nt = 0; nt < 8; nt++) {
            const int row = bm + wm*32 + mt*16 + g;
            const int col = bn + wn*64 + nt*8 + 2*t4;
            wr(row,     col, acc[mt][nt][0], acc[mt][nt][1]);
            wr(row + 8, col, acc[mt][nt][2], acc[mt][nt][3]);
        }
    }
}

// ---------------- wrappers ----------------
__global__ void __launch_bounds__(256, 2) kt_qkv() {
    extern __shared__ __align__(16) uint8_t dynsm[];
    const int bm = blockIdx.y * 128, bn = blockIdx.x * 128;
    if (blockIdx.z == 0)
        fcore1<10>(dynsm, g_xn, 1024, g_wqt, 1024, 1024,
                   bm, bn, nullptr, 0, g_q_h, g_q_l, 1024, nullptr, nullptr);
    else if (blockIdx.z == 1)
        fcore1<12>(dynsm, g_xn, 1024, g_wkt, 1024, 1024,
                   bm, bn, nullptr, 0, g_k, nullptr, 1024, nullptr, nullptr);
    else
        fcore1<13>(dynsm, g_xn, 1024, g_wvt, 1024, 1024,
                   bm, bn, nullptr, 0, g_vt, nullptr, 4096, nullptr, nullptr);
}
__global__ void __launch_bounds__(256, 2) kt_wo(const float* __restrict__ x) {
    extern __shared__ __align__(16) uint8_t dynsm[];
    fcore1<4>(dynsm, g_ctx, 1024, g_wot, 1024, 1024,
              blockIdx.y*128, blockIdx.x*128,
              g_x1, 1024, nullptr, nullptr, 0, nullptr, x);
}
__global__ void __launch_bounds__(256, 2) kt_ffn1(const float* __restrict__ b1) {
    extern __shared__ __align__(16) uint8_t dynsm[];
    fcore1<14>(dynsm, g_xn, 1024, g_w1t, 1024, 1024,
               blockIdx.y*128, blockIdx.x*128,
               nullptr, 0, g_ffh, nullptr, 4096, b1, nullptr);
}
__global__ void __launch_bounds__(256, 2) kt_ffn2(const float* __restrict__ b2,
                                                  float* __restrict__ out) {
    extern __shared__ __align__(16) uint8_t dynsm[];
    fcore1<5>(dynsm, g_ffh, 4096, g_w2t, 4096, 4096,
              blockIdx.y*128, blockIdx.x*128,
              out, 1024, nullptr, nullptr, 0, b2, g_x1);
}

// ---------------- launch ----------------
extern "C" void kernel_launch(void* const* d_in, const int* in_sizes, int n_in,
                              void* d_out, int out_size)
{
    const float* x      = (const float*)d_in[0];
    const int*   mask   = (const int*)  d_in[1];
    const float* wq     = (const float*)d_in[2];
    const float* wk     = (const float*)d_in[3];
    const float* wv     = (const float*)d_in[4];
    const float* wo     = (const float*)d_in[5];
    const float* w1     = (const float*)d_in[6];
    const float* b1     = (const float*)d_in[7];
    const float* w2     = (const float*)d_in[8];
    const float* b2     = (const float*)d_in[9];
    const float* alpha1 = (const float*)d_in[10];
    const float* bias1  = (const float*)d_in[11];
    const float* alpha2 = (const float*)d_in[12];
    const float* bias2  = (const float*)d_in[13];
    float* out = (float*)d_out;

    static int attr_set = 0;
    if (!attr_set) {
        cudaFuncSetAttribute(kt_attn, cudaFuncAttributeMaxDynamicSharedMemorySize, ATTN_SMEM);
        cudaFuncSetAttribute(kt_qkv,  cudaFuncAttributeMaxDynamicSharedMemorySize, GEMM1_SMEM);
        cudaFuncSetAttribute(kt_wo,   cudaFuncAttributeMaxDynamicSharedMemorySize, GEMM1_SMEM);
        cudaFuncSetAttribute(kt_ffn1, cudaFuncAttributeMaxDynamicSharedMemorySize, GEMM1_SMEM);
        cudaFuncSetAttribute(kt_ffn2, cudaFuncAttributeMaxDynamicSharedMemorySize, GEMM1_SMEM);
        attr_set = 1;
    }

    k_prep_all<<<12288, 256>>>(wq, wk, wv, wo, w1, w2);

    // sublayer 1
    k_ln<<<NTOK, 256>>>(x, 0, alpha1, bias1);
    kt_qkv<<<dim3(8, 32, 3), 256, GEMM1_SMEM>>>();
    kt_attn<<<dim3(16, 32), 256, ATTN_SMEM>>>(mask);
    kt_wo<<<dim3(8, 32), 256, GEMM1_SMEM>>>(x);

    // sublayer 2
    k_ln<<<NTOK, 256>>>(x, 1, alpha2, bias2);
    kt_ffn1<<<dim3(32, 32), 256, GEMM1_SMEM>>>(b1);
    kt_ffn2<<<dim3(8, 32), 256, GEMM1_SMEM>>>(b2, out);
}

// round 16
// speedup vs baseline: 2.3989x; 1.0750x over previous
#include <cuda_runtime.h>
#include <cuda_fp16.h>
#include <math.h>
#include <stdint.h>

#define DMODEL 1024
#define DFF 4096
#define SEQ 2048
#define NTOK 4096
#define LN_EPS 1e-5f
typedef __half fp16;

// ---------------- device-global scratch ----------------
__device__ fp16 g_wqt[1u<<20];                      // [N,K] K-major, pre-scaled 0.125
__device__ fp16 g_wkt[1u<<20];
__device__ fp16 g_wvt[1u<<20];
__device__ fp16 g_wot[1u<<20];
__device__ fp16 g_w1t[1u<<22];                      // [4096,1024]
__device__ fp16 g_w2t[1u<<22];                      // [1024,4096]
__device__ fp16 g_xn [1u<<22];                      // LN out, fp16
__device__ fp16 g_q  [1u<<22];                      // Q fp16
__device__ fp16 g_k  [1u<<22];                      // K fp16
__device__ fp16 g_vt [1u<<22];                      // V^T fp16 [1024 dk, 4096 tok]
__device__ fp16 g_ctx[1u<<22];                      // ctx fp16
__device__ fp16 g_ffh[1u<<24];                      // ffn hidden fp16
__device__ float g_x1[1u<<22];

// ---------------- helpers ----------------
__device__ __forceinline__ void mma_hf(float* d, const uint32_t* a, const uint32_t* b) {
    asm volatile(
        "mma.sync.aligned.m16n8k16.row.col.f32.f16.f16.f32 "
        "{%0,%1,%2,%3}, {%4,%5,%6,%7}, {%8,%9}, {%0,%1,%2,%3};"
        : "+f"(d[0]), "+f"(d[1]), "+f"(d[2]), "+f"(d[3])
        : "r"(a[0]), "r"(a[1]), "r"(a[2]), "r"(a[3]), "r"(b[0]), "r"(b[1]));
}
__device__ __forceinline__ uint16_t hfbits(fp16 v) { return __half_as_ushort(v); }
__device__ __forceinline__ void cpa16(uint32_t dst, const void* src) {
    asm volatile("cp.async.cg.shared.global [%0], [%1], 16;" :: "r"(dst), "l"(src) : "memory");
}
#define CP_COMMIT() asm volatile("cp.async.commit_group;" ::: "memory")
#define CP_WAIT(n)  asm volatile("cp.async.wait_group %0;" :: "n"(n) : "memory")
__device__ __forceinline__ uint32_t smem_u32(const void* p) {
    uint32_t a;
    asm("{ .reg .u64 t; cvta.to.shared.u64 t, %1; cvt.u32.u64 %0, t; }" : "=r"(a) : "l"(p));
    return a;
}
__device__ __forceinline__ float warpSum(float v) {
    #pragma unroll
    for (int o = 16; o > 0; o >>= 1) v += __shfl_down_sync(0xffffffffu, v, o);
    return v;
}
__device__ __forceinline__ float blockSum(float v) {
    __shared__ float sh[8];
    int l = threadIdx.x & 31, w = threadIdx.x >> 5;
    v = warpSum(v);
    if (l == 0) sh[w] = v;
    __syncthreads();
    if (w == 0) { float t = (l < 8) ? sh[l] : 0.f; t = warpSum(t); if (l == 0) sh[0] = t; }
    __syncthreads();
    float r = sh[0]; __syncthreads();
    return r;
}

// ---------------- weight prep: ONE launch, all six -> fp16 ----------------
__global__ void __launch_bounds__(256) k_prep_all(
    const float* __restrict__ wq, const float* __restrict__ wk,
    const float* __restrict__ wv, const float* __restrict__ wo,
    const float* __restrict__ w1, const float* __restrict__ w2)
{
    int t = blockIdx.x;
    const float* w; fp16* fh;
    int K, N, local;
    float scale = 1.0f;
    if (t < 4096) {
        int seg = t >> 10; local = t & 1023;
        K = 1024; N = 1024;
        switch (seg) {
            case 0: w = wq; fh = g_wqt; scale = 0.125f; break;
            case 1: w = wk; fh = g_wkt; break;
            case 2: w = wv; fh = g_wvt; break;
            default: w = wo; fh = g_wot; break;
        }
    } else if (t < 8192) {
        local = t - 4096; w = w1; fh = g_w1t; K = 1024; N = 4096;
    } else {
        local = t - 8192; w = w2; fh = g_w2t; K = 4096; N = 1024;
    }
    const int xt = N >> 5;
    const int n0 = (local % xt) * 32, k0 = (local / xt) * 32;

    __shared__ float ts[32][33];
    int tx = threadIdx.x & 31, ty = threadIdx.x >> 5;
    #pragma unroll
    for (int i = 0; i < 4; i++)
        ts[ty + 8*i][tx] = w[(size_t)(k0 + ty + 8*i) * N + n0 + tx];
    __syncthreads();
    #pragma unroll
    for (int i = 0; i < 4; i++) {
        int n = n0 + ty + 8*i, k = k0 + tx;
        fh[(size_t)n * K + k] = __float2half_rn(ts[tx][ty + 8*i] * scale);
    }
}

// ---------------- LayerNorm -> fp16 ----------------
__global__ void __launch_bounds__(256) k_ln(const float* __restrict__ xin, int use_x1,
                                            const float* __restrict__ ap,
                                            const float* __restrict__ bp)
{
    const float* src = use_x1 ? g_x1 : xin;
    int row = blockIdx.x, t = threadIdx.x;
    const float* xr = src + (size_t)row * DMODEL;
    float v[4], s = 0.f, sq = 0.f;
    #pragma unroll
    for (int i = 0; i < 4; i++) { v[i] = xr[t + 256*i]; s += v[i]; sq += v[i]*v[i]; }
    s = blockSum(s); sq = blockSum(sq);
    float mean = s * (1.0f / DMODEL);
    float var = fmaxf((sq - (float)DMODEL * mean * mean) * (1.0f / (DMODEL - 1)), 0.f);
    float sc = ap[0] / (sqrtf(var) + LN_EPS);
    float bi = bp[0];
    #pragma unroll
    for (int i = 0; i < 4; i++) {
        size_t o = (size_t)row * DMODEL + t + 256*i;
        g_xn[o] = __float2half_rn((v[i] - mean) * sc + bi);
    }
}

// ---------------------------------------------------------------------------
// Fused flash attention: S = Qh·Kh (1 MMA), O += (Ph+Pl)·Vh (2 MMAs).
// K/V double-buffered via cp.async.
// ---------------------------------------------------------------------------
#define ATTN_SMEM 45056
#define BUFB 18432u
#define TILEB 9216u

__global__ void __launch_bounds__(256, 2) kt_attn(const int* __restrict__ mask)
{
    extern __shared__ __align__(16) uint8_t dynsm[];
    const int z = blockIdx.y, b = z >> 4, h = z & 15;
    const int q0 = blockIdx.x * 128;
    const int tid = threadIdx.x, wid = tid >> 5, lane = tid & 31;
    const int g = lane >> 2, t4 = lane & 3;

    uint32_t sbase = smem_u32(dynsm);
    int* s_mask = (int*)(dynsm + 2*BUFB);

    for (int i = tid; i < SEQ/4; i += 256)
        *(int4*)&s_mask[i*4] = *(const int4*)&mask[b*SEQ + i*4];

    // Q fragments (fp16 hi), register-resident
    uint32_t qh[4][4];
    {
        const uint32_t* Q32 = (const uint32_t*)g_q;
        size_t r0 = ((size_t)(b*SEQ + q0 + wid*16 + g)) * 512 + h*32;
        size_t r8 = r0 + 8*512;
        #pragma unroll
        for (int s = 0; s < 4; s++) {
            qh[s][0] = Q32[r0 + s*8 + t4];
            qh[s][1] = Q32[r8 + s*8 + t4];
            qh[s][2] = Q32[r0 + s*8 + 4 + t4];
            qh[s][3] = Q32[r8 + s*8 + 4 + t4];
        }
    }

    float O[8][4];
    #pragma unroll
    for (int i = 0; i < 8; i++)
        #pragma unroll
        for (int j = 0; j < 4; j++) O[i][j] = 0.f;
    float m0 = -INFINITY, m1 = -INFINITY, l0 = 0.f, l1 = 0.f;

    const int krow = tid >> 2, kcb = (tid & 3) * 16;
    const uint32_t soff = (uint32_t)(krow*72 + kcb) * 2u;

    auto load_tile = [&](int kt, int p) {
        const uint32_t base = sbase + p*BUFB;
        size_t gk = ((size_t)(b*SEQ + kt*64 + krow)) * 1024 + h*64 + kcb;
        cpa16(base + soff,      &g_k[gk]);
        cpa16(base + soff + 16, &g_k[gk + 8]);
        size_t gv = ((size_t)(h*64 + krow)) * 4096 + b*SEQ + kt*64 + kcb;
        cpa16(base + TILEB + soff,      &g_vt[gv]);
        cpa16(base + TILEB + soff + 16, &g_vt[gv + 8]);
        CP_COMMIT();
    };

    load_tile(0, 0);
    for (int kt = 0; kt < SEQ/64; kt++) {
        __syncthreads();
        if (kt + 1 < SEQ/64) { load_tile(kt + 1, (kt + 1) & 1); CP_WAIT(1); }
        else                 { CP_WAIT(0); }
        __syncthreads();

        const uint8_t* buf = dynsm + (kt & 1) * BUFB;
        const uint32_t* K32 = (const uint32_t*)(buf);
        const uint32_t* V32 = (const uint32_t*)(buf + TILEB);

        // ---- S = Qh K^T ----
        float s[8][4];
        #pragma unroll
        for (int nt = 0; nt < 8; nt++) {
            s[nt][0] = s[nt][1] = s[nt][2] = s[nt][3] = 0.f;
            const int nr = (nt*8 + g) * 36;
            #pragma unroll
            for (int ks = 0; ks < 4; ks++) {
                uint32_t bh[2] = { K32[nr + ks*8 + t4], K32[nr + ks*8 + 4 + t4] };
                mma_hf(s[nt], qh[ks], bh);
            }
        }
        // ---- mask ----
        #pragma unroll
        for (int nt = 0; nt < 8; nt++) {
            const int c = kt*64 + nt*8 + 2*t4;
            if (s_mask[c]   == 0) { s[nt][0] = -1e9f; s[nt][2] = -1e9f; }
            if (s_mask[c+1] == 0) { s[nt][1] = -1e9f; s[nt][3] = -1e9f; }
        }
        // ---- online softmax ----
        float mx0 = -INFINITY, mx1 = -INFINITY;
        #pragma unroll
        for (int nt = 0; nt < 8; nt++) {
            mx0 = fmaxf(mx0, fmaxf(s[nt][0], s[nt][1]));
            mx1 = fmaxf(mx1, fmaxf(s[nt][2], s[nt][3]));
        }
        mx0 = fmaxf(mx0, __shfl_xor_sync(0xffffffffu, mx0, 1));
        mx0 = fmaxf(mx0, __shfl_xor_sync(0xffffffffu, mx0, 2));
        mx1 = fmaxf(mx1, __shfl_xor_sync(0xffffffffu, mx1, 1));
        mx1 = fmaxf(mx1, __shfl_xor_sync(0xffffffffu, mx1, 2));
        float nm0 = fmaxf(m0, mx0), nm1 = fmaxf(m1, mx1);
        float a0 = __expf(m0 - nm0), a1 = __expf(m1 - nm1);
        m0 = nm0; m1 = nm1;
        float ps0 = 0.f, ps1 = 0.f;
        #pragma unroll
        for (int nt = 0; nt < 8; nt++) {
            s[nt][0] = __expf(s[nt][0] - nm0);
            s[nt][1] = __expf(s[nt][1] - nm0);
            s[nt][2] = __expf(s[nt][2] - nm1);
            s[nt][3] = __expf(s[nt][3] - nm1);
            ps0 += s[nt][0] + s[nt][1];
            ps1 += s[nt][2] + s[nt][3];
        }
        ps0 += __shfl_xor_sync(0xffffffffu, ps0, 1);
        ps0 += __shfl_xor_sync(0xffffffffu, ps0, 2);
        ps1 += __shfl_xor_sync(0xffffffffu, ps1, 1);
        ps1 += __shfl_xor_sync(0xffffffffu, ps1, 2);
        l0 = l0 * a0 + ps0;
        l1 = l1 * a1 + ps1;
        #pragma unroll
        for (int nt = 0; nt < 8; nt++) {
            O[nt][0] *= a0; O[nt][1] *= a0;
            O[nt][2] *= a1; O[nt][3] *= a1;
        }
        // ---- P -> fp16 hi/lo A-fragments ----
        uint32_t pH[4][4], pL[4][4];
        #pragma unroll
        for (int ks = 0; ks < 4; ks++) {
            #pragma unroll
            for (int half = 0; half < 2; half++) {
                const int nt = 2*ks + half;
                fp16 h0 = __float2half_rn(s[nt][0]);
                fp16 h1 = __float2half_rn(s[nt][1]);
                fp16 h2 = __float2half_rn(s[nt][2]);
                fp16 h3 = __float2half_rn(s[nt][3]);
                pH[ks][2*half]   = (uint32_t)hfbits(h0) | ((uint32_t)hfbits(h1) << 16);
                pH[ks][2*half+1] = (uint32_t)hfbits(h2) | ((uint32_t)hfbits(h3) << 16);
                fp16 e0 = __float2half_rn(s[nt][0] - __half2float(h0));
                fp16 e1 = __float2half_rn(s[nt][1] - __half2float(h1));
                fp16 e2 = __float2half_rn(s[nt][2] - __half2float(h2));
                fp16 e3 = __float2half_rn(s[nt][3] - __half2float(h3));
                pL[ks][2*half]   = (uint32_t)hfbits(e0) | ((uint32_t)hfbits(e1) << 16);
                pL[ks][2*half+1] = (uint32_t)hfbits(e2) | ((uint32_t)hfbits(e3) << 16);
            }
        }
        // ---- O += (Ph+Pl) V^T ----
        #pragma unroll
        for (int nt = 0; nt < 8; nt++) {
            const int nr = (nt*8 + g) * 36;
            #pragma unroll
            for (int ks = 0; ks < 4; ks++) {
                uint32_t bh[2] = { V32[nr + ks*8 + t4], V32[nr + ks*8 + 4 + t4] };
                mma_hf(O[nt], pH[ks], bh);
                mma_hf(O[nt], pL[ks], bh);
            }
        }
    }

    // ---- epilogue: ctx = O / l ----
    const float il0 = 1.0f / l0, il1 = 1.0f / l1;
    const size_t row0 = (size_t)(b*SEQ + q0 + wid*16 + g);
    const size_t row8 = row0 + 8;
    #pragma unroll
    for (int nt = 0; nt < 8; nt++) {
        const int col = h*64 + nt*8 + 2*t4;
        *(uint32_t*)(g_ctx + row0*1024 + col) =
            (uint32_t)hfbits(__float2half_rn(O[nt][0] * il0)) |
            ((uint32_t)hfbits(__float2half_rn(O[nt][1] * il0)) << 16);
        *(uint32_t*)(g_ctx + row8*1024 + col) =
            (uint32_t)hfbits(__float2half_rn(O[nt][2] * il1)) |
            ((uint32_t)hfbits(__float2half_rn(O[nt][3] * il1)) << 16);
    }
}

// ---------------------------------------------------------------------------
// fp16 1-MMA GEMM core, 4-stage cp.async pipeline. Stage = Ah + Bh (20 KB).
// EPI: 4 fp32+resid | 5 fp32+bias+resid | 12 fp16 out
//      13 fp16 transposed out | 14 bias+relu fp16 out
// ---------------------------------------------------------------------------
#define GEMM1_SMEM 81920
#define G1STAGE 20480u
#define GTILE 10240u

template<int EPI>
__device__ __forceinline__ void fcore1(
    uint8_t* dynsm,
    const fp16* __restrict__ Ah, int lda,
    const fp16* __restrict__ Bh, int ldb,
    int K, int bm, int bn,
    float* __restrict__ Cf, int ldc,
    fp16* __restrict__ Oh, int ldo,
    const float* __restrict__ bias, const float* __restrict__ resid)
{
    const int tid = threadIdx.x, wid = tid >> 5, lane = tid & 31;
    const int wm = wid & 3, wn = wid >> 2;
    const int g = lane >> 2, t4 = lane & 3;
    const int ar = tid >> 1, akq = (tid & 1) * 16;

    const uint32_t sbase = smem_u32(dynsm);
    const uint32_t doff = (uint32_t)(ar*40 + akq) * 2u;

    float acc[2][8][4];
    #pragma unroll
    for (int i = 0; i < 2; i++)
        #pragma unroll
        for (int j = 0; j < 8; j++)
            #pragma unroll
            for (int e = 0; e < 4; e++) acc[i][j][e] = 0.f;

    auto load_chunk = [&](int k0, int p) {
        const uint32_t base = sbase + (uint32_t)p*G1STAGE + doff;
        const fp16* a_h = Ah + (size_t)(bm + ar) * lda + k0 + akq;
        cpa16(base,      a_h);
        cpa16(base + 16, a_h + 8);
        const fp16* b_h = Bh + (size_t)(bn + ar) * ldb + k0 + akq;
        cpa16(base + GTILE,      b_h);
        cpa16(base + GTILE + 16, b_h + 8);
        CP_COMMIT();
    };

    const int nch = K >> 5;     // always >= 32
    load_chunk(0, 0);
    load_chunk(32, 1);
    load_chunk(64, 2);
    for (int c = 0; c < nch; c++) {
        const int rem = nch - 1 - c;
        if (rem >= 2)      CP_WAIT(2);
        else if (rem == 1) CP_WAIT(1);
        else               CP_WAIT(0);
        __syncthreads();
        // safe: all warps finished computing chunk c-1, whose buffer (c+3)&3 reuses
        if (c + 3 < nch) load_chunk((c + 3) << 5, (c + 3) & 3);

        const uint8_t* st = dynsm + (c & 3) * G1STAGE;
        const uint32_t* A32 = (const uint32_t*)(st);
        const uint32_t* B32 = (const uint32_t*)(st + GTILE);

        #pragma unroll
        for (int kh = 0; kh < 2; kh++) {
            const int ko = kh * 8;
            uint32_t aH[2][4];
            #pragma unroll
            for (int mt = 0; mt < 2; mt++) {
                const int r = wm*32 + mt*16 + g;
                aH[mt][0] = A32[r*20 + ko + t4];
                aH[mt][1] = A32[(r+8)*20 + ko + t4];
                aH[mt][2] = A32[r*20 + ko + 4 + t4];
                aH[mt][3] = A32[(r+8)*20 + ko + 4 + t4];
            }
            #pragma unroll
            for (int nt = 0; nt < 8; nt++) {
                const int nr = wn*64 + nt*8 + g;
                uint32_t bH[2];
                bH[0] = B32[nr*20 + ko + t4];
                bH[1] = B32[nr*20 + ko + 4 + t4];
                #pragma unroll
                for (int mt = 0; mt < 2; mt++)
                    mma_hf(acc[mt][nt], aH[mt], bH);
            }
        }
    }
    __syncthreads();

    auto wr = [&](int row, int col, float v0, float v1) {
        if (EPI == 12 || EPI == 14) {
            if (EPI == 14) {
                v0 = fmaxf(v0 + bias[col], 0.f);
                v1 = fmaxf(v1 + bias[col + 1], 0.f);
            }
            *(uint32_t*)(Oh + (size_t)row * ldo + col) =
                (uint32_t)hfbits(__float2half_rn(v0)) |
                ((uint32_t)hfbits(__float2half_rn(v1)) << 16);
        } else if (EPI == 13) {
            Oh[(size_t)col * ldo + row]       = __float2half_rn(v0);
            Oh[(size_t)(col + 1) * ldo + row] = __float2half_rn(v1);
        } else {
            const float* rr = resid + (size_t)row * ldc + col;
            float2 o;
            o.x = v0 + rr[0]; o.y = v1 + rr[1];
            if (EPI == 5) { o.x += bias[col]; o.y += bias[col + 1]; }
            *(float2*)(Cf + (size_t)row * ldc + col) = o;
        }
    };
    #pragma unroll
    for (int mt = 0; mt < 2; mt++) {
        #pragma unroll
        for (int nt = 0; nt < 8; nt++) {
            const int row = bm + wm*32 + mt*16 + g;
            const int col = bn + wn*64 + nt*8 + 2*t4;
            wr(row,     col, acc[mt][nt][0], acc[mt][nt][1]);
            wr(row + 8, col, acc[mt][nt][2], acc[mt][nt][3]);
        }
    }
}

// ---------------- wrappers ----------------
__global__ void __launch_bounds__(256, 2) kt_qkv() {
    extern __shared__ __align__(16) uint8_t dynsm[];
    const int bm = blockIdx.y * 128, bn = blockIdx.x * 128;
    if (blockIdx.z == 0)
        fcore1<12>(dynsm, g_xn, 1024, g_wqt, 1024, 1024,
                   bm, bn, nullptr, 0, g_q, 1024, nullptr, nullptr);
    else if (blockIdx.z == 1)
        fcore1<12>(dynsm, g_xn, 1024, g_wkt, 1024, 1024,
                   bm, bn, nullptr, 0, g_k, 1024, nullptr, nullptr);
    else
        fcore1<13>(dynsm, g_xn, 1024, g_wvt, 1024, 1024,
                   bm, bn, nullptr, 0, g_vt, 4096, nullptr, nullptr);
}
__global__ void __launch_bounds__(256, 2) kt_wo(const float* __restrict__ x) {
    extern __shared__ __align__(16) uint8_t dynsm[];
    fcore1<4>(dynsm, g_ctx, 1024, g_wot, 1024, 1024,
              blockIdx.y*128, blockIdx.x*128,
              g_x1, 1024, nullptr, 0, nullptr, x);
}
__global__ void __launch_bounds__(256, 2) kt_ffn1(const float* __restrict__ b1) {
    extern __shared__ __align__(16) uint8_t dynsm[];
    fcore1<14>(dynsm, g_xn, 1024, g_w1t, 1024, 1024,
               blockIdx.y*128, blockIdx.x*128,
               nullptr, 0, g_ffh, 4096, b1, nullptr);
}
__global__ void __launch_bounds__(256, 2) kt_ffn2(const float* __restrict__ b2,
                                                  float* __restrict__ out) {
    extern __shared__ __align__(16) uint8_t dynsm[];
    fcore1<5>(dynsm, g_ffh, 4096, g_w2t, 4096, 4096,
              blockIdx.y*128, blockIdx.x*128,
              out, 1024, nullptr, 0, b2, g_x1);
}

// ---------------- launch ----------------
extern "C" void kernel_launch(void* const* d_in, const int* in_sizes, int n_in,
                              void* d_out, int out_size)
{
    const float* x      = (const float*)d_in[0];
    const int*   mask   = (const int*)  d_in[1];
    const float* wq     = (const float*)d_in[2];
    const float* wk     = (const float*)d_in[3];
    const float* wv     = (const float*)d_in[4];
    const float* wo     = (const float*)d_in[5];
    const float* w1     = (const float*)d_in[6];
    const float* b1     = (const float*)d_in[7];
    const float* w2     = (const float*)d_in[8];
    const float* b2     = (const float*)d_in[9];
    const float* alpha1 = (const float*)d_in[10];
    const float* bias1  = (const float*)d_in[11];
    const float* alpha2 = (const float*)d_in[12];
    const float* bias2  = (const float*)d_in[13];
    float* out = (float*)d_out;

    static int attr_set = 0;
    if (!attr_set) {
        cudaFuncSetAttribute(kt_attn, cudaFuncAttributeMaxDynamicSharedMemorySize, ATTN_SMEM);
        cudaFuncSetAttribute(kt_qkv,  cudaFuncAttributeMaxDynamicSharedMemorySize, GEMM1_SMEM);
        cudaFuncSetAttribute(kt_wo,   cudaFuncAttributeMaxDynamicSharedMemorySize, GEMM1_SMEM);
        cudaFuncSetAttribute(kt_ffn1, cudaFuncAttributeMaxDynamicSharedMemorySize, GEMM1_SMEM);
        cudaFuncSetAttribute(kt_ffn2, cudaFuncAttributeMaxDynamicSharedMemorySize, GEMM1_SMEM);
        attr_set = 1;
    }

    k_prep_all<<<12288, 256>>>(wq, wk, wv, wo, w1, w2);

    // sublayer 1
    k_ln<<<NTOK, 256>>>(x, 0, alpha1, bias1);
    kt_qkv<<<dim3(8, 32, 3), 256, GEMM1_SMEM>>>();
    kt_attn<<<dim3(16, 32), 256, ATTN_SMEM>>>(mask);
    kt_wo<<<dim3(8, 32), 256, GEMM1_SMEM>>>(x);

    // sublayer 2
    k_ln<<<NTOK, 256>>>(x, 1, alpha2, bias2);
    kt_ffn1<<<dim3(32, 32), 256, GEMM1_SMEM>>>(b1);
    kt_ffn2<<<dim3(8, 32), 256, GEMM1_SMEM>>>(b2, out);
}

// round 17
// speedup vs baseline: 2.5498x; 1.0629x over previous
#include <cuda_runtime.h>
#include <cuda_fp16.h>
#include <math.h>
#include <stdint.h>

#define DMODEL 1024
#define DFF 4096
#define SEQ 2048
#define NTOK 4096
#define LN_EPS 1e-5f
typedef __half fp16;

// ---------------- device-global scratch ----------------
__device__ fp16 g_wqt[1u<<20];                      // [N,K] K-major, pre-scaled 0.125
__device__ fp16 g_wkt[1u<<20];
__device__ fp16 g_wvt[1u<<20];
__device__ fp16 g_wot[1u<<20];
__device__ fp16 g_w1t[1u<<22];                      // [4096,1024]
__device__ fp16 g_w2t[1u<<22];                      // [1024,4096]
__device__ fp16 g_xn [1u<<22];                      // LN out, fp16
__device__ fp16 g_q  [1u<<22];                      // Q fp16
__device__ fp16 g_k  [1u<<22];                      // K fp16
__device__ fp16 g_vt [1u<<22];                      // V^T fp16 [1024 dk, 4096 tok]
__device__ fp16 g_ctx[1u<<22];                      // ctx fp16
__device__ fp16 g_ffh[1u<<24];                      // ffn hidden fp16
__device__ float g_x1[1u<<22];

// ---------------- helpers ----------------
__device__ __forceinline__ void mma_hf(float* d, const uint32_t* a, const uint32_t* b) {
    asm volatile(
        "mma.sync.aligned.m16n8k16.row.col.f32.f16.f16.f32 "
        "{%0,%1,%2,%3}, {%4,%5,%6,%7}, {%8,%9}, {%0,%1,%2,%3};"
        : "+f"(d[0]), "+f"(d[1]), "+f"(d[2]), "+f"(d[3])
        : "r"(a[0]), "r"(a[1]), "r"(a[2]), "r"(a[3]), "r"(b[0]), "r"(b[1]));
}
__device__ __forceinline__ void ldm4(uint32_t& r0, uint32_t& r1, uint32_t& r2, uint32_t& r3,
                                     uint32_t addr) {
    asm volatile("ldmatrix.sync.aligned.m8n8.x4.shared.b16 {%0,%1,%2,%3}, [%4];"
        : "=r"(r0), "=r"(r1), "=r"(r2), "=r"(r3) : "r"(addr));
}
__device__ __forceinline__ uint16_t hfbits(fp16 v) { return __half_as_ushort(v); }
__device__ __forceinline__ void cpa16(uint32_t dst, const void* src) {
    asm volatile("cp.async.cg.shared.global [%0], [%1], 16;" :: "r"(dst), "l"(src) : "memory");
}
#define CP_COMMIT() asm volatile("cp.async.commit_group;" ::: "memory")
#define CP_WAIT(n)  asm volatile("cp.async.wait_group %0;" :: "n"(n) : "memory")
__device__ __forceinline__ uint32_t smem_u32(const void* p) {
    uint32_t a;
    asm("{ .reg .u64 t; cvta.to.shared.u64 t, %1; cvt.u32.u64 %0, t; }" : "=r"(a) : "l"(p));
    return a;
}
__device__ __forceinline__ float warpSum(float v) {
    #pragma unroll
    for (int o = 16; o > 0; o >>= 1) v += __shfl_down_sync(0xffffffffu, v, o);
    return v;
}
__device__ __forceinline__ float blockSum(float v) {
    __shared__ float sh[8];
    int l = threadIdx.x & 31, w = threadIdx.x >> 5;
    v = warpSum(v);
    if (l == 0) sh[w] = v;
    __syncthreads();
    if (w == 0) { float t = (l < 8) ? sh[l] : 0.f; t = warpSum(t); if (l == 0) sh[0] = t; }
    __syncthreads();
    float r = sh[0]; __syncthreads();
    return r;
}

// ---------------- weight prep: ONE launch, all six -> fp16 ----------------
__global__ void __launch_bounds__(256) k_prep_all(
    const float* __restrict__ wq, const float* __restrict__ wk,
    const float* __restrict__ wv, const float* __restrict__ wo,
    const float* __restrict__ w1, const float* __restrict__ w2)
{
    int t = blockIdx.x;
    const float* w; fp16* fh;
    int K, N, local;
    float scale = 1.0f;
    if (t < 4096) {
        int seg = t >> 10; local = t & 1023;
        K = 1024; N = 1024;
        switch (seg) {
            case 0: w = wq; fh = g_wqt; scale = 0.125f; break;
            case 1: w = wk; fh = g_wkt; break;
            case 2: w = wv; fh = g_wvt; break;
            default: w = wo; fh = g_wot; break;
        }
    } else if (t < 8192) {
        local = t - 4096; w = w1; fh = g_w1t; K = 1024; N = 4096;
    } else {
        local = t - 8192; w = w2; fh = g_w2t; K = 4096; N = 1024;
    }
    const int xt = N >> 5;
    const int n0 = (local % xt) * 32, k0 = (local / xt) * 32;

    __shared__ float ts[32][33];
    int tx = threadIdx.x & 31, ty = threadIdx.x >> 5;
    #pragma unroll
    for (int i = 0; i < 4; i++)
        ts[ty + 8*i][tx] = w[(size_t)(k0 + ty + 8*i) * N + n0 + tx];
    __syncthreads();
    #pragma unroll
    for (int i = 0; i < 4; i++) {
        int n = n0 + ty + 8*i, k = k0 + tx;
        fh[(size_t)n * K + k] = __float2half_rn(ts[tx][ty + 8*i] * scale);
    }
}

// ---------------- LayerNorm -> fp16 ----------------
__global__ void __launch_bounds__(256) k_ln(const float* __restrict__ xin, int use_x1,
                                            const float* __restrict__ ap,
                                            const float* __restrict__ bp)
{
    const float* src = use_x1 ? g_x1 : xin;
    int row = blockIdx.x, t = threadIdx.x;
    const float* xr = src + (size_t)row * DMODEL;
    float v[4], s = 0.f, sq = 0.f;
    #pragma unroll
    for (int i = 0; i < 4; i++) { v[i] = xr[t + 256*i]; s += v[i]; sq += v[i]*v[i]; }
    s = blockSum(s); sq = blockSum(sq);
    float mean = s * (1.0f / DMODEL);
    float var = fmaxf((sq - (float)DMODEL * mean * mean) * (1.0f / (DMODEL - 1)), 0.f);
    float sc = ap[0] / (sqrtf(var) + LN_EPS);
    float bi = bp[0];
    #pragma unroll
    for (int i = 0; i < 4; i++) {
        size_t o = (size_t)row * DMODEL + t + 256*i;
        g_xn[o] = __float2half_rn((v[i] - mean) * sc + bi);
    }
}

// ---------------------------------------------------------------------------
// Fused flash attention (identical to R16): S = Qh·Kh, O += (Ph+Pl)·Vh.
// ---------------------------------------------------------------------------
#define ATTN_SMEM 45056
#define BUFB 18432u
#define TILEB 9216u

__global__ void __launch_bounds__(256, 2) kt_attn(const int* __restrict__ mask)
{
    extern __shared__ __align__(16) uint8_t dynsm[];
    const int z = blockIdx.y, b = z >> 4, h = z & 15;
    const int q0 = blockIdx.x * 128;
    const int tid = threadIdx.x, wid = tid >> 5, lane = tid & 31;
    const int g = lane >> 2, t4 = lane & 3;

    uint32_t sbase = smem_u32(dynsm);
    int* s_mask = (int*)(dynsm + 2*BUFB);

    for (int i = tid; i < SEQ/4; i += 256)
        *(int4*)&s_mask[i*4] = *(const int4*)&mask[b*SEQ + i*4];

    uint32_t qh[4][4];
    {
        const uint32_t* Q32 = (const uint32_t*)g_q;
        size_t r0 = ((size_t)(b*SEQ + q0 + wid*16 + g)) * 512 + h*32;
        size_t r8 = r0 + 8*512;
        #pragma unroll
        for (int s = 0; s < 4; s++) {
            qh[s][0] = Q32[r0 + s*8 + t4];
            qh[s][1] = Q32[r8 + s*8 + t4];
            qh[s][2] = Q32[r0 + s*8 + 4 + t4];
            qh[s][3] = Q32[r8 + s*8 + 4 + t4];
        }
    }

    float O[8][4];
    #pragma unroll
    for (int i = 0; i < 8; i++)
        #pragma unroll
        for (int j = 0; j < 4; j++) O[i][j] = 0.f;
    float m0 = -INFINITY, m1 = -INFINITY, l0 = 0.f, l1 = 0.f;

    const int krow = tid >> 2, kcb = (tid & 3) * 16;
    const uint32_t soff = (uint32_t)(krow*72 + kcb) * 2u;

    auto load_tile = [&](int kt, int p) {
        const uint32_t base = sbase + p*BUFB;
        size_t gk = ((size_t)(b*SEQ + kt*64 + krow)) * 1024 + h*64 + kcb;
        cpa16(base + soff,      &g_k[gk]);
        cpa16(base + soff + 16, &g_k[gk + 8]);
        size_t gv = ((size_t)(h*64 + krow)) * 4096 + b*SEQ + kt*64 + kcb;
        cpa16(base + TILEB + soff,      &g_vt[gv]);
        cpa16(base + TILEB + soff + 16, &g_vt[gv + 8]);
        CP_COMMIT();
    };

    load_tile(0, 0);
    for (int kt = 0; kt < SEQ/64; kt++) {
        __syncthreads();
        if (kt + 1 < SEQ/64) { load_tile(kt + 1, (kt + 1) & 1); CP_WAIT(1); }
        else                 { CP_WAIT(0); }
        __syncthreads();

        const uint8_t* buf = dynsm + (kt & 1) * BUFB;
        const uint32_t* K32 = (const uint32_t*)(buf);
        const uint32_t* V32 = (const uint32_t*)(buf + TILEB);

        float s[8][4];
        #pragma unroll
        for (int nt = 0; nt < 8; nt++) {
            s[nt][0] = s[nt][1] = s[nt][2] = s[nt][3] = 0.f;
            const int nr = (nt*8 + g) * 36;
            #pragma unroll
            for (int ks = 0; ks < 4; ks++) {
                uint32_t bh[2] = { K32[nr + ks*8 + t4], K32[nr + ks*8 + 4 + t4] };
                mma_hf(s[nt], qh[ks], bh);
            }
        }
        #pragma unroll
        for (int nt = 0; nt < 8; nt++) {
            const int c = kt*64 + nt*8 + 2*t4;
            if (s_mask[c]   == 0) { s[nt][0] = -1e9f; s[nt][2] = -1e9f; }
            if (s_mask[c+1] == 0) { s[nt][1] = -1e9f; s[nt][3] = -1e9f; }
        }
        float mx0 = -INFINITY, mx1 = -INFINITY;
        #pragma unroll
        for (int nt = 0; nt < 8; nt++) {
            mx0 = fmaxf(mx0, fmaxf(s[nt][0], s[nt][1]));
            mx1 = fmaxf(mx1, fmaxf(s[nt][2], s[nt][3]));
        }
        mx0 = fmaxf(mx0, __shfl_xor_sync(0xffffffffu, mx0, 1));
        mx0 = fmaxf(mx0, __shfl_xor_sync(0xffffffffu, mx0, 2));
        mx1 = fmaxf(mx1, __shfl_xor_sync(0xffffffffu, mx1, 1));
        mx1 = fmaxf(mx1, __shfl_xor_sync(0xffffffffu, mx1, 2));
        float nm0 = fmaxf(m0, mx0), nm1 = fmaxf(m1, mx1);
        float a0 = __expf(m0 - nm0), a1 = __expf(m1 - nm1);
        m0 = nm0; m1 = nm1;
        float ps0 = 0.f, ps1 = 0.f;
        #pragma unroll
        for (int nt = 0; nt < 8; nt++) {
            s[nt][0] = __expf(s[nt][0] - nm0);
            s[nt][1] = __expf(s[nt][1] - nm0);
            s[nt][2] = __expf(s[nt][2] - nm1);
            s[nt][3] = __expf(s[nt][3] - nm1);
            ps0 += s[nt][0] + s[nt][1];
            ps1 += s[nt][2] + s[nt][3];
        }
        ps0 += __shfl_xor_sync(0xffffffffu, ps0, 1);
        ps0 += __shfl_xor_sync(0xffffffffu, ps0, 2);
        ps1 += __shfl_xor_sync(0xffffffffu, ps1, 1);
        ps1 += __shfl_xor_sync(0xffffffffu, ps1, 2);
        l0 = l0 * a0 + ps0;
        l1 = l1 * a1 + ps1;
        #pragma unroll
        for (int nt = 0; nt < 8; nt++) {
            O[nt][0] *= a0; O[nt][1] *= a0;
            O[nt][2] *= a1; O[nt][3] *= a1;
        }
        uint32_t pH[4][4], pL[4][4];
        #pragma unroll
        for (int ks = 0; ks < 4; ks++) {
            #pragma unroll
            for (int half = 0; half < 2; half++) {
                const int nt = 2*ks + half;
                fp16 h0 = __float2half_rn(s[nt][0]);
                fp16 h1 = __float2half_rn(s[nt][1]);
                fp16 h2 = __float2half_rn(s[nt][2]);
                fp16 h3 = __float2half_rn(s[nt][3]);
                pH[ks][2*half]   = (uint32_t)hfbits(h0) | ((uint32_t)hfbits(h1) << 16);
                pH[ks][2*half+1] = (uint32_t)hfbits(h2) | ((uint32_t)hfbits(h3) << 16);
                fp16 e0 = __float2half_rn(s[nt][0] - __half2float(h0));
                fp16 e1 = __float2half_rn(s[nt][1] - __half2float(h1));
                fp16 e2 = __float2half_rn(s[nt][2] - __half2float(h2));
                fp16 e3 = __float2half_rn(s[nt][3] - __half2float(h3));
                pL[ks][2*half]   = (uint32_t)hfbits(e0) | ((uint32_t)hfbits(e1) << 16);
                pL[ks][2*half+1] = (uint32_t)hfbits(e2) | ((uint32_t)hfbits(e3) << 16);
            }
        }
        #pragma unroll
        for (int nt = 0; nt < 8; nt++) {
            const int nr = (nt*8 + g) * 36;
            #pragma unroll
            for (int ks = 0; ks < 4; ks++) {
                uint32_t bh[2] = { V32[nr + ks*8 + t4], V32[nr + ks*8 + 4 + t4] };
                mma_hf(O[nt], pH[ks], bh);
                mma_hf(O[nt], pL[ks], bh);
            }
        }
    }

    const float il0 = 1.0f / l0, il1 = 1.0f / l1;
    const size_t row0 = (size_t)(b*SEQ + q0 + wid*16 + g);
    const size_t row8 = row0 + 8;
    #pragma unroll
    for (int nt = 0; nt < 8; nt++) {
        const int col = h*64 + nt*8 + 2*t4;
        *(uint32_t*)(g_ctx + row0*1024 + col) =
            (uint32_t)hfbits(__float2half_rn(O[nt][0] * il0)) |
            ((uint32_t)hfbits(__float2half_rn(O[nt][1] * il0)) << 16);
        *(uint32_t*)(g_ctx + row8*1024 + col) =
            (uint32_t)hfbits(__float2half_rn(O[nt][2] * il1)) |
            ((uint32_t)hfbits(__float2half_rn(O[nt][3] * il1)) << 16);
    }
}

// ---------------------------------------------------------------------------
// fp16 1-MMA GEMM core, 4-stage cp.async pipeline + ldmatrix fragment loads.
// Per kh-half: 2 ldmatrix.x4 (A) + 4 ldmatrix.x4 (B) feed 16 HMMAs.
// EPI: 4 fp32+resid | 5 fp32+bias+resid | 12 fp16 out
//      13 fp16 transposed out | 14 bias+relu fp16 out
// ---------------------------------------------------------------------------
#define GEMM1_SMEM 81920
#define G1STAGE 20480u
#define GTILE 10240u

template<int EPI>
__device__ __forceinline__ void fcore1(
    uint8_t* dynsm,
    const fp16* __restrict__ Ah, int lda,
    const fp16* __restrict__ Bh, int ldb,
    int K, int bm, int bn,
    float* __restrict__ Cf, int ldc,
    fp16* __restrict__ Oh, int ldo,
    const float* __restrict__ bias, const float* __restrict__ resid)
{
    const int tid = threadIdx.x, wid = tid >> 5, lane = tid & 31;
    const int wm = wid & 3, wn = wid >> 2;
    const int g = lane >> 2, t4 = lane & 3;
    const int ar = tid >> 1, akq = (tid & 1) * 16;
    const int lrow = lane & 7, lt = lane >> 3;   // ldmatrix lane mapping

    const uint32_t sbase = smem_u32(dynsm);
    const uint32_t doff = (uint32_t)(ar*40 + akq) * 2u;

    // ldmatrix byte offsets within a stage (kh adds 32 bytes)
    // A tiles (reg order): (m lo,k lo),(m hi,k lo),(m lo,k hi),(m hi,k hi)
    uint32_t aoff[2];
    #pragma unroll
    for (int mt = 0; mt < 2; mt++)
        aoff[mt] = (uint32_t)((wm*32 + mt*16 + (lt & 1)*8 + lrow)*40 + (lt >> 1)*8) * 2u;
    // B tiles (reg order): (n lo,k lo),(n lo,k hi),(n hi,k lo),(n hi,k hi)
    uint32_t boff[4];
    #pragma unroll
    for (int np = 0; np < 4; np++)
        boff[np] = (uint32_t)GTILE +
                   (uint32_t)((wn*64 + np*16 + (lt >> 1)*8 + lrow)*40 + (lt & 1)*8) * 2u;

    float acc[2][8][4];
    #pragma unroll
    for (int i = 0; i < 2; i++)
        #pragma unroll
        for (int j = 0; j < 8; j++)
            #pragma unroll
            for (int e = 0; e < 4; e++) acc[i][j][e] = 0.f;

    auto load_chunk = [&](int k0, int p) {
        const uint32_t base = sbase + (uint32_t)p*G1STAGE + doff;
        const fp16* a_h = Ah + (size_t)(bm + ar) * lda + k0 + akq;
        cpa16(base,      a_h);
        cpa16(base + 16, a_h + 8);
        const fp16* b_h = Bh + (size_t)(bn + ar) * ldb + k0 + akq;
        cpa16(base + GTILE,      b_h);
        cpa16(base + GTILE + 16, b_h + 8);
        CP_COMMIT();
    };

    const int nch = K >> 5;
    load_chunk(0, 0);
    load_chunk(32, 1);
    load_chunk(64, 2);
    for (int c = 0; c < nch; c++) {
        const int rem = nch - 1 - c;
        if (rem >= 2)      CP_WAIT(2);
        else if (rem == 1) CP_WAIT(1);
        else               CP_WAIT(0);
        __syncthreads();
        if (c + 3 < nch) load_chunk((c + 3) << 5, (c + 3) & 3);

        const uint32_t st = sbase + (uint32_t)(c & 3) * G1STAGE;

        #pragma unroll
        for (int kh = 0; kh < 2; kh++) {
            const uint32_t kadd = (uint32_t)kh * 32u;
            uint32_t aH[2][4];
            ldm4(aH[0][0], aH[0][1], aH[0][2], aH[0][3], st + aoff[0] + kadd);
            ldm4(aH[1][0], aH[1][1], aH[1][2], aH[1][3], st + aoff[1] + kadd);
            uint32_t bb[4][4];
            #pragma unroll
            for (int np = 0; np < 4; np++)
                ldm4(bb[np][0], bb[np][1], bb[np][2], bb[np][3], st + boff[np] + kadd);
            #pragma unroll
            for (int nt = 0; nt < 8; nt++) {
                uint32_t bH[2] = { bb[nt >> 1][(nt & 1)*2], bb[nt >> 1][(nt & 1)*2 + 1] };
                #pragma unroll
                for (int mt = 0; mt < 2; mt++)
                    mma_hf(acc[mt][nt], aH[mt], bH);
            }
        }
    }
    __syncthreads();

    auto wr = [&](int row, int col, float v0, float v1) {
        if (EPI == 12 || EPI == 14) {
            if (EPI == 14) {
                v0 = fmaxf(v0 + bias[col], 0.f);
                v1 = fmaxf(v1 + bias[col + 1], 0.f);
            }
            *(uint32_t*)(Oh + (size_t)row * ldo + col) =
                (uint32_t)hfbits(__float2half_rn(v0)) |
                ((uint32_t)hfbits(__float2half_rn(v1)) << 16);
        } else if (EPI == 13) {
            Oh[(size_t)col * ldo + row]       = __float2half_rn(v0);
            Oh[(size_t)(col + 1) * ldo + row] = __float2half_rn(v1);
        } else {
            const float* rr = resid + (size_t)row * ldc + col;
            float2 o;
            o.x = v0 + rr[0]; o.y = v1 + rr[1];
            if (EPI == 5) { o.x += bias[col]; o.y += bias[col + 1]; }
            *(float2*)(Cf + (size_t)row * ldc + col) = o;
        }
    };
    #pragma unroll
    for (int mt = 0; mt < 2; mt++) {
        #pragma unroll
        for (int nt = 0; nt < 8; nt++) {
            const int row = bm + wm*32 + mt*16 + g;
            const int col = bn + wn*64 + nt*8 + 2*t4;
            wr(row,     col, acc[mt][nt][0], acc[mt][nt][1]);
            wr(row + 8, col, acc[mt][nt][2], acc[mt][nt][3]);
        }
    }
}

// ---------------- wrappers ----------------
__global__ void __launch_bounds__(256, 2) kt_qkv() {
    extern __shared__ __align__(16) uint8_t dynsm[];
    const int bm = blockIdx.y * 128, bn = blockIdx.x * 128;
    if (blockIdx.z == 0)
        fcore1<12>(dynsm, g_xn, 1024, g_wqt, 1024, 1024,
                   bm, bn, nullptr, 0, g_q, 1024, nullptr, nullptr);
    else if (blockIdx.z == 1)
        fcore1<12>(dynsm, g_xn, 1024, g_wkt, 1024, 1024,
                   bm, bn, nullptr, 0, g_k, 1024, nullptr, nullptr);
    else
        fcore1<13>(dynsm, g_xn, 1024, g_wvt, 1024, 1024,
                   bm, bn, nullptr, 0, g_vt, 4096, nullptr, nullptr);
}
__global__ void __launch_bounds__(256, 2) kt_wo(const float* __restrict__ x) {
    extern __shared__ __align__(16) uint8_t dynsm[];
    fcore1<4>(dynsm, g_ctx, 1024, g_wot, 1024, 1024,
              blockIdx.y*128, blockIdx.x*128,
              g_x1, 1024, nullptr, 0, nullptr, x);
}
__global__ void __launch_bounds__(256, 2) kt_ffn1(const float* __restrict__ b1) {
    extern __shared__ __align__(16) uint8_t dynsm[];
    fcore1<14>(dynsm, g_xn, 1024, g_w1t, 1024, 1024,
               blockIdx.y*128, blockIdx.x*128,
               nullptr, 0, g_ffh, 4096, b1, nullptr);
}
__global__ void __launch_bounds__(256, 2) kt_ffn2(const float* __restrict__ b2,
                                                  float* __restrict__ out) {
    extern __shared__ __align__(16) uint8_t dynsm[];
    fcore1<5>(dynsm, g_ffh, 4096, g_w2t, 4096, 4096,
              blockIdx.y*128, blockIdx.x*128,
              out, 1024, nullptr, 0, b2, g_x1);
}

// ---------------- launch ----------------
extern "C" void kernel_launch(void* const* d_in, const int* in_sizes, int n_in,
                              void* d_out, int out_size)
{
    const float* x      = (const float*)d_in[0];
    const int*   mask   = (const int*)  d_in[1];
    const float* wq     = (const float*)d_in[2];
    const float* wk     = (const float*)d_in[3];
    const float* wv     = (const float*)d_in[4];
    const float* wo     = (const float*)d_in[5];
    const float* w1     = (const float*)d_in[6];
    const float* b1     = (const float*)d_in[7];
    const float* w2     = (const float*)d_in[8];
    const float* b2     = (const float*)d_in[9];
    const float* alpha1 = (const float*)d_in[10];
    const float* bias1  = (const float*)d_in[11];
    const float* alpha2 = (const float*)d_in[12];
    const float* bias2  = (const float*)d_in[13];
    float* out = (float*)d_out;

    static int attr_set = 0;
    if (!attr_set) {
        cudaFuncSetAttribute(kt_attn, cudaFuncAttributeMaxDynamicSharedMemorySize, ATTN_SMEM);
        cudaFuncSetAttribute(kt_qkv,  cudaFuncAttributeMaxDynamicSharedMemorySize, GEMM1_SMEM);
        cudaFuncSetAttribute(kt_wo,   cudaFuncAttributeMaxDynamicSharedMemorySize, GEMM1_SMEM);
        cudaFuncSetAttribute(kt_ffn1, cudaFuncAttributeMaxDynamicSharedMemorySize, GEMM1_SMEM);
        cudaFuncSetAttribute(kt_ffn2, cudaFuncAttributeMaxDynamicSharedMemorySize, GEMM1_SMEM);
        attr_set = 1;
    }

    k_prep_all<<<12288, 256>>>(wq, wk, wv, wo, w1, w2);

    // sublayer 1
    k_ln<<<NTOK, 256>>>(x, 0, alpha1, bias1);
    kt_qkv<<<dim3(8, 32, 3), 256, GEMM1_SMEM>>>();
    kt_attn<<<dim3(16, 32), 256, ATTN_SMEM>>>(mask);
    kt_wo<<<dim3(8, 32), 256, GEMM1_SMEM>>>(x);

    // sublayer 2
    k_ln<<<NTOK, 256>>>(x, 1, alpha2, bias2);
    kt_ffn1<<<dim3(32, 32), 256, GEMM1_SMEM>>>(b1);
    kt_ffn2<<<dim3(8, 32), 256, GEMM1_SMEM>>>(b2, out);
}